// round 4
// baseline (speedup 1.0000x reference)
#include <cuda_runtime.h>
#include <math.h>

// ---------------------------------------------------------------------------
// Scratch (allocation-free rule: __device__ globals)
// ---------------------------------------------------------------------------
__device__ float g_x [4194304];    // running residual [4096,1024]
__device__ float g_h [4194304];    // layernorm output
__device__ float g_q [4194304];
__device__ float g_k [4194304];
__device__ float g_v [4194304];
__device__ float g_o [4194304];    // attention output (pre out-proj)
__device__ float g_S [134217728];  // scores [2,16,2048,2048] (reused for cross w/ ld=80)
__device__ float g_hg[33554432];   // FFN intermediate [4096,8192]
__device__ float g_gg[16777216];   // GEGLU output [4096,4096]

// ---------------------------------------------------------------------------
// LayerNorm: one CTA (128 threads) per row of 1024
// ---------------------------------------------------------------------------
__global__ void ln_kernel(const float* __restrict__ x, const float* __restrict__ gamma,
                          const float* __restrict__ beta, float* __restrict__ out)
{
    __shared__ float red[4];
    const long long row = blockIdx.x;
    const float* xr = x + row * 1024;
    const int t = threadIdx.x;
    float v[8];
    *reinterpret_cast<float4*>(&v[0]) = *reinterpret_cast<const float4*>(xr + t * 8);
    *reinterpret_cast<float4*>(&v[4]) = *reinterpret_cast<const float4*>(xr + t * 8 + 4);
    float s = 0.f;
#pragma unroll
    for (int i = 0; i < 8; ++i) s += v[i];
#pragma unroll
    for (int o = 16; o; o >>= 1) s += __shfl_xor_sync(0xffffffffu, s, o);
    if ((t & 31) == 0) red[t >> 5] = s;
    __syncthreads();
    const float mu = (red[0] + red[1] + red[2] + red[3]) * (1.0f / 1024.0f);
    __syncthreads();
    float ss = 0.f;
#pragma unroll
    for (int i = 0; i < 8; ++i) { float d = v[i] - mu; ss += d * d; }
#pragma unroll
    for (int o = 16; o; o >>= 1) ss += __shfl_xor_sync(0xffffffffu, ss, o);
    if ((t & 31) == 0) red[t >> 5] = ss;
    __syncthreads();
    const float var = (red[0] + red[1] + red[2] + red[3]) * (1.0f / 1024.0f);
    const float rs = rsqrtf(var + 1e-5f);
    float* orow = out + row * 1024;
#pragma unroll
    for (int i = 0; i < 8; ++i) {
        const int c = t * 8 + i;
        orow[c] = (v[i] - mu) * rs * gamma[c] + beta[c];
    }
}

// ---------------------------------------------------------------------------
// Softmax + 8-bit fake quant (zp=0) in place. One CTA (128 thr) per row.
// Pads columns [L, ld) with zeros (so padded K in the following GEMM is inert).
// ---------------------------------------------------------------------------
__global__ void softmax_quant_kernel(float* __restrict__ S, int L, int ld,
                                     const float* __restrict__ dptr)
{
    __shared__ float buf[2048];
    __shared__ float red[4];
    const long long row = blockIdx.x;
    float* r = S + row * (long long)ld;
    const int t = threadIdx.x;
    float mx = -3.0e38f;
    for (int j = t; j < L; j += 128) { float v = r[j]; buf[j] = v; mx = fmaxf(mx, v); }
#pragma unroll
    for (int o = 16; o; o >>= 1) mx = fmaxf(mx, __shfl_xor_sync(0xffffffffu, mx, o));
    if ((t & 31) == 0) red[t >> 5] = mx;
    __syncthreads();
    mx = fmaxf(fmaxf(red[0], red[1]), fmaxf(red[2], red[3]));
    __syncthreads();
    float s = 0.f;
    for (int j = t; j < L; j += 128) s += expf(buf[j] - mx);
#pragma unroll
    for (int o = 16; o; o >>= 1) s += __shfl_xor_sync(0xffffffffu, s, o);
    if ((t & 31) == 0) red[t >> 5] = s;
    __syncthreads();
    s = red[0] + red[1] + red[2] + red[3];
    const float delta = *dptr;
    for (int j = t; j < L; j += 128) {
        const float p  = expf(buf[j] - mx) / s;
        float xi = rintf(p / delta);                 // zp = 0
        xi = fminf(fmaxf(xi, 0.f), 255.f);
        r[j] = xi * delta;
    }
    for (int j = L + t; j < ld; j += 128) r[j] = 0.f;
}

// ---------------------------------------------------------------------------
// GEGLU: gg[r][c] = hg[r][c] * gelu_exact(hg[r][4096+c])   (4096x4096, float4)
// ---------------------------------------------------------------------------
__global__ void geglu_kernel(const float* __restrict__ hg, float* __restrict__ gg)
{
    const long long i4 = (long long)blockIdx.x * blockDim.x + threadIdx.x;
    const long long r  = i4 >> 10;              // 1024 float4 per 4096-wide row
    const long long c  = (i4 & 1023) << 2;
    const float4 a = *reinterpret_cast<const float4*>(hg + r * 8192 + c);
    const float4 g = *reinterpret_cast<const float4*>(hg + r * 8192 + 4096 + c);
    const float k = 0.70710678118654752440f;
    float4 o;
    o.x = a.x * (0.5f * g.x * (1.f + erff(g.x * k)));
    o.y = a.y * (0.5f * g.y * (1.f + erff(g.y * k)));
    o.z = a.z * (0.5f * g.z * (1.f + erff(g.z * k)));
    o.w = a.w * (0.5f * g.w * (1.f + erff(g.w * k)));
    *reinterpret_cast<float4*>(gg + r * 4096 + c) = o;
}

// ---------------------------------------------------------------------------
// Generic tiled SGEMM.
//   C = scale * (A @ op(B)) [+ bias[n]] [+ res] [-> fake-quant(delta, zp)]
//   A: [M,K] row-major (lda).   BT=false: B is [K,N] (ldb).  BT=true: B is [N,K] (ldb).
//   Batched over blockIdx.z = b*16 + h with independent (b,h) strides.
//   BK = 16; K must be a multiple of 16 and 16B-aligned rows (guaranteed by caller).
// ---------------------------------------------------------------------------
template<int BM, int BN, int TM, int TN, bool BT>
__global__ void __launch_bounds__(256, 2)
gemm_kernel(const float* __restrict__ A, const float* __restrict__ Bm, float* __restrict__ C,
            int M, int N, int K, int lda, int ldb, int ldc,
            long long sAb, long long sAh, long long sBb, long long sBh,
            long long sCb, long long sCh,
            const float* __restrict__ bias,
            const float* __restrict__ res, long long sRb, long long sRh, int ldr,
            const float* __restrict__ dptr, float zp, float scale)
{
    __shared__ float As[16][BM + 4];
    __shared__ float Bs[16][BN + 4];

    const int bz = blockIdx.z;
    const int hb = bz & 15;
    const int bb = bz >> 4;
    A  += bb * sAb + hb * sAh;
    Bm += bb * sBb + hb * sBh;
    C  += bb * sCb + hb * sCh;
    if (res) res += bb * sRb + hb * sRh;

    const int bm = blockIdx.y * BM;
    const int bn = blockIdx.x * BN;
    const int tid = threadIdx.x;
    constexpr int TCOLS = BN / TN;
    const int tcol = tid % TCOLS;
    const int trow = tid / TCOLS;

    float acc[TM][TN];
#pragma unroll
    for (int i = 0; i < TM; ++i)
#pragma unroll
        for (int j = 0; j < TN; ++j) acc[i][j] = 0.f;

    constexpr int A_ITERS = (BM * 16) / 1024;
    constexpr int B_ITERS = (BN * 16) / 1024;

    for (int k0 = 0; k0 < K; k0 += 16) {
        // ---- load A tile [BM x 16], transposed into As[k][m] ----
#pragma unroll
        for (int i = 0; i < A_ITERS; ++i) {
            const int idx = tid + i * 256;
            const int r  = idx >> 2;     // 4 float4 per row (BK=16)
            const int c4 = idx & 3;
            const int gr = bm + r;
            float4 a = make_float4(0.f, 0.f, 0.f, 0.f);
            if (gr < M)
                a = *reinterpret_cast<const float4*>(A + (long long)gr * lda + k0 + c4 * 4);
            As[c4 * 4 + 0][r] = a.x;
            As[c4 * 4 + 1][r] = a.y;
            As[c4 * 4 + 2][r] = a.z;
            As[c4 * 4 + 3][r] = a.w;
        }
        // ---- load B tile into Bs[k][n] ----
        if (BT) {
#pragma unroll
            for (int i = 0; i < B_ITERS; ++i) {
                const int idx = tid + i * 256;
                const int r  = idx >> 2;
                const int c4 = idx & 3;
                const int gn = bn + r;
                float4 b = make_float4(0.f, 0.f, 0.f, 0.f);
                if (gn < N)
                    b = *reinterpret_cast<const float4*>(Bm + (long long)gn * ldb + k0 + c4 * 4);
                Bs[c4 * 4 + 0][r] = b.x;
                Bs[c4 * 4 + 1][r] = b.y;
                Bs[c4 * 4 + 2][r] = b.z;
                Bs[c4 * 4 + 3][r] = b.w;
            }
        } else {
            constexpr int C4R = BN / 4;
#pragma unroll
            for (int i = 0; i < B_ITERS; ++i) {
                const int idx = tid + i * 256;
                const int r  = idx / C4R;
                const int c4 = idx % C4R;
                const int gk = k0 + r;
                const int gn = bn + c4 * 4;
                float4 b = make_float4(0.f, 0.f, 0.f, 0.f);
                if (gk < K) {
                    if (gn + 3 < N) {
                        b = *reinterpret_cast<const float4*>(Bm + (long long)gk * ldb + gn);
                    } else {
                        const float* bp = Bm + (long long)gk * ldb + gn;
                        b.x = (gn + 0 < N) ? bp[0] : 0.f;
                        b.y = (gn + 1 < N) ? bp[1] : 0.f;
                        b.z = (gn + 2 < N) ? bp[2] : 0.f;
                        b.w = (gn + 3 < N) ? bp[3] : 0.f;
                    }
                }
                *reinterpret_cast<float4*>(&Bs[r][c4 * 4]) = b;
            }
        }
        __syncthreads();

#pragma unroll
        for (int kk = 0; kk < 16; ++kk) {
            float af[TM], bf[TN];
#pragma unroll
            for (int i = 0; i < TM; i += 4)
                *reinterpret_cast<float4*>(&af[i]) =
                    *reinterpret_cast<const float4*>(&As[kk][trow * TM + i]);
#pragma unroll
            for (int j = 0; j < TN; j += 4)
                *reinterpret_cast<float4*>(&bf[j]) =
                    *reinterpret_cast<const float4*>(&Bs[kk][tcol * TN + j]);
#pragma unroll
            for (int i = 0; i < TM; ++i)
#pragma unroll
                for (int j = 0; j < TN; ++j)
                    acc[i][j] = fmaf(af[i], bf[j], acc[i][j]);
        }
        __syncthreads();
    }

    // ---- epilogue ----
    float delta = 1.f;
    if (dptr) delta = *dptr;
#pragma unroll
    for (int i = 0; i < TM; ++i) {
        const int r = bm + trow * TM + i;
        if (r >= M) continue;
#pragma unroll
        for (int j = 0; j < TN; ++j) {
            const int c = bn + tcol * TN + j;
            if (c >= N) continue;
            float v = acc[i][j] * scale;
            if (bias) v += bias[c];
            if (res)  v += res[(long long)r * ldr + c];
            if (dptr) {
                float xi = rintf(v / delta) + zp;
                xi = fminf(fmaxf(xi, 0.f), 255.f);
                v = (xi - zp) * delta;
            }
            C[(long long)r * ldc + c] = v;
        }
    }
}

template<int BM, int BN, int TM, int TN, bool BT>
static void run_gemm(const float* A, const float* B, float* C,
                     int M, int N, int K, int lda, int ldb, int ldc,
                     long long sAb, long long sAh, long long sBb, long long sBh,
                     long long sCb, long long sCh, int nbatch,
                     const float* bias,
                     const float* res, long long sRb, long long sRh, int ldr,
                     const float* dptr, float zp, float scale)
{
    dim3 grid((N + BN - 1) / BN, (M + BM - 1) / BM, nbatch);
    gemm_kernel<BM, BN, TM, TN, BT><<<grid, 256>>>(
        A, B, C, M, N, K, lda, ldb, ldc,
        sAb, sAh, sBb, sBh, sCb, sCh,
        bias, res, sRb, sRh, ldr, dptr, zp, scale);
}

// ---------------------------------------------------------------------------
// kernel_launch
// ---------------------------------------------------------------------------
extern "C" void kernel_launch(void* const* d_in, const int* in_sizes, int n_in,
                              void* d_out, int out_size)
{
    (void)in_sizes; (void)n_in; (void)out_size;
    const float* x     = (const float*)d_in[0];
    const float* ctx   = (const float*)d_in[1];
    const float* ln1_g = (const float*)d_in[2];
    const float* ln1_b = (const float*)d_in[3];
    const float* ln2_g = (const float*)d_in[4];
    const float* ln2_b = (const float*)d_in[5];
    const float* ln3_g = (const float*)d_in[6];
    const float* ln3_b = (const float*)d_in[7];
    const float* wq1 = (const float*)d_in[8];
    const float* wk1 = (const float*)d_in[9];
    const float* wv1 = (const float*)d_in[10];
    const float* wo1 = (const float*)d_in[11];
    const float* bo1 = (const float*)d_in[12];
    const float* wq2 = (const float*)d_in[13];
    const float* wk2 = (const float*)d_in[14];
    const float* wv2 = (const float*)d_in[15];
    const float* wo2 = (const float*)d_in[16];
    const float* bo2 = (const float*)d_in[17];
    const float* w1  = (const float*)d_in[18];
    const float* b1  = (const float*)d_in[19];
    const float* w2  = (const float*)d_in[20];
    const float* b2  = (const float*)d_in[21];
    const float* dq1 = (const float*)d_in[22];
    const float* dk1 = (const float*)d_in[23];
    const float* dv1 = (const float*)d_in[24];
    const float* dw1 = (const float*)d_in[25];
    const float* dq2 = (const float*)d_in[26];
    const float* dk2 = (const float*)d_in[27];
    const float* dv2 = (const float*)d_in[28];
    const float* dw2 = (const float*)d_in[29];
    float* out = (float*)d_out;

    float *px, *ph, *pq, *pk, *pv, *po, *pS, *phg, *pgg;
    cudaGetSymbolAddress((void**)&px,  g_x);
    cudaGetSymbolAddress((void**)&ph,  g_h);
    cudaGetSymbolAddress((void**)&pq,  g_q);
    cudaGetSymbolAddress((void**)&pk,  g_k);
    cudaGetSymbolAddress((void**)&pv,  g_v);
    cudaGetSymbolAddress((void**)&po,  g_o);
    cudaGetSymbolAddress((void**)&pS,  g_S);
    cudaGetSymbolAddress((void**)&phg, g_hg);
    cudaGetSymbolAddress((void**)&pgg, g_gg);

    const long long ND  = 2048LL * 1024;       // per-b stride of q/k/v/o/x (b-major)
    const long long SB1 = 16LL * 2048 * 2048;  // S1 per-b stride
    const long long SH1 = 2048LL * 2048;       // S1 per-h stride
    const long long SB2 = 16LL * 2048 * 80;    // S2 per-b stride (padded ld=80)
    const long long SH2 = 2048LL * 80;
    const long long CKV = 77LL * 1024;         // cross K/V per-b stride

    // ================= self attention =================
    ln_kernel<<<4096, 128>>>(x, ln1_g, ln1_b, ph);
    run_gemm<128,128,8,8,false>(ph, wq1, pq, 4096,1024,1024, 1024,1024,1024,
        0,0, 0,0, 0,0, 1, nullptr, nullptr,0,0,0, dq1, 128.f, 1.f);
    run_gemm<128,128,8,8,false>(ph, wk1, pk, 4096,1024,1024, 1024,1024,1024,
        0,0, 0,0, 0,0, 1, nullptr, nullptr,0,0,0, dk1, 128.f, 1.f);
    run_gemm<128,128,8,8,false>(ph, wv1, pv, 4096,1024,1024, 1024,1024,1024,
        0,0, 0,0, 0,0, 1, nullptr, nullptr,0,0,0, dv1, 128.f, 1.f);
    // S1[b,h] = fq(q) @ fq(k)^T * 0.125
    run_gemm<128,128,8,8,true>(pq, pk, pS, 2048,2048,64, 1024,1024,2048,
        ND,64, ND,64, SB1,SH1, 32, nullptr, nullptr,0,0,0, nullptr, 0.f, 0.125f);
    softmax_quant_kernel<<<65536, 128>>>(pS, 2048, 2048, dw1);
    // O1[b,h] = P @ fq(v)
    run_gemm<128,64,8,4,false>(pS, pv, po, 2048,64,2048, 2048,1024,1024,
        SB1,SH1, ND,64, ND,64, 32, nullptr, nullptr,0,0,0, nullptr, 0.f, 1.f);
    // x = O1 @ wo1 + bo1 + x
    run_gemm<128,128,8,8,false>(po, wo1, px, 4096,1024,1024, 1024,1024,1024,
        0,0, 0,0, 0,0, 1, bo1, x, 0,0,1024, nullptr, 0.f, 1.f);

    // ================= cross attention =================
    ln_kernel<<<4096, 128>>>(px, ln2_g, ln2_b, ph);
    run_gemm<128,128,8,8,false>(ph, wq2, pq, 4096,1024,1024, 1024,1024,1024,
        0,0, 0,0, 0,0, 1, nullptr, nullptr,0,0,0, dq2, 128.f, 1.f);
    run_gemm<128,128,8,8,false>(ctx, wk2, pk, 154,1024,1024, 1024,1024,1024,
        0,0, 0,0, 0,0, 1, nullptr, nullptr,0,0,0, dk2, 128.f, 1.f);
    run_gemm<128,128,8,8,false>(ctx, wv2, pv, 154,1024,1024, 1024,1024,1024,
        0,0, 0,0, 0,0, 1, nullptr, nullptr,0,0,0, dv2, 128.f, 1.f);
    // S2[b,h] = fq(q) @ fq(k)^T * 0.125   (N=77, stored ld=80)
    run_gemm<128,128,8,8,true>(pq, pk, pS, 2048,77,64, 1024,1024,80,
        ND,64, CKV,64, SB2,SH2, 32, nullptr, nullptr,0,0,0, nullptr, 0.f, 0.125f);
    softmax_quant_kernel<<<65536, 128>>>(pS, 77, 80, dw2);   // zero-pads cols 77..79
    // O2[b,h] = P @ fq(v)   (K padded to 80; pad cols are exact zeros)
    run_gemm<128,64,8,4,false>(pS, pv, po, 2048,64,80, 80,1024,1024,
        SB2,SH2, CKV,64, ND,64, 32, nullptr, nullptr,0,0,0, nullptr, 0.f, 1.f);
    // x = O2 @ wo2 + bo2 + x   (in-place residual: each element read+written by its own thread)
    run_gemm<128,128,8,8,false>(po, wo2, px, 4096,1024,1024, 1024,1024,1024,
        0,0, 0,0, 0,0, 1, bo2, px, 0,0,1024, nullptr, 0.f, 1.f);

    // ================= GEGLU feed-forward =================
    ln_kernel<<<4096, 128>>>(px, ln3_g, ln3_b, ph);
    run_gemm<128,128,8,8,false>(ph, w1, phg, 4096,8192,1024, 1024,8192,8192,
        0,0, 0,0, 0,0, 1, b1, nullptr,0,0,0, nullptr, 0.f, 1.f);
    geglu_kernel<<<16384, 256>>>(phg, pgg);
    run_gemm<128,128,8,8,false>(pgg, w2, out, 4096,1024,4096, 4096,1024,1024,
        0,0, 0,0, 0,0, 1, b2, px, 0,0,1024, nullptr, 0.f, 1.f);
}

// round 6
// speedup vs baseline: 2.1726x; 2.1726x over previous
#include <cuda_runtime.h>
#include <cstdint>
#include <math.h>

// ---------------- scratch ----------------
__device__ float g_x [4194304];
__device__ float g_h [4194304];   // ln out (hi or rna)
__device__ float g_hl[4194304];   // ln out lo (split)
__device__ float g_q [4194304];
__device__ float g_k [4194304];
__device__ float g_v [4194304];
__device__ float g_o [4194304];
__device__ float g_vt[4194304];
__device__ float g_S [134217728];
__device__ float g_hg[33554432];
__device__ float g_gg[16777216];
__device__ float g_w [27262976];
__device__ float g_cs[327680];    // ctx hi/lo (154*1024*2)

// ---------------- helpers ----------------
static __device__ __forceinline__ uint32_t smem_u32(const void* p) {
    uint32_t a;
    asm("{ .reg .u64 t; cvta.to.shared.u64 t, %1; cvt.u32.u64 %0, t; }" : "=r"(a) : "l"(p));
    return a;
}
static __device__ __forceinline__ float hi13(float x) {
    return __uint_as_float(__float_as_uint(x) & 0xFFFFE000u);
}
static __device__ __forceinline__ float rna_tf32(float x) {
    uint32_t u;
    asm("cvt.rna.tf32.f32 %0, %1;" : "=r"(u) : "f"(x));
    return __uint_as_float(u);
}
#define MMA4(d, a, b) \
    asm volatile("mma.sync.aligned.m16n8k8.row.col.f32.tf32.tf32.f32 " \
        "{%0,%1,%2,%3},{%4,%5,%6,%7},{%8,%9},{%0,%1,%2,%3};" \
        : "+f"((d)[0]), "+f"((d)[1]), "+f"((d)[2]), "+f"((d)[3]) \
        : "r"((a)[0]), "r"((a)[1]), "r"((a)[2]), "r"((a)[3]), "r"((b)[0]), "r"((b)[1]))
#define CPA(dst, src, sz) \
    asm volatile("cp.async.cg.shared.global [%0], [%1], 16, %2;" :: "r"(dst), "l"(src), "r"(sz))

// ---------------- tf32 mma GEMM ----------------
// C[M,Nstore] = s0*s1*s2*(A[M,K] @ B[N,K]^T) [+bias] [+res] [->quant codes] [->rna]
struct GArgs {
    const float *A, *Al, *B, *Bl; float* C;
    int M, N, Nstore, K, lda, ldb, ldc, ldr, rna_out;
    long long sAb, sAh, sBb, sBh, sCb, sCh, sRb, sRh;
    const float *bias, *res, *s1, *s2, *qd;
    float s0;
};

template<int BN, int WM, bool SPLIT>
__global__ void __launch_bounds__(256, SPLIT ? 1 : 2)
mmagemm(const __grid_constant__ GArgs g)
{
    constexpr int WN  = 8 / WM;
    constexpr int WTM = 128 / WM, WTN = BN / WN;
    constexpr int MF  = WTM / 16, NF = WTN / 8;
    constexpr int AS  = 128 * 36;          // floats per A tile (stride 36)
    constexpr int BS  = BN * 36;
    constexpr int NT  = SPLIT ? 2 : 1;
    constexpr int STG = NT * (AS + BS);

    extern __shared__ float sm[];
    const uint32_t smb = smem_u32(sm);

    const int tid = threadIdx.x, wid = tid >> 5, lane = tid & 31;
    const int gq = lane >> 2, tg = lane & 3;
    const int wm = wid / WN, wn = wid % WN;

    const int z = blockIdx.z, bb = z >> 4, hb = z & 15;
    const float* Ab = g.A + bb * g.sAb + hb * g.sAh;
    const float* Al = SPLIT ? (g.Al + bb * g.sAb + hb * g.sAh) : (const float*)0;
    const float* Bb = g.B + bb * g.sBb + hb * g.sBh;
    const float* Bl = SPLIT ? (g.Bl + bb * g.sBb + hb * g.sBh) : (const float*)0;
    float* C = g.C + bb * g.sCb + hb * g.sCh;
    const float* res = g.res ? (g.res + bb * g.sRb + hb * g.sRh) : (const float*)0;

    const int bm = blockIdx.y * 128, bn = blockIdx.x * BN;
    const int nch = g.K >> 5;

    float acc[MF][NF][4];
#pragma unroll
    for (int i = 0; i < MF; ++i)
#pragma unroll
        for (int j = 0; j < NF; ++j)
#pragma unroll
            for (int c = 0; c < 4; ++c) acc[i][j][c] = 0.f;

    auto issue = [&](int ch, int st) {
        const int k0 = ch << 5;
        const uint32_t sa = smb + (uint32_t)st * STG * 4;
#pragma unroll
        for (int i = 0; i < 4; ++i) {          // A tile 128x32
            const int idx = tid + (i << 8);
            const int r = idx >> 3, c4 = idx & 7;
            const int gr = bm + r;
            const int ok = (gr < g.M);
            const float* s = ok ? (Ab + (long long)gr * g.lda + k0 + (c4 << 2)) : Ab;
            const uint32_t d = sa + (uint32_t)(r * 36 + (c4 << 2)) * 4;
            CPA(d, s, ok ? 16 : 0);
            if (SPLIT) {
                const float* s2 = ok ? (Al + (long long)gr * g.lda + k0 + (c4 << 2)) : Al;
                CPA(d + AS * 4, s2, ok ? 16 : 0);
            }
        }
#pragma unroll
        for (int i = 0; i < BN / 32; ++i) {    // B tile BNx32
            const int idx = tid + (i << 8);
            const int r = idx >> 3, c4 = idx & 7;
            const int gn = bn + r;
            const int ok = (gn < g.N);
            const float* s = ok ? (Bb + (long long)gn * g.ldb + k0 + (c4 << 2)) : Bb;
            const uint32_t d = sa + (uint32_t)(NT * AS + r * 36 + (c4 << 2)) * 4;
            CPA(d, s, ok ? 16 : 0);
            if (SPLIT) {
                const float* s2 = ok ? (Bl + (long long)gn * g.ldb + k0 + (c4 << 2)) : Bl;
                CPA(d + BS * 4, s2, ok ? 16 : 0);
            }
        }
    };

    auto compute = [&](int st) {
        const float* sa  = sm + st * STG;
        const float* sal = sa + AS;
        const float* sbh = sa + NT * AS;
        const float* sbl = sbh + BS;
#pragma unroll
        for (int kk = 0; kk < 4; ++kk) {
            const int kb = kk << 3;
            uint32_t bh[NF][2], bl[NF][2];
#pragma unroll
            for (int nf = 0; nf < NF; ++nf) {
                const int o = (wn * WTN + (nf << 3) + gq) * 36 + kb + tg;
                bh[nf][0] = __float_as_uint(sbh[o]);
                bh[nf][1] = __float_as_uint(sbh[o + 4]);
                if (SPLIT) {
                    bl[nf][0] = __float_as_uint(sbl[o]);
                    bl[nf][1] = __float_as_uint(sbl[o + 4]);
                }
            }
#pragma unroll
            for (int mf = 0; mf < MF; ++mf) {
                const int o = (wm * WTM + (mf << 4) + gq) * 36 + kb + tg;
                uint32_t ah[4] = { __float_as_uint(sa[o]),     __float_as_uint(sa[o + 288]),
                                   __float_as_uint(sa[o + 4]), __float_as_uint(sa[o + 292]) };
#pragma unroll
                for (int nf = 0; nf < NF; ++nf) MMA4(acc[mf][nf], ah, bh[nf]);
                if (SPLIT) {
                    uint32_t al[4] = { __float_as_uint(sal[o]),     __float_as_uint(sal[o + 288]),
                                       __float_as_uint(sal[o + 4]), __float_as_uint(sal[o + 292]) };
#pragma unroll
                    for (int nf = 0; nf < NF; ++nf) {
                        MMA4(acc[mf][nf], ah, bl[nf]);
                        MMA4(acc[mf][nf], al, bh[nf]);
                    }
                }
            }
        }
    };

    issue(0, 0);
    asm volatile("cp.async.commit_group;");
    for (int ch = 0; ch < nch; ++ch) {
        if (ch + 1 < nch) issue(ch + 1, (ch + 1) & 1);
        asm volatile("cp.async.commit_group;");
        asm volatile("cp.async.wait_group 1;");
        __syncthreads();
        compute(ch & 1);
        __syncthreads();
    }

    float alpha = g.s0;
    if (g.s1) alpha *= __ldg(g.s1);
    if (g.s2) alpha *= __ldg(g.s2);
    const float qd = g.qd ? __ldg(g.qd) : 1.f;
#pragma unroll
    for (int mf = 0; mf < MF; ++mf) {
        const int r0 = bm + wm * WTM + (mf << 4) + gq;
#pragma unroll
        for (int nf = 0; nf < NF; ++nf) {
            const int c0 = bn + wn * WTN + (nf << 3) + (tg << 1);
#pragma unroll
            for (int e = 0; e < 4; ++e) {
                const int r = r0 + ((e >> 1) << 3);
                const int c = c0 + (e & 1);
                if (r < g.M && c < g.Nstore) {
                    float v = acc[mf][nf][e] * alpha;
                    if (g.bias) v += __ldg(g.bias + c);
                    if (res)    v += res[(long long)r * g.ldr + c];
                    if (g.qd) {
                        float xi = rintf(v / qd) + 128.f;
                        v = fminf(fmaxf(xi, 0.f), 255.f) - 128.f;
                    }
                    if (g.rna_out) v = rna_tf32(v);
                    C[(long long)r * g.ldc + c] = v;
                }
            }
        }
    }
}

template<int BN, int WM, bool SPLIT>
static void run_mm(GArgs a, int nb)
{
    constexpr int STG = (SPLIT ? 2 : 1) * (128 * 36 + BN * 36);
    const int smem = 2 * STG * 4;
    cudaFuncSetAttribute(mmagemm<BN, WM, SPLIT>,
                         cudaFuncAttributeMaxDynamicSharedMemorySize, smem);
    dim3 grid((a.N + BN - 1) / BN, (a.M + 127) / 128, nb);
    mmagemm<BN, WM, SPLIT><<<grid, 256, smem>>>(a);
}

static GArgs ga(const float* A, const float* Al, const float* B, const float* Bl,
                float* C, int M, int N, int Nstore, int K, int lda, int ldb, int ldc)
{
    GArgs g;
    g.A = A; g.Al = Al; g.B = B; g.Bl = Bl; g.C = C;
    g.M = M; g.N = N; g.Nstore = Nstore; g.K = K;
    g.lda = lda; g.ldb = ldb; g.ldc = ldc; g.ldr = 0; g.rna_out = 0;
    g.sAb = g.sAh = g.sBb = g.sBh = g.sCb = g.sCh = g.sRb = g.sRh = 0;
    g.bias = 0; g.res = 0; g.s1 = 0; g.s2 = 0; g.qd = 0; g.s0 = 1.f;
    return g;
}

// ---------------- transposes ----------------
__global__ void wtrans(const float* __restrict__ in, float* __restrict__ out, int K, int N)
{
    __shared__ float t[32][33];
    const int n0 = blockIdx.x * 32, k0 = blockIdx.y * 32;
    const int tx = threadIdx.x, ty = threadIdx.y;
#pragma unroll
    for (int i = 0; i < 32; i += 8)
        t[ty + i][tx] = in[(long long)(k0 + ty + i) * N + n0 + tx];
    __syncthreads();
#pragma unroll
    for (int i = 0; i < 32; i += 8)
        out[(long long)(n0 + ty + i) * K + k0 + tx] = rna_tf32(t[tx][ty + i]);
}
__global__ void wtrans_split(const float* __restrict__ in, float* __restrict__ oH,
                             float* __restrict__ oL, int K, int N)
{
    __shared__ float t[32][33];
    const int n0 = blockIdx.x * 32, k0 = blockIdx.y * 32;
    const int tx = threadIdx.x, ty = threadIdx.y;
#pragma unroll
    for (int i = 0; i < 32; i += 8)
        t[ty + i][tx] = in[(long long)(k0 + ty + i) * N + n0 + tx];
    __syncthreads();
#pragma unroll
    for (int i = 0; i < 32; i += 8) {
        const float v = t[tx][ty + i], h = hi13(v);
        const long long o = (long long)(n0 + ty + i) * K + k0 + tx;
        oH[o] = h; oL[o] = v - h;
    }
}
// v [b,t,h*64+d] codes -> vt [b][h][d][t], zero-padded to Tpad
__global__ void vtrans(const float* __restrict__ v, float* __restrict__ vt, int T, int Tpad)
{
    __shared__ float t[32][33];
    const int bz = blockIdx.z, b = bz >> 4, h = bz & 15;
    const int t0 = blockIdx.x * 32, d0 = blockIdx.y * 32;
    const int tx = threadIdx.x, ty = threadIdx.y;
#pragma unroll
    for (int i = 0; i < 32; i += 8) {
        const int tt = t0 + ty + i;
        t[ty + i][tx] = (tt < T) ? v[((long long)b * T + tt) * 1024 + h * 64 + d0 + tx] : 0.f;
    }
    __syncthreads();
#pragma unroll
    for (int i = 0; i < 32; i += 8) {
        const int tt = t0 + tx;
        if (tt < Tpad)
            vt[(((long long)b * 16 + h) * 64 + d0 + ty + i) * Tpad + tt] = t[tx][ty + i];
    }
}
// elementwise hi/lo split (ctx)
__global__ void esplit(const float* __restrict__ in, float* __restrict__ oH,
                       float* __restrict__ oL, int n)
{
    const int i = blockIdx.x * 256 + threadIdx.x;
    if (i < n) { const float v = in[i], h = hi13(v); oH[i] = h; oL[i] = v - h; }
}

// ---------------- layernorm (mode 0: plain, 1: rna, 2: hi/lo split) ----------------
__global__ void ln_kernel(const float* __restrict__ x, const float* __restrict__ gm,
                          const float* __restrict__ bt, float* __restrict__ out,
                          float* __restrict__ out2, int mode)
{
    __shared__ float red[4];
    const long long row = blockIdx.x;
    const float* xr = x + row * 1024;
    const int t = threadIdx.x;
    float v[8];
    *reinterpret_cast<float4*>(&v[0]) = *reinterpret_cast<const float4*>(xr + t * 8);
    *reinterpret_cast<float4*>(&v[4]) = *reinterpret_cast<const float4*>(xr + t * 8 + 4);
    float s = 0.f;
#pragma unroll
    for (int i = 0; i < 8; ++i) s += v[i];
#pragma unroll
    for (int o = 16; o; o >>= 1) s += __shfl_xor_sync(0xffffffffu, s, o);
    if ((t & 31) == 0) red[t >> 5] = s;
    __syncthreads();
    const float mu = (red[0] + red[1] + red[2] + red[3]) * (1.f / 1024.f);
    __syncthreads();
    float ss = 0.f;
#pragma unroll
    for (int i = 0; i < 8; ++i) { float d = v[i] - mu; ss += d * d; }
#pragma unroll
    for (int o = 16; o; o >>= 1) ss += __shfl_xor_sync(0xffffffffu, ss, o);
    if ((t & 31) == 0) red[t >> 5] = ss;
    __syncthreads();
    const float rs = rsqrtf((red[0] + red[1] + red[2] + red[3]) * (1.f / 1024.f) + 1e-5f);
    float* orow = out + row * 1024;
    float* o2 = out2 ? (out2 + row * 1024) : (float*)0;
#pragma unroll
    for (int i = 0; i < 8; ++i) {
        const int c = t * 8 + i;
        const float y = (v[i] - mu) * rs * gm[c] + bt[c];
        if (mode == 0)      orow[c] = y;
        else if (mode == 1) orow[c] = rna_tf32(y);
        else { const float h = hi13(y); orow[c] = h; o2[c] = y - h; }
    }
}

// ---------------- softmax -> quant codes (zp=0), zero-pad cols [L,ld) ----------------
__global__ void softmax_quant(float* __restrict__ S, int L, int ld, const float* __restrict__ dptr)
{
    __shared__ float buf[2048];
    __shared__ float red[4];
    const long long row = blockIdx.x;
    float* r = S + row * (long long)ld;
    const int t = threadIdx.x;
    float mx = -3.0e38f;
    for (int j = t; j < L; j += 128) { float v = r[j]; buf[j] = v; mx = fmaxf(mx, v); }
#pragma unroll
    for (int o = 16; o; o >>= 1) mx = fmaxf(mx, __shfl_xor_sync(0xffffffffu, mx, o));
    if ((t & 31) == 0) red[t >> 5] = mx;
    __syncthreads();
    mx = fmaxf(fmaxf(red[0], red[1]), fmaxf(red[2], red[3]));
    __syncthreads();
    float s = 0.f;
    for (int j = t; j < L; j += 128) s += expf(buf[j] - mx);
#pragma unroll
    for (int o = 16; o; o >>= 1) s += __shfl_xor_sync(0xffffffffu, s, o);
    if ((t & 31) == 0) red[t >> 5] = s;
    __syncthreads();
    s = red[0] + red[1] + red[2] + red[3];
    const float delta = *dptr;
    for (int j = t; j < L; j += 128) {
        const float p = expf(buf[j] - mx) / s;
        r[j] = fminf(fmaxf(rintf(p / delta), 0.f), 255.f);
    }
    for (int j = L + t; j < ld; j += 128) r[j] = 0.f;
}

// ---------------- GEGLU (rna output: feeds ffn2 tf32 GEMM) ----------------
__global__ void geglu_kernel(const float* __restrict__ hg, float* __restrict__ gg)
{
    const long long i4 = (long long)blockIdx.x * blockDim.x + threadIdx.x;
    const long long r = i4 >> 10, c = (i4 & 1023) << 2;
    const float4 a = *reinterpret_cast<const float4*>(hg + r * 8192 + c);
    const float4 g = *reinterpret_cast<const float4*>(hg + r * 8192 + 4096 + c);
    const float k = 0.70710678118654752440f;
    float4 o;
    o.x = rna_tf32(a.x * (0.5f * g.x * (1.f + erff(g.x * k))));
    o.y = rna_tf32(a.y * (0.5f * g.y * (1.f + erff(g.y * k))));
    o.z = rna_tf32(a.z * (0.5f * g.z * (1.f + erff(g.z * k))));
    o.w = rna_tf32(a.w * (0.5f * g.w * (1.f + erff(g.w * k))));
    *reinterpret_cast<float4*>(gg + r * 4096 + c) = o;
}

// ---------------- launcher ----------------
extern "C" void kernel_launch(void* const* d_in, const int* in_sizes, int n_in,
                              void* d_out, int out_size)
{
    (void)in_sizes; (void)n_in; (void)out_size;
    const float* x   = (const float*)d_in[0];
    const float* ctx = (const float*)d_in[1];
    const float *ln1g = (const float*)d_in[2], *ln1b = (const float*)d_in[3];
    const float *ln2g = (const float*)d_in[4], *ln2b = (const float*)d_in[5];
    const float *ln3g = (const float*)d_in[6], *ln3b = (const float*)d_in[7];
    const float *wq1 = (const float*)d_in[8],  *wk1 = (const float*)d_in[9];
    const float *wv1 = (const float*)d_in[10], *wo1 = (const float*)d_in[11];
    const float *bo1 = (const float*)d_in[12];
    const float *wq2 = (const float*)d_in[13], *wk2 = (const float*)d_in[14];
    const float *wv2 = (const float*)d_in[15], *wo2 = (const float*)d_in[16];
    const float *bo2 = (const float*)d_in[17];
    const float *w1 = (const float*)d_in[18], *b1 = (const float*)d_in[19];
    const float *w2 = (const float*)d_in[20], *b2 = (const float*)d_in[21];
    const float *dq1 = (const float*)d_in[22], *dk1 = (const float*)d_in[23];
    const float *dv1 = (const float*)d_in[24], *dw1 = (const float*)d_in[25];
    const float *dq2 = (const float*)d_in[26], *dk2 = (const float*)d_in[27];
    const float *dv2 = (const float*)d_in[28], *dw2 = (const float*)d_in[29];
    float* out = (float*)d_out;

    float *px, *ph, *phl, *pq, *pk, *pv, *po, *pvt, *pS, *phg, *pgg, *pw, *pcs;
    cudaGetSymbolAddress((void**)&px,  g_x);
    cudaGetSymbolAddress((void**)&ph,  g_h);
    cudaGetSymbolAddress((void**)&phl, g_hl);
    cudaGetSymbolAddress((void**)&pq,  g_q);
    cudaGetSymbolAddress((void**)&pk,  g_k);
    cudaGetSymbolAddress((void**)&pv,  g_v);
    cudaGetSymbolAddress((void**)&po,  g_o);
    cudaGetSymbolAddress((void**)&pvt, g_vt);
    cudaGetSymbolAddress((void**)&pS,  g_S);
    cudaGetSymbolAddress((void**)&phg, g_hg);
    cudaGetSymbolAddress((void**)&pgg, g_gg);
    cudaGetSymbolAddress((void**)&pw,  g_w);
    cudaGetSymbolAddress((void**)&pcs, g_cs);

    const long long M1 = 1048576;
    float *q1h = pw,        *q1l = pw + M1,   *k1h = pw + 2*M1, *k1l = pw + 3*M1;
    float *v1h = pw + 4*M1, *v1l = pw + 5*M1, *q2h = pw + 6*M1, *q2l = pw + 7*M1;
    float *k2h = pw + 8*M1, *k2l = pw + 9*M1, *v2h = pw + 10*M1,*v2l = pw + 11*M1;
    float *o1t = pw + 12*M1, *o2t = pw + 13*M1, *w1t = pw + 14*M1, *w2t = pw + 22*M1;
    float *chi = pcs, *clo = pcs + 157696;

    dim3 tb(32, 8);
    wtrans_split<<<dim3(32,32), tb>>>(wq1, q1h, q1l, 1024, 1024);
    wtrans_split<<<dim3(32,32), tb>>>(wk1, k1h, k1l, 1024, 1024);
    wtrans_split<<<dim3(32,32), tb>>>(wv1, v1h, v1l, 1024, 1024);
    wtrans_split<<<dim3(32,32), tb>>>(wq2, q2h, q2l, 1024, 1024);
    wtrans_split<<<dim3(32,32), tb>>>(wk2, k2h, k2l, 1024, 1024);
    wtrans_split<<<dim3(32,32), tb>>>(wv2, v2h, v2l, 1024, 1024);
    wtrans<<<dim3(32,32),  tb>>>(wo1, o1t, 1024, 1024);
    wtrans<<<dim3(32,32),  tb>>>(wo2, o2t, 1024, 1024);
    wtrans<<<dim3(256,32), tb>>>(w1,  w1t, 1024, 8192);
    wtrans<<<dim3(32,128), tb>>>(w2,  w2t, 4096, 1024);
    esplit<<<616, 256>>>(ctx, chi, clo, 157696);

    const long long ND  = 2048LL * 1024;
    const long long SB1 = 16LL * 2048 * 2048, SH1 = 2048LL * 2048;
    const long long SB2 = 16LL * 2048 * 96,   SH2 = 2048LL * 96;
    const long long CKV = 77LL * 1024;
    const long long VT1b = 16LL * 64 * 2048, VT1h = 64LL * 2048;
    const long long VT2b = 16LL * 64 * 96,   VT2h = 64LL * 96;

    // ===== self attention =====
    ln_kernel<<<4096, 128>>>(x, ln1g, ln1b, ph, phl, 2);
    { GArgs g = ga(ph, phl, q1h, q1l, pq, 4096,1024,1024,1024, 1024,1024,1024); g.qd = dq1; run_mm<128,2,true>(g, 1); }
    { GArgs g = ga(ph, phl, k1h, k1l, pk, 4096,1024,1024,1024, 1024,1024,1024); g.qd = dk1; run_mm<128,2,true>(g, 1); }
    { GArgs g = ga(ph, phl, v1h, v1l, pv, 4096,1024,1024,1024, 1024,1024,1024); g.qd = dv1; run_mm<128,2,true>(g, 1); }
    vtrans<<<dim3(64,2,32), tb>>>(pv, pvt, 2048, 2048);
    { GArgs g = ga(pq, 0, pk, 0, pS, 2048,2048,2048,64, 1024,1024,2048);
      g.sAb = ND; g.sAh = 64; g.sBb = ND; g.sBh = 64; g.sCb = SB1; g.sCh = SH1;
      g.s0 = 0.125f; g.s1 = dq1; g.s2 = dk1; run_mm<128,2,false>(g, 32); }
    softmax_quant<<<65536, 128>>>(pS, 2048, 2048, dw1);
    { GArgs g = ga(pS, 0, pvt, 0, po, 2048,64,64,2048, 2048,2048,1024);
      g.sAb = SB1; g.sAh = SH1; g.sBb = VT1b; g.sBh = VT1h; g.sCb = ND; g.sCh = 64;
      g.s1 = dw1; g.s2 = dv1; g.rna_out = 1; run_mm<64,4,false>(g, 32); }
    { GArgs g = ga(po, 0, o1t, 0, px, 4096,1024,1024,1024, 1024,1024,1024);
      g.bias = bo1; g.res = x; g.ldr = 1024; run_mm<128,2,false>(g, 1); }

    // ===== cross attention =====
    ln_kernel<<<4096, 128>>>(px, ln2g, ln2b, ph, phl, 2);
    { GArgs g = ga(ph, phl, q2h, q2l, pq, 4096,1024,1024,1024, 1024,1024,1024); g.qd = dq2; run_mm<128,2,true>(g, 1); }
    { GArgs g = ga(chi, clo, k2h, k2l, pk, 154,1024,1024,1024, 1024,1024,1024); g.qd = dk2; run_mm<128,2,true>(g, 1); }
    { GArgs g = ga(chi, clo, v2h, v2l, pv, 154,1024,1024,1024, 1024,1024,1024); g.qd = dv2; run_mm<128,2,true>(g, 1); }
    vtrans<<<dim3(3,2,32), tb>>>(pv, pvt, 77, 96);
    { GArgs g = ga(pq, 0, pk, 0, pS, 2048,77,77,64, 1024,1024,96);
      g.sAb = ND; g.sAh = 64; g.sBb = CKV; g.sBh = 64; g.sCb = SB2; g.sCh = SH2;
      g.s0 = 0.125f; g.s1 = dq2; g.s2 = dk2; run_mm<128,2,false>(g, 32); }
    softmax_quant<<<65536, 128>>>(pS, 77, 96, dw2);
    { GArgs g = ga(pS, 0, pvt, 0, po, 2048,64,64,96, 96,96,1024);
      g.sAb = SB2; g.sAh = SH2; g.sBb = VT2b; g.sBh = VT2h; g.sCb = ND; g.sCh = 64;
      g.s1 = dw2; g.s2 = dv2; g.rna_out = 1; run_mm<64,4,false>(g, 32); }
    { GArgs g = ga(po, 0, o2t, 0, px, 4096,1024,1024,1024, 1024,1024,1024);
      g.bias = bo2; g.res = px; g.ldr = 1024; run_mm<128,2,false>(g, 1); }

    // ===== GEGLU feed-forward =====
    ln_kernel<<<4096, 128>>>(px, ln3g, ln3b, ph, 0, 1);
    { GArgs g = ga(ph, 0, w1t, 0, phg, 4096,8192,8192,1024, 1024,1024,8192);
      g.bias = b1; run_mm<128,2,false>(g, 1); }
    geglu_kernel<<<16384, 256>>>(phg, pgg);
    { GArgs g = ga(pgg, 0, w2t, 0, out, 4096,1024,1024,4096, 4096,4096,1024);
      g.bias = b2; g.res = px; g.ldr = 1024; run_mm<128,2,false>(g, 1); }
}

// round 7
// speedup vs baseline: 2.8344x; 1.3046x over previous
#include <cuda_runtime.h>
#include <cuda_fp16.h>
#include <cstdint>
#include <math.h>

// ---------------- scratch ----------------
__device__ float g_x [4194304];
__device__ float g_h [4194304];   // ln out: half hi (attn) or fp32 rna (ffn)
__device__ float g_hl[4194304];   // ln out: half lo
__device__ float g_q [4194304];   // half codes
__device__ float g_k [4194304];
__device__ float g_v [4194304];
__device__ float g_o [4194304];   // fp32 attn out
__device__ float g_vt[4194304];   // half v^T codes
__device__ float g_S [134217728]; // fp32 scores; P codes written in-place as half
__device__ float g_hg[33554432];
__device__ float g_gg[16777216];
__device__ float g_w [27262976];
__device__ float g_cs[327680];

// ---------------- helpers ----------------
static __device__ __forceinline__ uint32_t smem_u32(const void* p) {
    uint32_t a;
    asm("{ .reg .u64 t; cvta.to.shared.u64 t, %1; cvt.u32.u64 %0, t; }" : "=r"(a) : "l"(p));
    return a;
}
static __device__ __forceinline__ float rna_tf32(float x) {
    uint32_t u;
    asm("cvt.rna.tf32.f32 %0, %1;" : "=r"(u) : "f"(x));
    return __uint_as_float(u);
}
#define MMA4(d, a, b) \
    asm volatile("mma.sync.aligned.m16n8k8.row.col.f32.tf32.tf32.f32 " \
        "{%0,%1,%2,%3},{%4,%5,%6,%7},{%8,%9},{%0,%1,%2,%3};" \
        : "+f"((d)[0]), "+f"((d)[1]), "+f"((d)[2]), "+f"((d)[3]) \
        : "r"((a)[0]), "r"((a)[1]), "r"((a)[2]), "r"((a)[3]), "r"((b)[0]), "r"((b)[1]))
#define MMAH(d, a, b) \
    asm volatile("mma.sync.aligned.m16n8k16.row.col.f32.f16.f16.f32 " \
        "{%0,%1,%2,%3},{%4,%5,%6,%7},{%8,%9},{%0,%1,%2,%3};" \
        : "+f"((d)[0]), "+f"((d)[1]), "+f"((d)[2]), "+f"((d)[3]) \
        : "r"((a)[0]), "r"((a)[1]), "r"((a)[2]), "r"((a)[3]), "r"((b)[0]), "r"((b)[1]))
#define CPA(dst, src, sz) \
    asm volatile("cp.async.cg.shared.global [%0], [%1], 16, %2;" :: "r"(dst), "l"(src), "r"(sz))
static __device__ __forceinline__ uint32_t ld32h(const __half* p) {
    return *reinterpret_cast<const uint32_t*>(p);
}

// ================= fp16 mma GEMM =================
// C = s0*s1*s2*(A[M,K] @ B[N,K]^T)  [-> quant codes] [-> rna], batched (b,h)
struct HArgs {
    const __half *A, *Al, *B, *Bl; void* C;
    int M, N, Nstore, K, lda, ldb, ldc, rna_out;
    long long sAb, sAh, sBb, sBh, sCb, sCh;
    const float *s1, *s2, *qd;
    float s0;
};

template<int BN, int WM, bool SPLIT, bool CHALF>
__global__ void __launch_bounds__(256)
hgemm(const __grid_constant__ HArgs g)
{
    constexpr int WN = 8 / WM, WTM = 128 / WM, WTN = BN / WN;
    constexpr int MF = WTM / 16, NF = WTN / 8;
    constexpr int AS = 128 * 40, BS = BN * 40;          // halfs, stride 40
    constexpr int NT = SPLIT ? 2 : 1, STG = NT * (AS + BS);

    extern __shared__ __half smh[];
    const uint32_t smb = smem_u32(smh);
    const int tid = threadIdx.x, wid = tid >> 5, lane = tid & 31;
    const int grp = lane >> 2, tg = lane & 3;
    const int wm = wid / WN, wn = wid % WN;

    const int z = blockIdx.z, bb = z >> 4, hb = z & 15;
    const __half* Ab = g.A + bb * g.sAb + hb * g.sAh;
    const __half* Al = SPLIT ? (g.Al + bb * g.sAb + hb * g.sAh) : (const __half*)0;
    const __half* Bb = g.B + bb * g.sBb + hb * g.sBh;
    const __half* Bl = SPLIT ? (g.Bl + bb * g.sBb + hb * g.sBh) : (const __half*)0;

    const int bm = blockIdx.y * 128, bn = blockIdx.x * BN;
    const int nch = g.K >> 5;

    float acc[MF][NF][4];
#pragma unroll
    for (int i = 0; i < MF; ++i)
#pragma unroll
        for (int j = 0; j < NF; ++j)
#pragma unroll
            for (int c = 0; c < 4; ++c) acc[i][j][c] = 0.f;

    auto issue = [&](int ch, int st) {
        const int k0 = ch << 5;
        const uint32_t sa = smb + (uint32_t)st * STG * 2;
#pragma unroll
        for (int i = 0; i < 2; ++i) {          // A 128x32h
            const int idx = tid + (i << 8);
            const int r = idx >> 2, c = idx & 3;
            const int gr = bm + r, ok = (gr < g.M);
            const __half* s = ok ? (Ab + (long long)gr * g.lda + k0 + (c << 3)) : Ab;
            const uint32_t d = sa + (uint32_t)(r * 40 + (c << 3)) * 2;
            CPA(d, s, ok ? 16 : 0);
            if (SPLIT) {
                const __half* s2 = ok ? (Al + (long long)gr * g.lda + k0 + (c << 3)) : Al;
                CPA(d + AS * 2, s2, ok ? 16 : 0);
            }
        }
#pragma unroll
        for (int i = 0; i < BN / 64; ++i) {    // B BNx32h
            const int idx = tid + (i << 8);
            const int r = idx >> 2, c = idx & 3;
            const int gn = bn + r, ok = (gn < g.N);
            const __half* s = ok ? (Bb + (long long)gn * g.ldb + k0 + (c << 3)) : Bb;
            const uint32_t d = sa + (uint32_t)(NT * AS + r * 40 + (c << 3)) * 2;
            CPA(d, s, ok ? 16 : 0);
            if (SPLIT) {
                const __half* s2 = ok ? (Bl + (long long)gn * g.ldb + k0 + (c << 3)) : Bl;
                CPA(d + BS * 2, s2, ok ? 16 : 0);
            }
        }
    };

    auto compute = [&](int st) {
        const __half* sa  = smh + st * STG;
        const __half* sal = sa + AS;
        const __half* sbh = sa + NT * AS;
        const __half* sbl = sbh + BS;
#pragma unroll
        for (int kk = 0; kk < 2; ++kk) {
            const int kb = kk << 4;
            uint32_t bh[NF][2], bl[NF][2];
#pragma unroll
            for (int nf = 0; nf < NF; ++nf) {
                const int o = (wn * WTN + (nf << 3) + grp) * 40 + kb + (tg << 1);
                bh[nf][0] = ld32h(sbh + o); bh[nf][1] = ld32h(sbh + o + 8);
                if (SPLIT) { bl[nf][0] = ld32h(sbl + o); bl[nf][1] = ld32h(sbl + o + 8); }
            }
#pragma unroll
            for (int mf = 0; mf < MF; ++mf) {
                const int o = (wm * WTM + (mf << 4) + grp) * 40 + kb + (tg << 1);
                uint32_t ah[4] = { ld32h(sa + o), ld32h(sa + o + 320),
                                   ld32h(sa + o + 8), ld32h(sa + o + 328) };
#pragma unroll
                for (int nf = 0; nf < NF; ++nf) MMAH(acc[mf][nf], ah, bh[nf]);
                if (SPLIT) {
                    uint32_t al[4] = { ld32h(sal + o), ld32h(sal + o + 320),
                                       ld32h(sal + o + 8), ld32h(sal + o + 328) };
#pragma unroll
                    for (int nf = 0; nf < NF; ++nf) {
                        MMAH(acc[mf][nf], ah, bl[nf]);
                        MMAH(acc[mf][nf], al, bh[nf]);
                    }
                }
            }
        }
    };

    issue(0, 0);
    asm volatile("cp.async.commit_group;");
    for (int ch = 0; ch < nch; ++ch) {
        if (ch + 1 < nch) issue(ch + 1, (ch + 1) & 1);
        asm volatile("cp.async.commit_group;");
        asm volatile("cp.async.wait_group 1;");
        __syncthreads();
        compute(ch & 1);
        __syncthreads();
    }

    float alpha = g.s0;
    if (g.s1) alpha *= __ldg(g.s1);
    if (g.s2) alpha *= __ldg(g.s2);
    const float qd = g.qd ? __ldg(g.qd) : 1.f;
#pragma unroll
    for (int mf = 0; mf < MF; ++mf) {
        const int r0 = bm + wm * WTM + (mf << 4) + grp;
#pragma unroll
        for (int nf = 0; nf < NF; ++nf) {
            const int c0 = bn + wn * WTN + (nf << 3) + (tg << 1);
#pragma unroll
            for (int e = 0; e < 4; ++e) {
                const int r = r0 + ((e >> 1) << 3);
                const int c = c0 + (e & 1);
                if (r < g.M && c < g.Nstore) {
                    float v = acc[mf][nf][e] * alpha;
                    if (g.qd) {
                        float xi = rintf(v / qd) + 128.f;
                        v = fminf(fmaxf(xi, 0.f), 255.f) - 128.f;
                    }
                    if (g.rna_out) v = rna_tf32(v);
                    const long long o = (long long)(bb * g.sCb + hb * g.sCh) + (long long)r * g.ldc + c;
                    if (CHALF) ((__half*)g.C)[o] = __float2half_rn(v);
                    else       ((float*)g.C)[o] = v;
                }
            }
        }
    }
}

template<int BN, int WM, bool SPLIT, bool CHALF>
static void run_h(HArgs a, int nb)
{
    constexpr int STG = (SPLIT ? 2 : 1) * (128 * 40 + BN * 40);
    const int smem = 2 * STG * 2;
    cudaFuncSetAttribute(hgemm<BN, WM, SPLIT, CHALF>,
                         cudaFuncAttributeMaxDynamicSharedMemorySize, smem);
    dim3 grid((a.N + BN - 1) / BN, (a.M + 127) / 128, nb);
    hgemm<BN, WM, SPLIT, CHALF><<<grid, 256, smem>>>(a);
}
static HArgs ha(const __half* A, const __half* Al, const __half* B, const __half* Bl,
                void* C, int M, int N, int Nstore, int K, int lda, int ldb, int ldc)
{
    HArgs g;
    g.A = A; g.Al = Al; g.B = B; g.Bl = Bl; g.C = C;
    g.M = M; g.N = N; g.Nstore = Nstore; g.K = K;
    g.lda = lda; g.ldb = ldb; g.ldc = ldc; g.rna_out = 0;
    g.sAb = g.sAh = g.sBb = g.sBh = g.sCb = g.sCh = 0;
    g.s1 = 0; g.s2 = 0; g.qd = 0; g.s0 = 1.f;
    return g;
}

// ================= tf32 mma GEMM (wo / FFN) =================
// C = A[M,K] @ B[N,K]^T + bias [+ res]
struct GArgs {
    const float *A, *B; float* C;
    int M, N, K, lda, ldb, ldc;
    const float *bias, *res;
};

template<int BN, int WM>
__global__ void __launch_bounds__(256, 2)
mmagemm(const __grid_constant__ GArgs g)
{
    constexpr int WN = 8 / WM, WTM = 128 / WM, WTN = BN / WN;
    constexpr int MF = WTM / 16, NF = WTN / 8;
    constexpr int AS = 128 * 36, BS = BN * 36, STG = AS + BS;

    extern __shared__ float sm[];
    const uint32_t smb = smem_u32(sm);
    const int tid = threadIdx.x, wid = tid >> 5, lane = tid & 31;
    const int grp = lane >> 2, tg = lane & 3;
    const int wm = wid / WN, wn = wid % WN;
    const int bm = blockIdx.y * 128, bn = blockIdx.x * BN;
    const int nch = g.K >> 5;

    float acc[MF][NF][4];
#pragma unroll
    for (int i = 0; i < MF; ++i)
#pragma unroll
        for (int j = 0; j < NF; ++j)
#pragma unroll
            for (int c = 0; c < 4; ++c) acc[i][j][c] = 0.f;

    auto issue = [&](int ch, int st) {
        const int k0 = ch << 5;
        const uint32_t sa = smb + (uint32_t)st * STG * 4;
#pragma unroll
        for (int i = 0; i < 4; ++i) {
            const int idx = tid + (i << 8);
            const int r = idx >> 3, c4 = idx & 7;
            const int gr = bm + r, ok = (gr < g.M);
            const float* s = ok ? (g.A + (long long)gr * g.lda + k0 + (c4 << 2)) : g.A;
            CPA(sa + (uint32_t)(r * 36 + (c4 << 2)) * 4, s, ok ? 16 : 0);
        }
#pragma unroll
        for (int i = 0; i < BN / 32; ++i) {
            const int idx = tid + (i << 8);
            const int r = idx >> 3, c4 = idx & 7;
            const int gn = bn + r, ok = (gn < g.N);
            const float* s = ok ? (g.B + (long long)gn * g.ldb + k0 + (c4 << 2)) : g.B;
            CPA(sa + (uint32_t)(AS + r * 36 + (c4 << 2)) * 4, s, ok ? 16 : 0);
        }
    };
    auto compute = [&](int st) {
        const float* sa = sm + st * STG;
        const float* sb = sa + AS;
#pragma unroll
        for (int kk = 0; kk < 4; ++kk) {
            const int kb = kk << 3;
            uint32_t bf[NF][2];
#pragma unroll
            for (int nf = 0; nf < NF; ++nf) {
                const int o = (wn * WTN + (nf << 3) + grp) * 36 + kb + tg;
                bf[nf][0] = __float_as_uint(sb[o]);
                bf[nf][1] = __float_as_uint(sb[o + 4]);
            }
#pragma unroll
            for (int mf = 0; mf < MF; ++mf) {
                const int o = (wm * WTM + (mf << 4) + grp) * 36 + kb + tg;
                uint32_t af[4] = { __float_as_uint(sa[o]),     __float_as_uint(sa[o + 288]),
                                   __float_as_uint(sa[o + 4]), __float_as_uint(sa[o + 292]) };
#pragma unroll
                for (int nf = 0; nf < NF; ++nf) MMA4(acc[mf][nf], af, bf[nf]);
            }
        }
    };

    issue(0, 0);
    asm volatile("cp.async.commit_group;");
    for (int ch = 0; ch < nch; ++ch) {
        if (ch + 1 < nch) issue(ch + 1, (ch + 1) & 1);
        asm volatile("cp.async.commit_group;");
        asm volatile("cp.async.wait_group 1;");
        __syncthreads();
        compute(ch & 1);
        __syncthreads();
    }

#pragma unroll
    for (int mf = 0; mf < MF; ++mf) {
        const int r0 = bm + wm * WTM + (mf << 4) + grp;
#pragma unroll
        for (int nf = 0; nf < NF; ++nf) {
            const int c0 = bn + wn * WTN + (nf << 3) + (tg << 1);
#pragma unroll
            for (int e = 0; e < 4; ++e) {
                const int r = r0 + ((e >> 1) << 3);
                const int c = c0 + (e & 1);
                if (r < g.M && c < g.N) {
                    float v = acc[mf][nf][e] + __ldg(g.bias + c);
                    if (g.res) v += g.res[(long long)r * g.N + c];
                    g.C[(long long)r * g.ldc + c] = v;
                }
            }
        }
    }
}
template<int BN, int WM>
static void run_g(GArgs a)
{
    constexpr int STG = 128 * 36 + BN * 36;
    const int smem = 2 * STG * 4;
    cudaFuncSetAttribute(mmagemm<BN, WM>, cudaFuncAttributeMaxDynamicSharedMemorySize, smem);
    dim3 grid((a.N + BN - 1) / BN, (a.M + 127) / 128, 1);
    mmagemm<BN, WM><<<grid, 256, smem>>>(a);
}

// ---------------- transposes / splits ----------------
__global__ void wtrans(const float* __restrict__ in, float* __restrict__ out, int K, int N)
{
    __shared__ float t[32][33];
    const int n0 = blockIdx.x * 32, k0 = blockIdx.y * 32;
    const int tx = threadIdx.x, ty = threadIdx.y;
#pragma unroll
    for (int i = 0; i < 32; i += 8)
        t[ty + i][tx] = in[(long long)(k0 + ty + i) * N + n0 + tx];
    __syncthreads();
#pragma unroll
    for (int i = 0; i < 32; i += 8)
        out[(long long)(n0 + ty + i) * K + k0 + tx] = rna_tf32(t[tx][ty + i]);
}
__global__ void wtrans_split(const float* __restrict__ in, __half* __restrict__ oH,
                             __half* __restrict__ oL, int K, int N)
{
    __shared__ float t[32][33];
    const int n0 = blockIdx.x * 32, k0 = blockIdx.y * 32;
    const int tx = threadIdx.x, ty = threadIdx.y;
#pragma unroll
    for (int i = 0; i < 32; i += 8)
        t[ty + i][tx] = in[(long long)(k0 + ty + i) * N + n0 + tx];
    __syncthreads();
#pragma unroll
    for (int i = 0; i < 32; i += 8) {
        const float v = t[tx][ty + i];
        const __half h = __float2half_rn(v);
        const long long o = (long long)(n0 + ty + i) * K + k0 + tx;
        oH[o] = h; oL[o] = __float2half_rn(v - __half2float(h));
    }
}
__global__ void vtrans(const __half* __restrict__ v, __half* __restrict__ vt, int T, int Tpad)
{
    __shared__ float t[32][33];
    const int bz = blockIdx.z, b = bz >> 4, h = bz & 15;
    const int t0 = blockIdx.x * 32, d0 = blockIdx.y * 32;
    const int tx = threadIdx.x, ty = threadIdx.y;
#pragma unroll
    for (int i = 0; i < 32; i += 8) {
        const int tt = t0 + ty + i;
        t[ty + i][tx] = (tt < T) ? __half2float(v[((long long)b * T + tt) * 1024 + h * 64 + d0 + tx]) : 0.f;
    }
    __syncthreads();
#pragma unroll
    for (int i = 0; i < 32; i += 8) {
        const int tt = t0 + tx;
        if (tt < Tpad)
            vt[(((long long)b * 16 + h) * 64 + d0 + ty + i) * Tpad + tt] = __float2half_rn(t[tx][ty + i]);
    }
}
__global__ void esplit(const float* __restrict__ in, __half* __restrict__ oH,
                       __half* __restrict__ oL, int n)
{
    const int i = blockIdx.x * 256 + threadIdx.x;
    if (i < n) {
        const float v = in[i];
        const __half h = __float2half_rn(v);
        oH[i] = h; oL[i] = __float2half_rn(v - __half2float(h));
    }
}

// ---------------- layernorm ----------------
__global__ void ln_kernel(const float* __restrict__ x, const float* __restrict__ gm,
                          const float* __restrict__ bt, float* __restrict__ outF,
                          __half* __restrict__ outH, __half* __restrict__ outL)
{
    __shared__ float red[4];
    const long long row = blockIdx.x;
    const float* xr = x + row * 1024;
    const int t = threadIdx.x;
    float v[8];
    *reinterpret_cast<float4*>(&v[0]) = *reinterpret_cast<const float4*>(xr + t * 8);
    *reinterpret_cast<float4*>(&v[4]) = *reinterpret_cast<const float4*>(xr + t * 8 + 4);
    float s = 0.f;
#pragma unroll
    for (int i = 0; i < 8; ++i) s += v[i];
#pragma unroll
    for (int o = 16; o; o >>= 1) s += __shfl_xor_sync(0xffffffffu, s, o);
    if ((t & 31) == 0) red[t >> 5] = s;
    __syncthreads();
    const float mu = (red[0] + red[1] + red[2] + red[3]) * (1.f / 1024.f);
    __syncthreads();
    float ss = 0.f;
#pragma unroll
    for (int i = 0; i < 8; ++i) { float d = v[i] - mu; ss += d * d; }
#pragma unroll
    for (int o = 16; o; o >>= 1) ss += __shfl_xor_sync(0xffffffffu, ss, o);
    if ((t & 31) == 0) red[t >> 5] = ss;
    __syncthreads();
    const float rs = rsqrtf((red[0] + red[1] + red[2] + red[3]) * (1.f / 1024.f) + 1e-5f);
#pragma unroll
    for (int i = 0; i < 8; ++i) {
        const int c = t * 8 + i;
        const float y = (v[i] - mu) * rs * gm[c] + bt[c];
        if (outF) outF[row * 1024 + c] = rna_tf32(y);
        else {
            const __half h = __float2half_rn(y);
            outH[row * 1024 + c] = h;
            outL[row * 1024 + c] = __float2half_rn(y - __half2float(h));
        }
    }
}

// ---------------- softmax -> half codes in-place, pad [L,ldp) ----------------
__global__ void softmax_quant(float* __restrict__ S, int L, int ld, int ldp,
                              const float* __restrict__ dptr)
{
    __shared__ float buf[2048];
    __shared__ float red[4];
    const long long row = blockIdx.x;
    float* r = S + row * (long long)ld;
    const int t = threadIdx.x;
    float mx = -3.0e38f;
    for (int j = t; j < L; j += 128) { float v = r[j]; buf[j] = v; mx = fmaxf(mx, v); }
#pragma unroll
    for (int o = 16; o; o >>= 1) mx = fmaxf(mx, __shfl_xor_sync(0xffffffffu, mx, o));
    if ((t & 31) == 0) red[t >> 5] = mx;
    __syncthreads();
    mx = fmaxf(fmaxf(red[0], red[1]), fmaxf(red[2], red[3]));
    __syncthreads();
    float s = 0.f;
    for (int j = t; j < L; j += 128) s += expf(buf[j] - mx);
#pragma unroll
    for (int o = 16; o; o >>= 1) s += __shfl_xor_sync(0xffffffffu, s, o);
    if ((t & 31) == 0) red[t >> 5] = s;
    __syncthreads();
    s = red[0] + red[1] + red[2] + red[3];
    const float delta = *dptr;
    __half* hp = reinterpret_cast<__half*>(r);
    __syncthreads();
    for (int j = t; j < L; j += 128) {
        const float p = expf(buf[j] - mx) / s;
        hp[j] = __float2half_rn(fminf(fmaxf(rintf(p / delta), 0.f), 255.f));
    }
    for (int j = L + t; j < ldp; j += 128) hp[j] = __float2half_rn(0.f);
}

// ---------------- GEGLU ----------------
__global__ void geglu_kernel(const float* __restrict__ hg, float* __restrict__ gg)
{
    const long long i4 = (long long)blockIdx.x * blockDim.x + threadIdx.x;
    const long long r = i4 >> 10, c = (i4 & 1023) << 2;
    const float4 a = *reinterpret_cast<const float4*>(hg + r * 8192 + c);
    const float4 g = *reinterpret_cast<const float4*>(hg + r * 8192 + 4096 + c);
    const float k = 0.70710678118654752440f;
    float4 o;
    o.x = rna_tf32(a.x * (0.5f * g.x * (1.f + erff(g.x * k))));
    o.y = rna_tf32(a.y * (0.5f * g.y * (1.f + erff(g.y * k))));
    o.z = rna_tf32(a.z * (0.5f * g.z * (1.f + erff(g.z * k))));
    o.w = rna_tf32(a.w * (0.5f * g.w * (1.f + erff(g.w * k))));
    *reinterpret_cast<float4*>(gg + r * 4096 + c) = o;
}

// ---------------- launcher ----------------
extern "C" void kernel_launch(void* const* d_in, const int* in_sizes, int n_in,
                              void* d_out, int out_size)
{
    (void)in_sizes; (void)n_in; (void)out_size;
    const float* x   = (const float*)d_in[0];
    const float* ctx = (const float*)d_in[1];
    const float *ln1g = (const float*)d_in[2], *ln1b = (const float*)d_in[3];
    const float *ln2g = (const float*)d_in[4], *ln2b = (const float*)d_in[5];
    const float *ln3g = (const float*)d_in[6], *ln3b = (const float*)d_in[7];
    const float *wq1 = (const float*)d_in[8],  *wk1 = (const float*)d_in[9];
    const float *wv1 = (const float*)d_in[10], *wo1 = (const float*)d_in[11];
    const float *bo1 = (const float*)d_in[12];
    const float *wq2 = (const float*)d_in[13], *wk2 = (const float*)d_in[14];
    const float *wv2 = (const float*)d_in[15], *wo2 = (const float*)d_in[16];
    const float *bo2 = (const float*)d_in[17];
    const float *w1 = (const float*)d_in[18], *b1 = (const float*)d_in[19];
    const float *w2 = (const float*)d_in[20], *b2 = (const float*)d_in[21];
    const float *dq1 = (const float*)d_in[22], *dk1 = (const float*)d_in[23];
    const float *dv1 = (const float*)d_in[24], *dw1 = (const float*)d_in[25];
    const float *dq2 = (const float*)d_in[26], *dk2 = (const float*)d_in[27];
    const float *dv2 = (const float*)d_in[28], *dw2 = (const float*)d_in[29];
    float* out = (float*)d_out;

    float *px, *ph, *phl, *pq, *pk, *pv, *po, *pvt, *pS, *phg, *pgg, *pw, *pcs;
    cudaGetSymbolAddress((void**)&px,  g_x);
    cudaGetSymbolAddress((void**)&ph,  g_h);
    cudaGetSymbolAddress((void**)&phl, g_hl);
    cudaGetSymbolAddress((void**)&pq,  g_q);
    cudaGetSymbolAddress((void**)&pk,  g_k);
    cudaGetSymbolAddress((void**)&pv,  g_v);
    cudaGetSymbolAddress((void**)&po,  g_o);
    cudaGetSymbolAddress((void**)&pvt, g_vt);
    cudaGetSymbolAddress((void**)&pS,  g_S);
    cudaGetSymbolAddress((void**)&phg, g_hg);
    cudaGetSymbolAddress((void**)&pgg, g_gg);
    cudaGetSymbolAddress((void**)&pw,  g_w);
    cudaGetSymbolAddress((void**)&pcs, g_cs);

    __half *hh = (__half*)ph, *hhl = (__half*)phl;
    __half *hq = (__half*)pq, *hk = (__half*)pk, *hv = (__half*)pv, *hvt = (__half*)pvt;
    __half *hS = (__half*)pS;

    const long long M1 = 1048576;
    __half *q1h = (__half*)pw,          *q1l = (__half*)(pw + M1);
    __half *k1h = (__half*)(pw + 2*M1), *k1l = (__half*)(pw + 3*M1);
    __half *v1h = (__half*)(pw + 4*M1), *v1l = (__half*)(pw + 5*M1);
    __half *q2h = (__half*)(pw + 6*M1), *q2l = (__half*)(pw + 7*M1);
    __half *k2h = (__half*)(pw + 8*M1), *k2l = (__half*)(pw + 9*M1);
    __half *v2h = (__half*)(pw + 10*M1),*v2l = (__half*)(pw + 11*M1);
    float  *o1t = pw + 12*M1, *o2t = pw + 13*M1, *w1t = pw + 14*M1, *w2t = pw + 22*M1;
    __half *chi = (__half*)pcs, *clo = (__half*)(pcs + 80000);

    dim3 tb(32, 8);
    wtrans_split<<<dim3(32,32), tb>>>(wq1, q1h, q1l, 1024, 1024);
    wtrans_split<<<dim3(32,32), tb>>>(wk1, k1h, k1l, 1024, 1024);
    wtrans_split<<<dim3(32,32), tb>>>(wv1, v1h, v1l, 1024, 1024);
    wtrans_split<<<dim3(32,32), tb>>>(wq2, q2h, q2l, 1024, 1024);
    wtrans_split<<<dim3(32,32), tb>>>(wk2, k2h, k2l, 1024, 1024);
    wtrans_split<<<dim3(32,32), tb>>>(wv2, v2h, v2l, 1024, 1024);
    wtrans<<<dim3(32,32),  tb>>>(wo1, o1t, 1024, 1024);
    wtrans<<<dim3(32,32),  tb>>>(wo2, o2t, 1024, 1024);
    wtrans<<<dim3(256,32), tb>>>(w1,  w1t, 1024, 8192);
    wtrans<<<dim3(32,128), tb>>>(w2,  w2t, 4096, 1024);
    esplit<<<616, 256>>>(ctx, chi, clo, 157696);

    const long long ND  = 2048LL * 1024;
    const long long SB1 = 16LL * 2048 * 2048, SH1 = 2048LL * 2048;
    const long long SB2 = 16LL * 2048 * 96,   SH2 = 2048LL * 96;
    const long long CKV = 77LL * 1024;
    const long long VT1b = 16LL * 64 * 2048, VT1h = 64LL * 2048;
    const long long VT2b = 16LL * 64 * 96,   VT2h = 64LL * 96;

    // ===== self attention =====
    ln_kernel<<<4096, 128>>>(x, ln1g, ln1b, 0, hh, hhl);
    { HArgs g = ha(hh, hhl, q1h, q1l, hq, 4096,1024,1024,1024, 1024,1024,1024); g.qd = dq1; run_h<128,2,true,true>(g, 1); }
    { HArgs g = ha(hh, hhl, k1h, k1l, hk, 4096,1024,1024,1024, 1024,1024,1024); g.qd = dk1; run_h<128,2,true,true>(g, 1); }
    { HArgs g = ha(hh, hhl, v1h, v1l, hv, 4096,1024,1024,1024, 1024,1024,1024); g.qd = dv1; run_h<128,2,true,true>(g, 1); }
    vtrans<<<dim3(64,2,32), tb>>>(hv, hvt, 2048, 2048);
    { HArgs g = ha(hq, 0, hk, 0, pS, 2048,2048,2048,64, 1024,1024,2048);
      g.sAb = ND; g.sAh = 64; g.sBb = ND; g.sBh = 64; g.sCb = SB1; g.sCh = SH1;
      g.s0 = 0.125f; g.s1 = dq1; g.s2 = dk1; run_h<128,2,false,false>(g, 32); }
    softmax_quant<<<65536, 128>>>(pS, 2048, 2048, 2048, dw1);
    { HArgs g = ha(hS, 0, hvt, 0, po, 2048,64,64,2048, 4096,2048,1024);
      g.sAb = 2*SB1; g.sAh = 2*SH1; g.sBb = VT1b; g.sBh = VT1h; g.sCb = ND; g.sCh = 64;
      g.s1 = dw1; g.s2 = dv1; g.rna_out = 1; run_h<64,4,false,false>(g, 32); }
    { GArgs g{po, o1t, px, 4096,1024,1024, 1024,1024,1024, bo1, x}; run_g<128,2>(g); }

    // ===== cross attention =====
    ln_kernel<<<4096, 128>>>(px, ln2g, ln2b, 0, hh, hhl);
    { HArgs g = ha(hh, hhl, q2h, q2l, hq, 4096,1024,1024,1024, 1024,1024,1024); g.qd = dq2; run_h<128,2,true,true>(g, 1); }
    { HArgs g = ha(chi, clo, k2h, k2l, hk, 154,1024,1024,1024, 1024,1024,1024); g.qd = dk2; run_h<128,2,true,true>(g, 1); }
    { HArgs g = ha(chi, clo, v2h, v2l, hv, 154,1024,1024,1024, 1024,1024,1024); g.qd = dv2; run_h<128,2,true,true>(g, 1); }
    vtrans<<<dim3(3,2,32), tb>>>(hv, hvt, 77, 96);
    { HArgs g = ha(hq, 0, hk, 0, pS, 2048,77,77,64, 1024,1024,96);
      g.sAb = ND; g.sAh = 64; g.sBb = CKV; g.sBh = 64; g.sCb = SB2; g.sCh = SH2;
      g.s0 = 0.125f; g.s1 = dq2; g.s2 = dk2; run_h<128,2,false,false>(g, 32); }
    softmax_quant<<<65536, 128>>>(pS, 77, 96, 96, dw2);
    { HArgs g = ha(hS, 0, hvt, 0, po, 2048,64,64,96, 192,96,1024);
      g.sAb = 2*SB2; g.sAh = 2*SH2; g.sBb = VT2b; g.sBh = VT2h; g.sCb = ND; g.sCh = 64;
      g.s1 = dw2; g.s2 = dv2; g.rna_out = 1; run_h<64,4,false,false>(g, 32); }
    { GArgs g{po, o2t, px, 4096,1024,1024, 1024,1024,1024, bo2, px}; run_g<128,2>(g); }

    // ===== GEGLU feed-forward =====
    ln_kernel<<<4096, 128>>>(px, ln3g, ln3b, ph, 0, 0);
    { GArgs g{ph, w1t, phg, 4096,8192,1024, 1024,1024,8192, b1, 0}; run_g<128,2>(g); }
    geglu_kernel<<<16384, 256>>>(phg, pgg);
    { GArgs g{pgg, w2t, out, 4096,1024,4096, 4096,4096,1024, b2, px}; run_g<128,2>(g); }
}

// round 8
// speedup vs baseline: 3.0061x; 1.0606x over previous
#include <cuda_runtime.h>
#include <cuda_fp16.h>
#include <cstdint>
#include <math.h>

// ---------------- scratch ----------------
__device__ float g_x [4194304];
__device__ float g_h [4194304];   // ln out: half hi
__device__ float g_hl[4194304];   // ln out: half lo
__device__ float g_q [4194304];   // half codes
__device__ float g_k [4194304];
__device__ float g_v [4194304];
__device__ float g_o [4194304];   // half attn out
__device__ float g_vt[4194304];   // half v^T codes
__device__ float g_S [134217728]; // fp32 scores; P codes written in-place as half
__device__ float g_hg[33554432];  // fp32 FFN intermediate
__device__ float g_gg[16777216];  // half GEGLU out (reinterpret)
__device__ float g_w [27262976];
__device__ float g_cs[327680];

// ---------------- helpers ----------------
static __device__ __forceinline__ uint32_t smem_u32(const void* p) {
    uint32_t a;
    asm("{ .reg .u64 t; cvta.to.shared.u64 t, %1; cvt.u32.u64 %0, t; }" : "=r"(a) : "l"(p));
    return a;
}
#define MMAH(d, a, b) \
    asm volatile("mma.sync.aligned.m16n8k16.row.col.f32.f16.f16.f32 " \
        "{%0,%1,%2,%3},{%4,%5,%6,%7},{%8,%9},{%0,%1,%2,%3};" \
        : "+f"((d)[0]), "+f"((d)[1]), "+f"((d)[2]), "+f"((d)[3]) \
        : "r"((a)[0]), "r"((a)[1]), "r"((a)[2]), "r"((a)[3]), "r"((b)[0]), "r"((b)[1]))
#define CPA(dst, src, sz) \
    asm volatile("cp.async.cg.shared.global [%0], [%1], 16, %2;" :: "r"(dst), "l"(src), "r"(sz))
static __device__ __forceinline__ uint32_t ld32h(const __half* p) {
    return *reinterpret_cast<const uint32_t*>(p);
}

// ================= fp16 mma GEMM =================
// C = s0*s1*s2*(A[M,K] @ B[N,K]^T) [+bias] [+res] [-> quant codes], batched (b,h)
struct HArgs {
    const __half *A, *Al, *B, *Bl; void* C;
    int M, N, Nstore, K, lda, ldb, ldc, ldr;
    long long sAb, sAh, sBb, sBh, sCb, sCh;
    const float *bias, *res, *s1, *s2, *qd;
    float s0;
};

template<int BN, int WM, bool SPLIT, bool CHALF>
__global__ void __launch_bounds__(256)
hgemm(const __grid_constant__ HArgs g)
{
    constexpr int WN = 8 / WM, WTM = 128 / WM, WTN = BN / WN;
    constexpr int MF = WTM / 16, NF = WTN / 8;
    constexpr int AS = 128 * 40, BS = BN * 40;          // halfs, stride 40
    constexpr int NT = SPLIT ? 2 : 1, STG = NT * (AS + BS);

    extern __shared__ __half smh[];
    const uint32_t smb = smem_u32(smh);
    const int tid = threadIdx.x, wid = tid >> 5, lane = tid & 31;
    const int grp = lane >> 2, tg = lane & 3;
    const int wm = wid / WN, wn = wid % WN;

    const int z = blockIdx.z, bb = z >> 4, hb = z & 15;
    const __half* Ab = g.A + bb * g.sAb + hb * g.sAh;
    const __half* Al = SPLIT ? (g.Al + bb * g.sAb + hb * g.sAh) : (const __half*)0;
    const __half* Bb = g.B + bb * g.sBb + hb * g.sBh;
    const __half* Bl = SPLIT ? (g.Bl + bb * g.sBb + hb * g.sBh) : (const __half*)0;

    const int bm = blockIdx.y * 128, bn = blockIdx.x * BN;
    const int nch = g.K >> 5;

    float acc[MF][NF][4];
#pragma unroll
    for (int i = 0; i < MF; ++i)
#pragma unroll
        for (int j = 0; j < NF; ++j)
#pragma unroll
            for (int c = 0; c < 4; ++c) acc[i][j][c] = 0.f;

    auto issue = [&](int ch, int st) {
        const int k0 = ch << 5;
        const uint32_t sa = smb + (uint32_t)st * STG * 2;
#pragma unroll
        for (int i = 0; i < 2; ++i) {          // A 128x32h
            const int idx = tid + (i << 8);
            const int r = idx >> 2, c = idx & 3;
            const int gr = bm + r, ok = (gr < g.M);
            const __half* s = ok ? (Ab + (long long)gr * g.lda + k0 + (c << 3)) : Ab;
            const uint32_t d = sa + (uint32_t)(r * 40 + (c << 3)) * 2;
            CPA(d, s, ok ? 16 : 0);
            if (SPLIT) {
                const __half* s2 = ok ? (Al + (long long)gr * g.lda + k0 + (c << 3)) : Al;
                CPA(d + AS * 2, s2, ok ? 16 : 0);
            }
        }
#pragma unroll
        for (int i = 0; i < BN / 64; ++i) {    // B BNx32h
            const int idx = tid + (i << 8);
            const int r = idx >> 2, c = idx & 3;
            const int gn = bn + r, ok = (gn < g.N);
            const __half* s = ok ? (Bb + (long long)gn * g.ldb + k0 + (c << 3)) : Bb;
            const uint32_t d = sa + (uint32_t)(NT * AS + r * 40 + (c << 3)) * 2;
            CPA(d, s, ok ? 16 : 0);
            if (SPLIT) {
                const __half* s2 = ok ? (Bl + (long long)gn * g.ldb + k0 + (c << 3)) : Bl;
                CPA(d + BS * 2, s2, ok ? 16 : 0);
            }
        }
    };

    auto compute = [&](int st) {
        const __half* sa  = smh + st * STG;
        const __half* sal = sa + AS;
        const __half* sbh = sa + NT * AS;
        const __half* sbl = sbh + BS;
#pragma unroll
        for (int kk = 0; kk < 2; ++kk) {
            const int kb = kk << 4;
            uint32_t bh[NF][2], bl[NF][2];
#pragma unroll
            for (int nf = 0; nf < NF; ++nf) {
                const int o = (wn * WTN + (nf << 3) + grp) * 40 + kb + (tg << 1);
                bh[nf][0] = ld32h(sbh + o); bh[nf][1] = ld32h(sbh + o + 8);
                if (SPLIT) { bl[nf][0] = ld32h(sbl + o); bl[nf][1] = ld32h(sbl + o + 8); }
            }
#pragma unroll
            for (int mf = 0; mf < MF; ++mf) {
                const int o = (wm * WTM + (mf << 4) + grp) * 40 + kb + (tg << 1);
                uint32_t ah[4] = { ld32h(sa + o), ld32h(sa + o + 320),
                                   ld32h(sa + o + 8), ld32h(sa + o + 328) };
#pragma unroll
                for (int nf = 0; nf < NF; ++nf) MMAH(acc[mf][nf], ah, bh[nf]);
                if (SPLIT) {
                    uint32_t al[4] = { ld32h(sal + o), ld32h(sal + o + 320),
                                       ld32h(sal + o + 8), ld32h(sal + o + 328) };
#pragma unroll
                    for (int nf = 0; nf < NF; ++nf) {
                        MMAH(acc[mf][nf], ah, bl[nf]);
                        MMAH(acc[mf][nf], al, bh[nf]);
                    }
                }
            }
        }
    };

    issue(0, 0);
    asm volatile("cp.async.commit_group;");
    for (int ch = 0; ch < nch; ++ch) {
        if (ch + 1 < nch) issue(ch + 1, (ch + 1) & 1);
        asm volatile("cp.async.commit_group;");
        asm volatile("cp.async.wait_group 1;");
        __syncthreads();
        compute(ch & 1);
        __syncthreads();
    }

    float alpha = g.s0;
    if (g.s1) alpha *= __ldg(g.s1);
    if (g.s2) alpha *= __ldg(g.s2);
    const float qd = g.qd ? __ldg(g.qd) : 1.f;
#pragma unroll
    for (int mf = 0; mf < MF; ++mf) {
        const int r0 = bm + wm * WTM + (mf << 4) + grp;
#pragma unroll
        for (int nf = 0; nf < NF; ++nf) {
            const int c0 = bn + wn * WTN + (nf << 3) + (tg << 1);
#pragma unroll
            for (int e = 0; e < 4; ++e) {
                const int r = r0 + ((e >> 1) << 3);
                const int c = c0 + (e & 1);
                if (r < g.M && c < g.Nstore) {
                    float v = acc[mf][nf][e] * alpha;
                    if (g.bias) v += __ldg(g.bias + c);
                    if (g.res)  v += g.res[(long long)r * g.ldr + c];
                    if (g.qd) {
                        float xi = rintf(v / qd) + 128.f;
                        v = fminf(fmaxf(xi, 0.f), 255.f) - 128.f;
                    }
                    const long long o = (long long)(bb * g.sCb + hb * g.sCh) + (long long)r * g.ldc + c;
                    if (CHALF) ((__half*)g.C)[o] = __float2half_rn(v);
                    else       ((float*)g.C)[o] = v;
                }
            }
        }
    }
}

template<int BN, int WM, bool SPLIT, bool CHALF>
static void run_h(HArgs a, int nb)
{
    constexpr int STG = (SPLIT ? 2 : 1) * (128 * 40 + BN * 40);
    const int smem = 2 * STG * 2;
    cudaFuncSetAttribute(hgemm<BN, WM, SPLIT, CHALF>,
                         cudaFuncAttributeMaxDynamicSharedMemorySize, smem);
    dim3 grid((a.N + BN - 1) / BN, (a.M + 127) / 128, nb);
    hgemm<BN, WM, SPLIT, CHALF><<<grid, 256, smem>>>(a);
}
static HArgs ha(const __half* A, const __half* Al, const __half* B, const __half* Bl,
                void* C, int M, int N, int Nstore, int K, int lda, int ldb, int ldc)
{
    HArgs g;
    g.A = A; g.Al = Al; g.B = B; g.Bl = Bl; g.C = C;
    g.M = M; g.N = N; g.Nstore = Nstore; g.K = K;
    g.lda = lda; g.ldb = ldb; g.ldc = ldc; g.ldr = 0;
    g.sAb = g.sAh = g.sBb = g.sBh = g.sCb = g.sCh = 0;
    g.bias = 0; g.res = 0; g.s1 = 0; g.s2 = 0; g.qd = 0; g.s0 = 1.f;
    return g;
}

// ---------------- transposes / splits ----------------
// fp32 [K,N] -> half [N,K] (1x, rn)
__global__ void wtrans(const float* __restrict__ in, __half* __restrict__ out, int K, int N)
{
    __shared__ float t[32][33];
    const int n0 = blockIdx.x * 32, k0 = blockIdx.y * 32;
    const int tx = threadIdx.x, ty = threadIdx.y;
#pragma unroll
    for (int i = 0; i < 32; i += 8)
        t[ty + i][tx] = in[(long long)(k0 + ty + i) * N + n0 + tx];
    __syncthreads();
#pragma unroll
    for (int i = 0; i < 32; i += 8)
        out[(long long)(n0 + ty + i) * K + k0 + tx] = __float2half_rn(t[tx][ty + i]);
}
__global__ void wtrans_split(const float* __restrict__ in, __half* __restrict__ oH,
                             __half* __restrict__ oL, int K, int N)
{
    __shared__ float t[32][33];
    const int n0 = blockIdx.x * 32, k0 = blockIdx.y * 32;
    const int tx = threadIdx.x, ty = threadIdx.y;
#pragma unroll
    for (int i = 0; i < 32; i += 8)
        t[ty + i][tx] = in[(long long)(k0 + ty + i) * N + n0 + tx];
    __syncthreads();
#pragma unroll
    for (int i = 0; i < 32; i += 8) {
        const float v = t[tx][ty + i];
        const __half h = __float2half_rn(v);
        const long long o = (long long)(n0 + ty + i) * K + k0 + tx;
        oH[o] = h; oL[o] = __float2half_rn(v - __half2float(h));
    }
}
__global__ void vtrans(const __half* __restrict__ v, __half* __restrict__ vt, int T, int Tpad)
{
    __shared__ float t[32][33];
    const int bz = blockIdx.z, b = bz >> 4, h = bz & 15;
    const int t0 = blockIdx.x * 32, d0 = blockIdx.y * 32;
    const int tx = threadIdx.x, ty = threadIdx.y;
#pragma unroll
    for (int i = 0; i < 32; i += 8) {
        const int tt = t0 + ty + i;
        t[ty + i][tx] = (tt < T) ? __half2float(v[((long long)b * T + tt) * 1024 + h * 64 + d0 + tx]) : 0.f;
    }
    __syncthreads();
#pragma unroll
    for (int i = 0; i < 32; i += 8) {
        const int tt = t0 + tx;
        if (tt < Tpad)
            vt[(((long long)b * 16 + h) * 64 + d0 + ty + i) * Tpad + tt] = __float2half_rn(t[tx][ty + i]);
    }
}
__global__ void esplit(const float* __restrict__ in, __half* __restrict__ oH,
                       __half* __restrict__ oL, int n)
{
    const int i = blockIdx.x * 256 + threadIdx.x;
    if (i < n) {
        const float v = in[i];
        const __half h = __float2half_rn(v);
        oH[i] = h; oL[i] = __float2half_rn(v - __half2float(h));
    }
}

// ---------------- layernorm -> half hi (+ optional half lo) ----------------
__global__ void ln_kernel(const float* __restrict__ x, const float* __restrict__ gm,
                          const float* __restrict__ bt,
                          __half* __restrict__ outH, __half* __restrict__ outL)
{
    __shared__ float red[4];
    const long long row = blockIdx.x;
    const float* xr = x + row * 1024;
    const int t = threadIdx.x;
    float v[8];
    *reinterpret_cast<float4*>(&v[0]) = *reinterpret_cast<const float4*>(xr + t * 8);
    *reinterpret_cast<float4*>(&v[4]) = *reinterpret_cast<const float4*>(xr + t * 8 + 4);
    float s = 0.f;
#pragma unroll
    for (int i = 0; i < 8; ++i) s += v[i];
#pragma unroll
    for (int o = 16; o; o >>= 1) s += __shfl_xor_sync(0xffffffffu, s, o);
    if ((t & 31) == 0) red[t >> 5] = s;
    __syncthreads();
    const float mu = (red[0] + red[1] + red[2] + red[3]) * (1.f / 1024.f);
    __syncthreads();
    float ss = 0.f;
#pragma unroll
    for (int i = 0; i < 8; ++i) { float d = v[i] - mu; ss += d * d; }
#pragma unroll
    for (int o = 16; o; o >>= 1) ss += __shfl_xor_sync(0xffffffffu, ss, o);
    if ((t & 31) == 0) red[t >> 5] = ss;
    __syncthreads();
    const float rs = rsqrtf((red[0] + red[1] + red[2] + red[3]) * (1.f / 1024.f) + 1e-5f);
#pragma unroll
    for (int i = 0; i < 8; ++i) {
        const int c = t * 8 + i;
        const float y = (v[i] - mu) * rs * gm[c] + bt[c];
        const __half h = __float2half_rn(y);
        outH[row * 1024 + c] = h;
        if (outL) outL[row * 1024 + c] = __float2half_rn(y - __half2float(h));
    }
}

// ---------------- softmax -> half codes in-place, pad [L,ldp) ----------------
__global__ void softmax_quant(float* __restrict__ S, int L, int ld, int ldp,
                              const float* __restrict__ dptr)
{
    __shared__ float buf[2048];
    __shared__ float red[4];
    const long long row = blockIdx.x;
    float* r = S + row * (long long)ld;
    const int t = threadIdx.x;
    float mx = -3.0e38f;
    for (int j = t; j < L; j += 128) { float v = r[j]; buf[j] = v; mx = fmaxf(mx, v); }
#pragma unroll
    for (int o = 16; o; o >>= 1) mx = fmaxf(mx, __shfl_xor_sync(0xffffffffu, mx, o));
    if ((t & 31) == 0) red[t >> 5] = mx;
    __syncthreads();
    mx = fmaxf(fmaxf(red[0], red[1]), fmaxf(red[2], red[3]));
    __syncthreads();
    float s = 0.f;
    for (int j = t; j < L; j += 128) s += expf(buf[j] - mx);
#pragma unroll
    for (int o = 16; o; o >>= 1) s += __shfl_xor_sync(0xffffffffu, s, o);
    if ((t & 31) == 0) red[t >> 5] = s;
    __syncthreads();
    s = red[0] + red[1] + red[2] + red[3];
    const float delta = *dptr;
    __half* hp = reinterpret_cast<__half*>(r);
    __syncthreads();
    for (int j = t; j < L; j += 128) {
        const float p = expf(buf[j] - mx) / s;
        hp[j] = __float2half_rn(fminf(fmaxf(rintf(p / delta), 0.f), 255.f));
    }
    for (int j = L + t; j < ldp; j += 128) hp[j] = __float2half_rn(0.f);
}

// ---------------- GEGLU: fp32 in, half out ----------------
__global__ void geglu_kernel(const float* __restrict__ hg, __half* __restrict__ gg)
{
    const long long i4 = (long long)blockIdx.x * blockDim.x + threadIdx.x;
    const long long r = i4 >> 10, c = (i4 & 1023) << 2;
    const float4 a = *reinterpret_cast<const float4*>(hg + r * 8192 + c);
    const float4 g = *reinterpret_cast<const float4*>(hg + r * 8192 + 4096 + c);
    const float k = 0.70710678118654752440f;
    __half2 o01 = __floats2half2_rn(a.x * (0.5f * g.x * (1.f + erff(g.x * k))),
                                    a.y * (0.5f * g.y * (1.f + erff(g.y * k))));
    __half2 o23 = __floats2half2_rn(a.z * (0.5f * g.z * (1.f + erff(g.z * k))),
                                    a.w * (0.5f * g.w * (1.f + erff(g.w * k))));
    __half2* op = reinterpret_cast<__half2*>(gg + r * 4096 + c);
    op[0] = o01; op[1] = o23;
}

// ---------------- launcher ----------------
extern "C" void kernel_launch(void* const* d_in, const int* in_sizes, int n_in,
                              void* d_out, int out_size)
{
    (void)in_sizes; (void)n_in; (void)out_size;
    const float* x   = (const float*)d_in[0];
    const float* ctx = (const float*)d_in[1];
    const float *ln1g = (const float*)d_in[2], *ln1b = (const float*)d_in[3];
    const float *ln2g = (const float*)d_in[4], *ln2b = (const float*)d_in[5];
    const float *ln3g = (const float*)d_in[6], *ln3b = (const float*)d_in[7];
    const float *wq1 = (const float*)d_in[8],  *wk1 = (const float*)d_in[9];
    const float *wv1 = (const float*)d_in[10], *wo1 = (const float*)d_in[11];
    const float *bo1 = (const float*)d_in[12];
    const float *wq2 = (const float*)d_in[13], *wk2 = (const float*)d_in[14];
    const float *wv2 = (const float*)d_in[15], *wo2 = (const float*)d_in[16];
    const float *bo2 = (const float*)d_in[17];
    const float *w1 = (const float*)d_in[18], *b1 = (const float*)d_in[19];
    const float *w2 = (const float*)d_in[20], *b2 = (const float*)d_in[21];
    const float *dq1 = (const float*)d_in[22], *dk1 = (const float*)d_in[23];
    const float *dv1 = (const float*)d_in[24], *dw1 = (const float*)d_in[25];
    const float *dq2 = (const float*)d_in[26], *dk2 = (const float*)d_in[27];
    const float *dv2 = (const float*)d_in[28], *dw2 = (const float*)d_in[29];
    float* out = (float*)d_out;

    float *px, *ph, *phl, *pq, *pk, *pv, *po, *pvt, *pS, *phg, *pgg, *pw, *pcs;
    cudaGetSymbolAddress((void**)&px,  g_x);
    cudaGetSymbolAddress((void**)&ph,  g_h);
    cudaGetSymbolAddress((void**)&phl, g_hl);
    cudaGetSymbolAddress((void**)&pq,  g_q);
    cudaGetSymbolAddress((void**)&pk,  g_k);
    cudaGetSymbolAddress((void**)&pv,  g_v);
    cudaGetSymbolAddress((void**)&po,  g_o);
    cudaGetSymbolAddress((void**)&pvt, g_vt);
    cudaGetSymbolAddress((void**)&pS,  g_S);
    cudaGetSymbolAddress((void**)&phg, g_hg);
    cudaGetSymbolAddress((void**)&pgg, g_gg);
    cudaGetSymbolAddress((void**)&pw,  g_w);
    cudaGetSymbolAddress((void**)&pcs, g_cs);

    __half *hh = (__half*)ph, *hhl = (__half*)phl;
    __half *hq = (__half*)pq, *hk = (__half*)pk, *hv = (__half*)pv, *hvt = (__half*)pvt;
    __half *hS = (__half*)pS, *hpo = (__half*)po, *hgg = (__half*)pgg;

    const long long M1 = 1048576;
    __half *q1h = (__half*)pw,          *q1l = (__half*)(pw + M1);
    __half *k1h = (__half*)(pw + 2*M1), *k1l = (__half*)(pw + 3*M1);
    __half *v1h = (__half*)(pw + 4*M1), *v1l = (__half*)(pw + 5*M1);
    __half *q2h = (__half*)(pw + 6*M1), *q2l = (__half*)(pw + 7*M1);
    __half *k2h = (__half*)(pw + 8*M1), *k2l = (__half*)(pw + 9*M1);
    __half *v2h = (__half*)(pw + 10*M1),*v2l = (__half*)(pw + 11*M1);
    __half *o1t = (__half*)(pw + 12*M1), *o2t = (__half*)(pw + 13*M1);
    __half *w1t = (__half*)(pw + 14*M1), *w2t = (__half*)(pw + 18*M1);
    __half *chi = (__half*)pcs, *clo = (__half*)(pcs + 80000);

    dim3 tb(32, 8);
    wtrans_split<<<dim3(32,32), tb>>>(wq1, q1h, q1l, 1024, 1024);
    wtrans_split<<<dim3(32,32), tb>>>(wk1, k1h, k1l, 1024, 1024);
    wtrans_split<<<dim3(32,32), tb>>>(wv1, v1h, v1l, 1024, 1024);
    wtrans_split<<<dim3(32,32), tb>>>(wq2, q2h, q2l, 1024, 1024);
    wtrans_split<<<dim3(32,32), tb>>>(wk2, k2h, k2l, 1024, 1024);
    wtrans_split<<<dim3(32,32), tb>>>(wv2, v2h, v2l, 1024, 1024);
    wtrans<<<dim3(32,32),  tb>>>(wo1, o1t, 1024, 1024);
    wtrans<<<dim3(32,32),  tb>>>(wo2, o2t, 1024, 1024);
    wtrans<<<dim3(256,32), tb>>>(w1,  w1t, 1024, 8192);
    wtrans<<<dim3(32,128), tb>>>(w2,  w2t, 4096, 1024);
    esplit<<<616, 256>>>(ctx, chi, clo, 157696);

    const long long ND  = 2048LL * 1024;
    const long long SB1 = 16LL * 2048 * 2048, SH1 = 2048LL * 2048;
    const long long SB2 = 16LL * 2048 * 96,   SH2 = 2048LL * 96;
    const long long CKV = 77LL * 1024;
    const long long VT1b = 16LL * 64 * 2048, VT1h = 64LL * 2048;
    const long long VT2b = 16LL * 64 * 96,   VT2h = 64LL * 96;

    // ===== self attention =====
    ln_kernel<<<4096, 128>>>(x, ln1g, ln1b, hh, hhl);
    { HArgs g = ha(hh, hhl, q1h, q1l, hq, 4096,1024,1024,1024, 1024,1024,1024); g.qd = dq1; run_h<128,2,true,true>(g, 1); }
    { HArgs g = ha(hh, hhl, k1h, k1l, hk, 4096,1024,1024,1024, 1024,1024,1024); g.qd = dk1; run_h<128,2,true,true>(g, 1); }
    { HArgs g = ha(hh, hhl, v1h, v1l, hv, 4096,1024,1024,1024, 1024,1024,1024); g.qd = dv1; run_h<128,2,true,true>(g, 1); }
    vtrans<<<dim3(64,2,32), tb>>>(hv, hvt, 2048, 2048);
    { HArgs g = ha(hq, 0, hk, 0, pS, 2048,2048,2048,64, 1024,1024,2048);
      g.sAb = ND; g.sAh = 64; g.sBb = ND; g.sBh = 64; g.sCb = SB1; g.sCh = SH1;
      g.s0 = 0.125f; g.s1 = dq1; g.s2 = dk1; run_h<128,2,false,false>(g, 32); }
    softmax_quant<<<65536, 128>>>(pS, 2048, 2048, 2048, dw1);
    { HArgs g = ha(hS, 0, hvt, 0, hpo, 2048,64,64,2048, 4096,2048,1024);
      g.sAb = 2*SB1; g.sAh = 2*SH1; g.sBb = VT1b; g.sBh = VT1h; g.sCb = ND; g.sCh = 64;
      g.s1 = dw1; g.s2 = dv1; run_h<64,4,false,true>(g, 32); }
    { HArgs g = ha(hpo, 0, o1t, 0, px, 4096,1024,1024,1024, 1024,1024,1024);
      g.bias = bo1; g.res = x; g.ldr = 1024; run_h<128,2,false,false>(g, 1); }

    // ===== cross attention =====
    ln_kernel<<<4096, 128>>>(px, ln2g, ln2b, hh, hhl);
    { HArgs g = ha(hh, hhl, q2h, q2l, hq, 4096,1024,1024,1024, 1024,1024,1024); g.qd = dq2; run_h<128,2,true,true>(g, 1); }
    { HArgs g = ha(chi, clo, k2h, k2l, hk, 154,1024,1024,1024, 1024,1024,1024); g.qd = dk2; run_h<128,2,true,true>(g, 1); }
    { HArgs g = ha(chi, clo, v2h, v2l, hv, 154,1024,1024,1024, 1024,1024,1024); g.qd = dv2; run_h<128,2,true,true>(g, 1); }
    vtrans<<<dim3(3,2,32), tb>>>(hv, hvt, 77, 96);
    { HArgs g = ha(hq, 0, hk, 0, pS, 2048,77,77,64, 1024,1024,96);
      g.sAb = ND; g.sAh = 64; g.sBb = CKV; g.sBh = 64; g.sCb = SB2; g.sCh = SH2;
      g.s0 = 0.125f; g.s1 = dq2; g.s2 = dk2; run_h<128,2,false,false>(g, 32); }
    softmax_quant<<<65536, 128>>>(pS, 77, 96, 96, dw2);
    { HArgs g = ha(hS, 0, hvt, 0, hpo, 2048,64,64,96, 192,96,1024);
      g.sAb = 2*SB2; g.sAh = 2*SH2; g.sBb = VT2b; g.sBh = VT2h; g.sCb = ND; g.sCh = 64;
      g.s1 = dw2; g.s2 = dv2; run_h<64,4,false,true>(g, 32); }
    { HArgs g = ha(hpo, 0, o2t, 0, px, 4096,1024,1024,1024, 1024,1024,1024);
      g.bias = bo2; g.res = px; g.ldr = 1024; run_h<128,2,false,false>(g, 1); }

    // ===== GEGLU feed-forward =====
    ln_kernel<<<4096, 128>>>(px, ln3g, ln3b, hh, 0);
    { HArgs g = ha(hh, 0, w1t, 0, phg, 4096,8192,8192,1024, 1024,1024,8192);
      g.bias = b1; run_h<128,2,false,false>(g, 1); }
    geglu_kernel<<<16384, 256>>>(phg, hgg);
    { HArgs g = ha(hgg, 0, w2t, 0, out, 4096,1024,1024,4096, 4096,4096,1024);
      g.bias = b2; g.res = px; g.ldr = 1024; run_h<128,2,false,false>(g, 1); }
}

// round 9
// speedup vs baseline: 3.3611x; 1.1181x over previous
#include <cuda_runtime.h>
#include <cuda_fp16.h>
#include <cstdint>
#include <math.h>

// ---------------- scratch ----------------
__device__ float g_x [4194304];
__device__ float g_h [4194304];   // ln out: half hi
__device__ float g_hl[4194304];   // ln out: half lo
__device__ float g_q [4194304];   // half codes
__device__ float g_k [4194304];
__device__ float g_v [4194304];
__device__ float g_o [4194304];   // half attn out
__device__ float g_vt[4194304];   // half v^T codes
__device__ float g_hg[33554432];  // fp32 FFN intermediate
__device__ float g_gg[16777216];  // half GEGLU out (reinterpret)
__device__ float g_w [27262976];
__device__ float g_cs[327680];

// ---------------- helpers ----------------
static __device__ __forceinline__ uint32_t smem_u32(const void* p) {
    uint32_t a;
    asm("{ .reg .u64 t; cvta.to.shared.u64 t, %1; cvt.u32.u64 %0, t; }" : "=r"(a) : "l"(p));
    return a;
}
#define MMAH(d, a, b) \
    asm volatile("mma.sync.aligned.m16n8k16.row.col.f32.f16.f16.f32 " \
        "{%0,%1,%2,%3},{%4,%5,%6,%7},{%8,%9},{%0,%1,%2,%3};" \
        : "+f"((d)[0]), "+f"((d)[1]), "+f"((d)[2]), "+f"((d)[3]) \
        : "r"((a)[0]), "r"((a)[1]), "r"((a)[2]), "r"((a)[3]), "r"((b)[0]), "r"((b)[1]))
#define CPA(dst, src, sz) \
    asm volatile("cp.async.cg.shared.global [%0], [%1], 16, %2;" :: "r"(dst), "l"(src), "r"(sz))
static __device__ __forceinline__ uint32_t ld32h(const __half* p) {
    return *reinterpret_cast<const uint32_t*>(p);
}
static __device__ __forceinline__ uint32_t packh2(float a, float b) {
    __half2 h = __floats2half2_rn(a, b);
    return *reinterpret_cast<uint32_t*>(&h);
}

// ================= fused attention (two-pass, max-free softmax) =================
// per CTA: 128 q rows x all keys for one (b,h).  q,k: half codes [b][t][h*64+d];
// vt: half codes [bh][d][Tkpad]; o: half out [b][t][h*64+d].
__global__ void __launch_bounds__(256)
fattn(const __half* __restrict__ q, const __half* __restrict__ k,
      const __half* __restrict__ vt, __half* __restrict__ o,
      int Tq, int Tk, int Tkpad,
      const float* __restrict__ dqp, const float* __restrict__ dkp,
      const float* __restrict__ dwp, const float* __restrict__ dvp)
{
    constexpr int QS = 128 * 72, KS = 128 * 72, VS = 64 * 136;
    extern __shared__ __half sh[];
    __half* Qs  = sh;
    __half* Ks0 = sh + QS;
    __half* Vs0 = sh + QS + 2 * KS;
    const uint32_t smb = smem_u32(sh);
    const uint32_t kb_ = smb + QS * 2, vb_ = smb + (QS + 2 * KS) * 2;

    const int tid = threadIdx.x, wid = tid >> 5, lane = tid & 31;
    const int grp = lane >> 2, tg = lane & 3;
    const int bh = blockIdx.z, b = bh >> 4, h = bh & 15;
    const int m0 = blockIdx.x * 128;
    const int nkt = (Tk + 127) >> 7;

    const float alpha = 0.125f * __ldg(dqp) * __ldg(dkp);
    const float dw = __ldg(dwp);
    const float beta = dw * __ldg(dvp);

    {   // Q tile 128x64h (rows always valid: Tq multiple of 128)
        const __half* qb = q + ((long long)b * Tq + m0) * 1024 + h * 64;
#pragma unroll
        for (int i = 0; i < 4; ++i) {
            const int idx = tid + (i << 8);
            const int r = idx >> 3, c = idx & 7;
            CPA(smb + (uint32_t)(r * 72 + (c << 3)) * 2, qb + (long long)r * 1024 + (c << 3), 16);
        }
    }

    auto loadK = [&](int t, int st) {
        const __half* kbase = k + ((long long)b * Tk) * 1024 + h * 64;
#pragma unroll
        for (int i = 0; i < 4; ++i) {
            const int idx = tid + (i << 8);
            const int r = idx >> 3, c = idx & 7;
            const int key = t * 128 + r;
            const int ok = key < Tk;
            const __half* s = ok ? (kbase + (long long)key * 1024 + (c << 3)) : kbase;
            CPA(kb_ + (uint32_t)(st * KS + r * 72 + (c << 3)) * 2, s, ok ? 16 : 0);
        }
    };
    auto loadV = [&](int t, int st) {
        const __half* vbase = vt + ((long long)bh * 64) * Tkpad;
#pragma unroll
        for (int i = 0; i < 4; ++i) {
            const int idx = tid + (i << 8);
            const int r = idx >> 4, c = idx & 15;
            const int key = t * 128 + (c << 3);
            const int ok = (key + 8) <= Tkpad;
            const __half* s = ok ? (vbase + (long long)r * Tkpad + key) : vbase;
            CPA(vb_ + (uint32_t)(st * VS + r * 136 + (c << 3)) * 2, s, ok ? 16 : 0);
        }
    };

    float sacc[16][4];
    auto computeS = [&](int st) {
#pragma unroll
        for (int nf = 0; nf < 16; ++nf)
#pragma unroll
            for (int e = 0; e < 4; ++e) sacc[nf][e] = 0.f;
        const __half* Kp = Ks0 + st * KS;
#pragma unroll
        for (int kc = 0; kc < 4; ++kc) {
            const int kb2 = kc << 4;
            const int oa = (wid * 16 + grp) * 72 + kb2 + (tg << 1);
            uint32_t ah[4] = { ld32h(Qs + oa), ld32h(Qs + oa + 576),
                               ld32h(Qs + oa + 8), ld32h(Qs + oa + 584) };
#pragma unroll
            for (int nf = 0; nf < 16; ++nf) {
                const int ob = (nf * 8 + grp) * 72 + kb2 + (tg << 1);
                uint32_t bf[2] = { ld32h(Kp + ob), ld32h(Kp + ob + 8) };
                MMAH(sacc[nf], ah, bf);
            }
        }
    };

    // ---- pass 1: l = sum(exp(alpha*s)) per row (no max needed: |alpha*s| <= ~52) ----
    float psum0 = 0.f, psum1 = 0.f;
    loadK(0, 0);
    asm volatile("cp.async.commit_group;");
    for (int t = 0; t < nkt; ++t) {
        if (t + 1 < nkt) loadK(t + 1, (t + 1) & 1);
        asm volatile("cp.async.commit_group;");
        if (t + 1 < nkt) asm volatile("cp.async.wait_group 1;");
        else             asm volatile("cp.async.wait_group 0;");
        __syncthreads();
        computeS(t & 1);
        __syncthreads();
        const int cb = t * 128;
#pragma unroll
        for (int nf = 0; nf < 16; ++nf) {
            const int c0 = cb + nf * 8 + (tg << 1);
            if (c0 < Tk)     { psum0 += expf(sacc[nf][0] * alpha); psum1 += expf(sacc[nf][2] * alpha); }
            if (c0 + 1 < Tk) { psum0 += expf(sacc[nf][1] * alpha); psum1 += expf(sacc[nf][3] * alpha); }
        }
    }
    psum0 += __shfl_xor_sync(0xffffffffu, psum0, 1);
    psum0 += __shfl_xor_sync(0xffffffffu, psum0, 2);
    psum1 += __shfl_xor_sync(0xffffffffu, psum1, 1);
    psum1 += __shfl_xor_sync(0xffffffffu, psum1, 2);

    // ---- pass 2: recompute S, quantize to codes, P@V from registers ----
    float oacc[8][4];
#pragma unroll
    for (int i = 0; i < 8; ++i)
#pragma unroll
        for (int e = 0; e < 4; ++e) oacc[i][e] = 0.f;

    loadK(0, 0); loadV(0, 0);
    asm volatile("cp.async.commit_group;");
    for (int t = 0; t < nkt; ++t) {
        if (t + 1 < nkt) { loadK(t + 1, (t + 1) & 1); loadV(t + 1, (t + 1) & 1); }
        asm volatile("cp.async.commit_group;");
        if (t + 1 < nkt) asm volatile("cp.async.wait_group 1;");
        else             asm volatile("cp.async.wait_group 0;");
        __syncthreads();
        computeS(t & 1);
        const __half* Vp = Vs0 + (t & 1) * VS;
        const int cb = t * 128;
#pragma unroll
        for (int kb = 0; kb < 8; ++kb) {
            uint32_t ah[4];
#pragma unroll
            for (int hf = 0; hf < 2; ++hf) {
                const int nf = 2 * kb + hf;
                const int c0 = cb + nf * 8 + (tg << 1);
                const int ok0 = c0 < Tk, ok1 = (c0 + 1) < Tk;
                float p0 = ok0 ? expf(sacc[nf][0] * alpha) / psum0 : 0.f;
                float p1 = ok1 ? expf(sacc[nf][1] * alpha) / psum0 : 0.f;
                float p2 = ok0 ? expf(sacc[nf][2] * alpha) / psum1 : 0.f;
                float p3 = ok1 ? expf(sacc[nf][3] * alpha) / psum1 : 0.f;
                const float q0 = fminf(fmaxf(rintf(p0 / dw), 0.f), 255.f);
                const float q1 = fminf(fmaxf(rintf(p1 / dw), 0.f), 255.f);
                const float q2 = fminf(fmaxf(rintf(p2 / dw), 0.f), 255.f);
                const float q3 = fminf(fmaxf(rintf(p3 / dw), 0.f), 255.f);
                ah[hf * 2]     = packh2(q0, q1);   // rows grp
                ah[hf * 2 + 1] = packh2(q2, q3);   // rows grp+8
            }
#pragma unroll
            for (int nfo = 0; nfo < 8; ++nfo) {
                const int ob = (nfo * 8 + grp) * 136 + (kb << 4) + (tg << 1);
                uint32_t bf[2] = { ld32h(Vp + ob), ld32h(Vp + ob + 8) };
                MMAH(oacc[nfo], ah, bf);
            }
        }
        __syncthreads();
    }

    // epilogue: o = beta * oacc
    const int row0 = m0 + wid * 16 + grp;
    __half* ob = o + ((long long)b * Tq) * 1024 + h * 64;
#pragma unroll
    for (int nfo = 0; nfo < 8; ++nfo) {
        const int c = nfo * 8 + (tg << 1);
        *reinterpret_cast<__half2*>(ob + (long long)row0 * 1024 + c) =
            __floats2half2_rn(oacc[nfo][0] * beta, oacc[nfo][1] * beta);
        *reinterpret_cast<__half2*>(ob + (long long)(row0 + 8) * 1024 + c) =
            __floats2half2_rn(oacc[nfo][2] * beta, oacc[nfo][3] * beta);
    }
}

// ================= fp16 mma GEMM =================
// C = s0*s1*s2*(A[M,K] @ B[N,K]^T) [+bias] [+res] [-> quant codes], batched (b,h)
struct HArgs {
    const __half *A, *Al, *B, *Bl; void* C;
    int M, N, Nstore, K, lda, ldb, ldc, ldr;
    long long sAb, sAh, sBb, sBh, sCb, sCh;
    const float *bias, *res, *s1, *s2, *qd;
    float s0;
};

template<int BN, int WM, bool SPLIT, bool CHALF>
__global__ void __launch_bounds__(256)
hgemm(const __grid_constant__ HArgs g)
{
    constexpr int WN = 8 / WM, WTM = 128 / WM, WTN = BN / WN;
    constexpr int MF = WTM / 16, NF = WTN / 8;
    constexpr int AS = 128 * 40, BS = BN * 40;
    constexpr int NT = SPLIT ? 2 : 1, STG = NT * (AS + BS);

    extern __shared__ __half smh[];
    const uint32_t smb = smem_u32(smh);
    const int tid = threadIdx.x, wid = tid >> 5, lane = tid & 31;
    const int grp = lane >> 2, tg = lane & 3;
    const int wm = wid / WN, wn = wid % WN;

    const int z = blockIdx.z, bb = z >> 4, hb = z & 15;
    const __half* Ab = g.A + bb * g.sAb + hb * g.sAh;
    const __half* Al = SPLIT ? (g.Al + bb * g.sAb + hb * g.sAh) : (const __half*)0;
    const __half* Bb = g.B + bb * g.sBb + hb * g.sBh;
    const __half* Bl = SPLIT ? (g.Bl + bb * g.sBb + hb * g.sBh) : (const __half*)0;

    const int bm = blockIdx.y * 128, bn = blockIdx.x * BN;
    const int nch = g.K >> 5;

    float acc[MF][NF][4];
#pragma unroll
    for (int i = 0; i < MF; ++i)
#pragma unroll
        for (int j = 0; j < NF; ++j)
#pragma unroll
            for (int c = 0; c < 4; ++c) acc[i][j][c] = 0.f;

    auto issue = [&](int ch, int st) {
        const int k0 = ch << 5;
        const uint32_t sa = smb + (uint32_t)st * STG * 2;
#pragma unroll
        for (int i = 0; i < 2; ++i) {
            const int idx = tid + (i << 8);
            const int r = idx >> 2, c = idx & 3;
            const int gr = bm + r, ok = (gr < g.M);
            const __half* s = ok ? (Ab + (long long)gr * g.lda + k0 + (c << 3)) : Ab;
            const uint32_t d = sa + (uint32_t)(r * 40 + (c << 3)) * 2;
            CPA(d, s, ok ? 16 : 0);
            if (SPLIT) {
                const __half* s2 = ok ? (Al + (long long)gr * g.lda + k0 + (c << 3)) : Al;
                CPA(d + AS * 2, s2, ok ? 16 : 0);
            }
        }
#pragma unroll
        for (int i = 0; i < BN / 64; ++i) {
            const int idx = tid + (i << 8);
            const int r = idx >> 2, c = idx & 3;
            const int gn = bn + r, ok = (gn < g.N);
            const __half* s = ok ? (Bb + (long long)gn * g.ldb + k0 + (c << 3)) : Bb;
            const uint32_t d = sa + (uint32_t)(NT * AS + r * 40 + (c << 3)) * 2;
            CPA(d, s, ok ? 16 : 0);
            if (SPLIT) {
                const __half* s2 = ok ? (Bl + (long long)gn * g.ldb + k0 + (c << 3)) : Bl;
                CPA(d + BS * 2, s2, ok ? 16 : 0);
            }
        }
    };

    auto compute = [&](int st) {
        const __half* sa  = smh + st * STG;
        const __half* sal = sa + AS;
        const __half* sbh = sa + NT * AS;
        const __half* sbl = sbh + BS;
#pragma unroll
        for (int kk = 0; kk < 2; ++kk) {
            const int kb = kk << 4;
            uint32_t bh[NF][2], bl[NF][2];
#pragma unroll
            for (int nf = 0; nf < NF; ++nf) {
                const int o = (wn * WTN + (nf << 3) + grp) * 40 + kb + (tg << 1);
                bh[nf][0] = ld32h(sbh + o); bh[nf][1] = ld32h(sbh + o + 8);
                if (SPLIT) { bl[nf][0] = ld32h(sbl + o); bl[nf][1] = ld32h(sbl + o + 8); }
            }
#pragma unroll
            for (int mf = 0; mf < MF; ++mf) {
                const int o = (wm * WTM + (mf << 4) + grp) * 40 + kb + (tg << 1);
                uint32_t ah[4] = { ld32h(sa + o), ld32h(sa + o + 320),
                                   ld32h(sa + o + 8), ld32h(sa + o + 328) };
#pragma unroll
                for (int nf = 0; nf < NF; ++nf) MMAH(acc[mf][nf], ah, bh[nf]);
                if (SPLIT) {
                    uint32_t al[4] = { ld32h(sal + o), ld32h(sal + o + 320),
                                       ld32h(sal + o + 8), ld32h(sal + o + 328) };
#pragma unroll
                    for (int nf = 0; nf < NF; ++nf) {
                        MMAH(acc[mf][nf], ah, bl[nf]);
                        MMAH(acc[mf][nf], al, bh[nf]);
                    }
                }
            }
        }
    };

    issue(0, 0);
    asm volatile("cp.async.commit_group;");
    for (int ch = 0; ch < nch; ++ch) {
        if (ch + 1 < nch) issue(ch + 1, (ch + 1) & 1);
        asm volatile("cp.async.commit_group;");
        asm volatile("cp.async.wait_group 1;");
        __syncthreads();
        compute(ch & 1);
        __syncthreads();
    }

    float alpha = g.s0;
    if (g.s1) alpha *= __ldg(g.s1);
    if (g.s2) alpha *= __ldg(g.s2);
    const float qd = g.qd ? __ldg(g.qd) : 1.f;
#pragma unroll
    for (int mf = 0; mf < MF; ++mf) {
        const int r0 = bm + wm * WTM + (mf << 4) + grp;
#pragma unroll
        for (int nf = 0; nf < NF; ++nf) {
            const int c0 = bn + wn * WTN + (nf << 3) + (tg << 1);
#pragma unroll
            for (int e = 0; e < 4; ++e) {
                const int r = r0 + ((e >> 1) << 3);
                const int c = c0 + (e & 1);
                if (r < g.M && c < g.Nstore) {
                    float v = acc[mf][nf][e] * alpha;
                    if (g.bias) v += __ldg(g.bias + c);
                    if (g.res)  v += g.res[(long long)r * g.ldr + c];
                    if (g.qd) {
                        float xi = rintf(v / qd) + 128.f;
                        v = fminf(fmaxf(xi, 0.f), 255.f) - 128.f;
                    }
                    const long long o = (long long)(bb * g.sCb + hb * g.sCh) + (long long)r * g.ldc + c;
                    if (CHALF) ((__half*)g.C)[o] = __float2half_rn(v);
                    else       ((float*)g.C)[o] = v;
                }
            }
        }
    }
}

template<int BN, int WM, bool SPLIT, bool CHALF>
static void run_h(HArgs a, int nb)
{
    constexpr int STG = (SPLIT ? 2 : 1) * (128 * 40 + BN * 40);
    const int smem = 2 * STG * 2;
    cudaFuncSetAttribute(hgemm<BN, WM, SPLIT, CHALF>,
                         cudaFuncAttributeMaxDynamicSharedMemorySize, smem);
    dim3 grid((a.N + BN - 1) / BN, (a.M + 127) / 128, nb);
    hgemm<BN, WM, SPLIT, CHALF><<<grid, 256, smem>>>(a);
}
static HArgs ha(const __half* A, const __half* Al, const __half* B, const __half* Bl,
                void* C, int M, int N, int Nstore, int K, int lda, int ldb, int ldc)
{
    HArgs g;
    g.A = A; g.Al = Al; g.B = B; g.Bl = Bl; g.C = C;
    g.M = M; g.N = N; g.Nstore = Nstore; g.K = K;
    g.lda = lda; g.ldb = ldb; g.ldc = ldc; g.ldr = 0;
    g.sAb = g.sAh = g.sBb = g.sBh = g.sCb = g.sCh = 0;
    g.bias = 0; g.res = 0; g.s1 = 0; g.s2 = 0; g.qd = 0; g.s0 = 1.f;
    return g;
}

// ---------------- transposes / splits ----------------
__global__ void wtrans(const float* __restrict__ in, __half* __restrict__ out, int K, int N)
{
    __shared__ float t[32][33];
    const int n0 = blockIdx.x * 32, k0 = blockIdx.y * 32;
    const int tx = threadIdx.x, ty = threadIdx.y;
#pragma unroll
    for (int i = 0; i < 32; i += 8)
        t[ty + i][tx] = in[(long long)(k0 + ty + i) * N + n0 + tx];
    __syncthreads();
#pragma unroll
    for (int i = 0; i < 32; i += 8)
        out[(long long)(n0 + ty + i) * K + k0 + tx] = __float2half_rn(t[tx][ty + i]);
}
__global__ void wtrans_split(const float* __restrict__ in, __half* __restrict__ oH,
                             __half* __restrict__ oL, int K, int N)
{
    __shared__ float t[32][33];
    const int n0 = blockIdx.x * 32, k0 = blockIdx.y * 32;
    const int tx = threadIdx.x, ty = threadIdx.y;
#pragma unroll
    for (int i = 0; i < 32; i += 8)
        t[ty + i][tx] = in[(long long)(k0 + ty + i) * N + n0 + tx];
    __syncthreads();
#pragma unroll
    for (int i = 0; i < 32; i += 8) {
        const float v = t[tx][ty + i];
        const __half h = __float2half_rn(v);
        const long long o = (long long)(n0 + ty + i) * K + k0 + tx;
        oH[o] = h; oL[o] = __float2half_rn(v - __half2float(h));
    }
}
__global__ void vtrans(const __half* __restrict__ v, __half* __restrict__ vt, int T, int Tpad)
{
    __shared__ float t[32][33];
    const int bz = blockIdx.z, b = bz >> 4, h = bz & 15;
    const int t0 = blockIdx.x * 32, d0 = blockIdx.y * 32;
    const int tx = threadIdx.x, ty = threadIdx.y;
#pragma unroll
    for (int i = 0; i < 32; i += 8) {
        const int tt = t0 + ty + i;
        t[ty + i][tx] = (tt < T) ? __half2float(v[((long long)b * T + tt) * 1024 + h * 64 + d0 + tx]) : 0.f;
    }
    __syncthreads();
#pragma unroll
    for (int i = 0; i < 32; i += 8) {
        const int tt = t0 + tx;
        if (tt < Tpad)
            vt[(((long long)b * 16 + h) * 64 + d0 + ty + i) * Tpad + tt] = __float2half_rn(t[tx][ty + i]);
    }
}
__global__ void esplit(const float* __restrict__ in, __half* __restrict__ oH,
                       __half* __restrict__ oL, int n)
{
    const int i = blockIdx.x * 256 + threadIdx.x;
    if (i < n) {
        const float v = in[i];
        const __half h = __float2half_rn(v);
        oH[i] = h; oL[i] = __float2half_rn(v - __half2float(h));
    }
}

// ---------------- layernorm -> half hi (+ optional half lo) ----------------
__global__ void ln_kernel(const float* __restrict__ x, const float* __restrict__ gm,
                          const float* __restrict__ bt,
                          __half* __restrict__ outH, __half* __restrict__ outL)
{
    __shared__ float red[4];
    const long long row = blockIdx.x;
    const float* xr = x + row * 1024;
    const int t = threadIdx.x;
    float v[8];
    *reinterpret_cast<float4*>(&v[0]) = *reinterpret_cast<const float4*>(xr + t * 8);
    *reinterpret_cast<float4*>(&v[4]) = *reinterpret_cast<const float4*>(xr + t * 8 + 4);
    float s = 0.f;
#pragma unroll
    for (int i = 0; i < 8; ++i) s += v[i];
#pragma unroll
    for (int o = 16; o; o >>= 1) s += __shfl_xor_sync(0xffffffffu, s, o);
    if ((t & 31) == 0) red[t >> 5] = s;
    __syncthreads();
    const float mu = (red[0] + red[1] + red[2] + red[3]) * (1.f / 1024.f);
    __syncthreads();
    float ss = 0.f;
#pragma unroll
    for (int i = 0; i < 8; ++i) { float d = v[i] - mu; ss += d * d; }
#pragma unroll
    for (int o = 16; o; o >>= 1) ss += __shfl_xor_sync(0xffffffffu, ss, o);
    if ((t & 31) == 0) red[t >> 5] = ss;
    __syncthreads();
    const float rs = rsqrtf((red[0] + red[1] + red[2] + red[3]) * (1.f / 1024.f) + 1e-5f);
#pragma unroll
    for (int i = 0; i < 8; ++i) {
        const int c = t * 8 + i;
        const float y = (v[i] - mu) * rs * gm[c] + bt[c];
        const __half h = __float2half_rn(y);
        outH[row * 1024 + c] = h;
        if (outL) outL[row * 1024 + c] = __float2half_rn(y - __half2float(h));
    }
}

// ---------------- GEGLU: fp32 in, half out ----------------
__global__ void geglu_kernel(const float* __restrict__ hg, __half* __restrict__ gg)
{
    const long long i4 = (long long)blockIdx.x * blockDim.x + threadIdx.x;
    const long long r = i4 >> 10, c = (i4 & 1023) << 2;
    const float4 a = *reinterpret_cast<const float4*>(hg + r * 8192 + c);
    const float4 g = *reinterpret_cast<const float4*>(hg + r * 8192 + 4096 + c);
    const float k = 0.70710678118654752440f;
    __half2 o01 = __floats2half2_rn(a.x * (0.5f * g.x * (1.f + erff(g.x * k))),
                                    a.y * (0.5f * g.y * (1.f + erff(g.y * k))));
    __half2 o23 = __floats2half2_rn(a.z * (0.5f * g.z * (1.f + erff(g.z * k))),
                                    a.w * (0.5f * g.w * (1.f + erff(g.w * k))));
    __half2* op = reinterpret_cast<__half2*>(gg + r * 4096 + c);
    op[0] = o01; op[1] = o23;
}

// ---------------- launcher ----------------
extern "C" void kernel_launch(void* const* d_in, const int* in_sizes, int n_in,
                              void* d_out, int out_size)
{
    (void)in_sizes; (void)n_in; (void)out_size;
    const float* x   = (const float*)d_in[0];
    const float* ctx = (const float*)d_in[1];
    const float *ln1g = (const float*)d_in[2], *ln1b = (const float*)d_in[3];
    const float *ln2g = (const float*)d_in[4], *ln2b = (const float*)d_in[5];
    const float *ln3g = (const float*)d_in[6], *ln3b = (const float*)d_in[7];
    const float *wq1 = (const float*)d_in[8],  *wk1 = (const float*)d_in[9];
    const float *wv1 = (const float*)d_in[10], *wo1 = (const float*)d_in[11];
    const float *bo1 = (const float*)d_in[12];
    const float *wq2 = (const float*)d_in[13], *wk2 = (const float*)d_in[14];
    const float *wv2 = (const float*)d_in[15], *wo2 = (const float*)d_in[16];
    const float *bo2 = (const float*)d_in[17];
    const float *w1 = (const float*)d_in[18], *b1 = (const float*)d_in[19];
    const float *w2 = (const float*)d_in[20], *b2 = (const float*)d_in[21];
    const float *dq1 = (const float*)d_in[22], *dk1 = (const float*)d_in[23];
    const float *dv1 = (const float*)d_in[24], *dw1 = (const float*)d_in[25];
    const float *dq2 = (const float*)d_in[26], *dk2 = (const float*)d_in[27];
    const float *dv2 = (const float*)d_in[28], *dw2 = (const float*)d_in[29];
    float* out = (float*)d_out;

    float *px, *ph, *phl, *pq, *pk, *pv, *po, *pvt, *phg, *pgg, *pw, *pcs;
    cudaGetSymbolAddress((void**)&px,  g_x);
    cudaGetSymbolAddress((void**)&ph,  g_h);
    cudaGetSymbolAddress((void**)&phl, g_hl);
    cudaGetSymbolAddress((void**)&pq,  g_q);
    cudaGetSymbolAddress((void**)&pk,  g_k);
    cudaGetSymbolAddress((void**)&pv,  g_v);
    cudaGetSymbolAddress((void**)&po,  g_o);
    cudaGetSymbolAddress((void**)&pvt, g_vt);
    cudaGetSymbolAddress((void**)&phg, g_hg);
    cudaGetSymbolAddress((void**)&pgg, g_gg);
    cudaGetSymbolAddress((void**)&pw,  g_w);
    cudaGetSymbolAddress((void**)&pcs, g_cs);

    __half *hh = (__half*)ph, *hhl = (__half*)phl;
    __half *hq = (__half*)pq, *hk = (__half*)pk, *hv = (__half*)pv, *hvt = (__half*)pvt;
    __half *hpo = (__half*)po, *hgg = (__half*)pgg;

    const long long M1 = 1048576;
    __half *q1h = (__half*)pw,          *q1l = (__half*)(pw + M1);
    __half *k1h = (__half*)(pw + 2*M1), *k1l = (__half*)(pw + 3*M1);
    __half *v1h = (__half*)(pw + 4*M1), *v1l = (__half*)(pw + 5*M1);
    __half *q2h = (__half*)(pw + 6*M1), *q2l = (__half*)(pw + 7*M1);
    __half *k2h = (__half*)(pw + 8*M1), *k2l = (__half*)(pw + 9*M1);
    __half *v2h = (__half*)(pw + 10*M1),*v2l = (__half*)(pw + 11*M1);
    __half *o1t = (__half*)(pw + 12*M1), *o2t = (__half*)(pw + 13*M1);
    __half *w1t = (__half*)(pw + 14*M1), *w2t = (__half*)(pw + 18*M1);
    __half *chi = (__half*)pcs, *clo = (__half*)(pcs + 80000);

    dim3 tb(32, 8);
    wtrans_split<<<dim3(32,32), tb>>>(wq1, q1h, q1l, 1024, 1024);
    wtrans_split<<<dim3(32,32), tb>>>(wk1, k1h, k1l, 1024, 1024);
    wtrans_split<<<dim3(32,32), tb>>>(wv1, v1h, v1l, 1024, 1024);
    wtrans_split<<<dim3(32,32), tb>>>(wq2, q2h, q2l, 1024, 1024);
    wtrans_split<<<dim3(32,32), tb>>>(wk2, k2h, k2l, 1024, 1024);
    wtrans_split<<<dim3(32,32), tb>>>(wv2, v2h, v2l, 1024, 1024);
    wtrans<<<dim3(32,32),  tb>>>(wo1, o1t, 1024, 1024);
    wtrans<<<dim3(32,32),  tb>>>(wo2, o2t, 1024, 1024);
    wtrans<<<dim3(256,32), tb>>>(w1,  w1t, 1024, 8192);
    wtrans<<<dim3(32,128), tb>>>(w2,  w2t, 4096, 1024);
    esplit<<<616, 256>>>(ctx, chi, clo, 157696);

    const int FSM = 90112;
    cudaFuncSetAttribute(fattn, cudaFuncAttributeMaxDynamicSharedMemorySize, FSM);

    // ===== self attention =====
    ln_kernel<<<4096, 128>>>(x, ln1g, ln1b, hh, hhl);
    { HArgs g = ha(hh, hhl, q1h, q1l, hq, 4096,1024,1024,1024, 1024,1024,1024); g.qd = dq1; run_h<128,2,true,true>(g, 1); }
    { HArgs g = ha(hh, hhl, k1h, k1l, hk, 4096,1024,1024,1024, 1024,1024,1024); g.qd = dk1; run_h<128,2,true,true>(g, 1); }
    { HArgs g = ha(hh, hhl, v1h, v1l, hv, 4096,1024,1024,1024, 1024,1024,1024); g.qd = dv1; run_h<128,2,true,true>(g, 1); }
    vtrans<<<dim3(64,2,32), tb>>>(hv, hvt, 2048, 2048);
    fattn<<<dim3(16,1,32), 256, FSM>>>(hq, hk, hvt, hpo, 2048, 2048, 2048, dq1, dk1, dw1, dv1);
    { HArgs g = ha(hpo, 0, o1t, 0, px, 4096,1024,1024,1024, 1024,1024,1024);
      g.bias = bo1; g.res = x; g.ldr = 1024; run_h<128,2,false,false>(g, 1); }

    // ===== cross attention =====
    ln_kernel<<<4096, 128>>>(px, ln2g, ln2b, hh, hhl);
    { HArgs g = ha(hh, hhl, q2h, q2l, hq, 4096,1024,1024,1024, 1024,1024,1024); g.qd = dq2; run_h<128,2,true,true>(g, 1); }
    { HArgs g = ha(chi, clo, k2h, k2l, hk, 154,1024,1024,1024, 1024,1024,1024); g.qd = dk2; run_h<128,2,true,true>(g, 1); }
    { HArgs g = ha(chi, clo, v2h, v2l, hv, 154,1024,1024,1024, 1024,1024,1024); g.qd = dv2; run_h<128,2,true,true>(g, 1); }
    vtrans<<<dim3(3,2,32), tb>>>(hv, hvt, 77, 96);
    fattn<<<dim3(16,1,32), 256, FSM>>>(hq, hk, hvt, hpo, 2048, 77, 96, dq2, dk2, dw2, dv2);
    { HArgs g = ha(hpo, 0, o2t, 0, px, 4096,1024,1024,1024, 1024,1024,1024);
      g.bias = bo2; g.res = px; g.ldr = 1024; run_h<128,2,false,false>(g, 1); }

    // ===== GEGLU feed-forward =====
    ln_kernel<<<4096, 128>>>(px, ln3g, ln3b, hh, 0);
    { HArgs g = ha(hh, 0, w1t, 0, phg, 4096,8192,8192,1024, 1024,1024,8192);
      g.bias = b1; run_h<128,2,false,false>(g, 1); }
    geglu_kernel<<<16384, 256>>>(phg, hgg);
    { HArgs g = ha(hgg, 0, w2t, 0, out, 4096,1024,1024,4096, 4096,4096,1024);
      g.bias = b2; g.res = px; g.ldr = 1024; run_h<128,2,false,false>(g, 1); }
}

// round 10
// speedup vs baseline: 3.6262x; 1.0789x over previous
#include <cuda_runtime.h>
#include <cuda_fp16.h>
#include <cstdint>
#include <math.h>

// ---------------- scratch ----------------
__device__ float g_x [4194304];
__device__ float g_h [4194304];   // ln out: half hi
__device__ float g_hl[4194304];   // ln out: half lo
__device__ float g_q [4194304];   // half codes
__device__ float g_k [4194304];
__device__ float g_v [4194304];
__device__ float g_o [4194304];   // half attn out
__device__ float g_vt[4194304];   // half v^T codes
__device__ float g_gg[16777216];  // half GEGLU out (reinterpret)
__device__ float g_w [27262976];
__device__ float g_cs[327680];

// ---------------- helpers ----------------
static __device__ __forceinline__ uint32_t smem_u32(const void* p) {
    uint32_t a;
    asm("{ .reg .u64 t; cvta.to.shared.u64 t, %1; cvt.u32.u64 %0, t; }" : "=r"(a) : "l"(p));
    return a;
}
#define MMAH(d, a, b) \
    asm volatile("mma.sync.aligned.m16n8k16.row.col.f32.f16.f16.f32 " \
        "{%0,%1,%2,%3},{%4,%5,%6,%7},{%8,%9},{%0,%1,%2,%3};" \
        : "+f"((d)[0]), "+f"((d)[1]), "+f"((d)[2]), "+f"((d)[3]) \
        : "r"((a)[0]), "r"((a)[1]), "r"((a)[2]), "r"((a)[3]), "r"((b)[0]), "r"((b)[1]))
#define CPA(dst, src, sz) \
    asm volatile("cp.async.cg.shared.global [%0], [%1], 16, %2;" :: "r"(dst), "l"(src), "r"(sz))
static __device__ __forceinline__ uint32_t ld32h(const __half* p) {
    return *reinterpret_cast<const uint32_t*>(p);
}
static __device__ __forceinline__ uint32_t packh2(float a, float b) {
    __half2 h = __floats2half2_rn(a, b);
    return *reinterpret_cast<uint32_t*>(&h);
}
static __device__ __forceinline__ float gelu(float g) {
    return 0.5f * g * (1.f + erff(g * 0.70710678118654752440f));
}

// ================= fused attention (two-pass, max-free softmax) =================
__global__ void __launch_bounds__(256)
fattn(const __half* __restrict__ q, const __half* __restrict__ k,
      const __half* __restrict__ vt, __half* __restrict__ o,
      int Tq, int Tk, int Tkpad,
      const float* __restrict__ dqp, const float* __restrict__ dkp,
      const float* __restrict__ dwp, const float* __restrict__ dvp)
{
    constexpr int QS = 128 * 72, KS = 128 * 72, VS = 64 * 136;
    extern __shared__ __half sh[];
    __half* Qs  = sh;
    __half* Ks0 = sh + QS;
    __half* Vs0 = sh + QS + 2 * KS;
    const uint32_t smb = smem_u32(sh);
    const uint32_t kb_ = smb + QS * 2, vb_ = smb + (QS + 2 * KS) * 2;

    const int tid = threadIdx.x, wid = tid >> 5, lane = tid & 31;
    const int grp = lane >> 2, tg = lane & 3;
    const int bh = blockIdx.z, b = bh >> 4, h = bh & 15;
    const int m0 = blockIdx.x * 128;
    const int nkt = (Tk + 127) >> 7;

    const float alpha = 0.125f * __ldg(dqp) * __ldg(dkp);
    const float dw = __ldg(dwp);
    const float beta = dw * __ldg(dvp);

    {
        const __half* qb = q + ((long long)b * Tq + m0) * 1024 + h * 64;
#pragma unroll
        for (int i = 0; i < 4; ++i) {
            const int idx = tid + (i << 8);
            const int r = idx >> 3, c = idx & 7;
            CPA(smb + (uint32_t)(r * 72 + (c << 3)) * 2, qb + (long long)r * 1024 + (c << 3), 16);
        }
    }

    auto loadK = [&](int t, int st) {
        const __half* kbase = k + ((long long)b * Tk) * 1024 + h * 64;
#pragma unroll
        for (int i = 0; i < 4; ++i) {
            const int idx = tid + (i << 8);
            const int r = idx >> 3, c = idx & 7;
            const int key = t * 128 + r;
            const int ok = key < Tk;
            const __half* s = ok ? (kbase + (long long)key * 1024 + (c << 3)) : kbase;
            CPA(kb_ + (uint32_t)(st * KS + r * 72 + (c << 3)) * 2, s, ok ? 16 : 0);
        }
    };
    auto loadV = [&](int t, int st) {
        const __half* vbase = vt + ((long long)bh * 64) * Tkpad;
#pragma unroll
        for (int i = 0; i < 4; ++i) {
            const int idx = tid + (i << 8);
            const int r = idx >> 4, c = idx & 15;
            const int key = t * 128 + (c << 3);
            const int ok = (key + 8) <= Tkpad;
            const __half* s = ok ? (vbase + (long long)r * Tkpad + key) : vbase;
            CPA(vb_ + (uint32_t)(st * VS + r * 136 + (c << 3)) * 2, s, ok ? 16 : 0);
        }
    };

    float sacc[16][4];
    auto computeS = [&](int st) {
#pragma unroll
        for (int nf = 0; nf < 16; ++nf)
#pragma unroll
            for (int e = 0; e < 4; ++e) sacc[nf][e] = 0.f;
        const __half* Kp = Ks0 + st * KS;
#pragma unroll
        for (int kc = 0; kc < 4; ++kc) {
            const int kb2 = kc << 4;
            const int oa = (wid * 16 + grp) * 72 + kb2 + (tg << 1);
            uint32_t ah[4] = { ld32h(Qs + oa), ld32h(Qs + oa + 576),
                               ld32h(Qs + oa + 8), ld32h(Qs + oa + 584) };
#pragma unroll
            for (int nf = 0; nf < 16; ++nf) {
                const int ob = (nf * 8 + grp) * 72 + kb2 + (tg << 1);
                uint32_t bf[2] = { ld32h(Kp + ob), ld32h(Kp + ob + 8) };
                MMAH(sacc[nf], ah, bf);
            }
        }
    };

    // ---- pass 1 ----
    float psum0 = 0.f, psum1 = 0.f;
    loadK(0, 0);
    asm volatile("cp.async.commit_group;");
    for (int t = 0; t < nkt; ++t) {
        if (t + 1 < nkt) loadK(t + 1, (t + 1) & 1);
        asm volatile("cp.async.commit_group;");
        if (t + 1 < nkt) asm volatile("cp.async.wait_group 1;");
        else             asm volatile("cp.async.wait_group 0;");
        __syncthreads();
        computeS(t & 1);
        __syncthreads();
        const int cb = t * 128;
#pragma unroll
        for (int nf = 0; nf < 16; ++nf) {
            const int c0 = cb + nf * 8 + (tg << 1);
            if (c0 < Tk)     { psum0 += expf(sacc[nf][0] * alpha); psum1 += expf(sacc[nf][2] * alpha); }
            if (c0 + 1 < Tk) { psum0 += expf(sacc[nf][1] * alpha); psum1 += expf(sacc[nf][3] * alpha); }
        }
    }
    psum0 += __shfl_xor_sync(0xffffffffu, psum0, 1);
    psum0 += __shfl_xor_sync(0xffffffffu, psum0, 2);
    psum1 += __shfl_xor_sync(0xffffffffu, psum1, 1);
    psum1 += __shfl_xor_sync(0xffffffffu, psum1, 2);

    // ---- pass 2 ----
    float oacc[8][4];
#pragma unroll
    for (int i = 0; i < 8; ++i)
#pragma unroll
        for (int e = 0; e < 4; ++e) oacc[i][e] = 0.f;

    loadK(0, 0); loadV(0, 0);
    asm volatile("cp.async.commit_group;");
    for (int t = 0; t < nkt; ++t) {
        if (t + 1 < nkt) { loadK(t + 1, (t + 1) & 1); loadV(t + 1, (t + 1) & 1); }
        asm volatile("cp.async.commit_group;");
        if (t + 1 < nkt) asm volatile("cp.async.wait_group 1;");
        else             asm volatile("cp.async.wait_group 0;");
        __syncthreads();
        computeS(t & 1);
        const __half* Vp = Vs0 + (t & 1) * VS;
        const int cb = t * 128;
#pragma unroll
        for (int kb = 0; kb < 8; ++kb) {
            uint32_t ah[4];
#pragma unroll
            for (int hf = 0; hf < 2; ++hf) {
                const int nf = 2 * kb + hf;
                const int c0 = cb + nf * 8 + (tg << 1);
                const int ok0 = c0 < Tk, ok1 = (c0 + 1) < Tk;
                float p0 = ok0 ? expf(sacc[nf][0] * alpha) / psum0 : 0.f;
                float p1 = ok1 ? expf(sacc[nf][1] * alpha) / psum0 : 0.f;
                float p2 = ok0 ? expf(sacc[nf][2] * alpha) / psum1 : 0.f;
                float p3 = ok1 ? expf(sacc[nf][3] * alpha) / psum1 : 0.f;
                const float q0 = fminf(fmaxf(rintf(p0 / dw), 0.f), 255.f);
                const float q1 = fminf(fmaxf(rintf(p1 / dw), 0.f), 255.f);
                const float q2 = fminf(fmaxf(rintf(p2 / dw), 0.f), 255.f);
                const float q3 = fminf(fmaxf(rintf(p3 / dw), 0.f), 255.f);
                ah[hf * 2]     = packh2(q0, q1);
                ah[hf * 2 + 1] = packh2(q2, q3);
            }
#pragma unroll
            for (int nfo = 0; nfo < 8; ++nfo) {
                const int ob = (nfo * 8 + grp) * 136 + (kb << 4) + (tg << 1);
                uint32_t bf[2] = { ld32h(Vp + ob), ld32h(Vp + ob + 8) };
                MMAH(oacc[nfo], ah, bf);
            }
        }
        __syncthreads();
    }

    const int row0 = m0 + wid * 16 + grp;
    __half* ob = o + ((long long)b * Tq) * 1024 + h * 64;
#pragma unroll
    for (int nfo = 0; nfo < 8; ++nfo) {
        const int c = nfo * 8 + (tg << 1);
        *reinterpret_cast<__half2*>(ob + (long long)row0 * 1024 + c) =
            __floats2half2_rn(oacc[nfo][0] * beta, oacc[nfo][1] * beta);
        *reinterpret_cast<__half2*>(ob + (long long)(row0 + 8) * 1024 + c) =
            __floats2half2_rn(oacc[nfo][2] * beta, oacc[nfo][3] * beta);
    }
}

// ================= fp16 mma GEMM =================
// C = s0*s1*s2*(A[M,K] @ B[N,K]^T) [+bias] [+res] [->quant] [->GEGLU], batched
struct HArgs {
    const __half *A, *Al, *B, *Bl; void* C;
    int M, N, Nstore, K, lda, ldb, ldc, ldr;
    long long sAb, sAh, sBb, sBh, sCb, sCh;
    const float *bias, *res, *s1, *s2, *qd;
    float s0;
};

// GEGLU virtual-row mapping: virtual n -> source row of w1t (w1 column)
static __device__ __forceinline__ int geglu_src(int n) {
    const int gp = n >> 4, r = n & 15;
    return (r < 8) ? (gp * 8 + r) : (4096 + gp * 8 + (r - 8));
}

template<int BN, int WM, int BK, bool SPLIT, bool CHALF, bool GEGLU>
__global__ void __launch_bounds__(256)
hgemm(const __grid_constant__ HArgs g)
{
    constexpr int WN = 8 / WM, WTM = 128 / WM, WTN = BN / WN;
    constexpr int MF = WTM / 16, NF = WTN / 8;
    constexpr int SB = BK + 8;
    constexpr int AS = 128 * SB, BS = BN * SB;
    constexpr int NT = SPLIT ? 2 : 1, STG = NT * (AS + BS);
    constexpr int KPC = BK / 8;              // 16B chunks per row
    constexpr int KK  = BK / 16;

    extern __shared__ __half smh[];
    const uint32_t smb = smem_u32(smh);
    const int tid = threadIdx.x, wid = tid >> 5, lane = tid & 31;
    const int grp = lane >> 2, tg = lane & 3;
    const int wm = wid / WN, wn = wid % WN;

    const int z = blockIdx.z, bb = z >> 4, hb = z & 15;
    const __half* Ab = g.A + bb * g.sAb + hb * g.sAh;
    const __half* Al = SPLIT ? (g.Al + bb * g.sAb + hb * g.sAh) : (const __half*)0;
    const __half* Bb = g.B + bb * g.sBb + hb * g.sBh;
    const __half* Bl = SPLIT ? (g.Bl + bb * g.sBb + hb * g.sBh) : (const __half*)0;

    const int bm = blockIdx.y * 128, bn = blockIdx.x * BN;
    const int nch = g.K / BK;

    float acc[MF][NF][4];
#pragma unroll
    for (int i = 0; i < MF; ++i)
#pragma unroll
        for (int j = 0; j < NF; ++j)
#pragma unroll
            for (int c = 0; c < 4; ++c) acc[i][j][c] = 0.f;

    auto issue = [&](int ch, int st) {
        const int k0 = ch * BK;
        const uint32_t sa = smb + (uint32_t)st * STG * 2;
#pragma unroll
        for (int i = 0; i < 128 * KPC / 256; ++i) {
            const int idx = tid + (i << 8);
            const int r = idx / KPC, c = idx % KPC;
            const int gr = bm + r, ok = (gr < g.M);
            const __half* s = ok ? (Ab + (long long)gr * g.lda + k0 + (c << 3)) : Ab;
            const uint32_t d = sa + (uint32_t)(r * SB + (c << 3)) * 2;
            CPA(d, s, ok ? 16 : 0);
            if (SPLIT) {
                const __half* s2 = ok ? (Al + (long long)gr * g.lda + k0 + (c << 3)) : Al;
                CPA(d + AS * 2, s2, ok ? 16 : 0);
            }
        }
#pragma unroll
        for (int i = 0; i < BN * KPC / 256; ++i) {
            const int idx = tid + (i << 8);
            const int r = idx / KPC, c = idx % KPC;
            const int gn = bn + r, ok = (gn < g.N);
            const int srow = GEGLU ? geglu_src(gn) : gn;
            const __half* s = ok ? (Bb + (long long)srow * g.ldb + k0 + (c << 3)) : Bb;
            const uint32_t d = sa + (uint32_t)(NT * AS + r * SB + (c << 3)) * 2;
            CPA(d, s, ok ? 16 : 0);
            if (SPLIT) {
                const __half* s2 = ok ? (Bl + (long long)srow * g.ldb + k0 + (c << 3)) : Bl;
                CPA(d + BS * 2, s2, ok ? 16 : 0);
            }
        }
    };

    auto compute = [&](int st) {
        const __half* sa  = smh + st * STG;
        const __half* sal = sa + AS;
        const __half* sbh = sa + NT * AS;
        const __half* sbl = sbh + BS;
#pragma unroll
        for (int kk = 0; kk < KK; ++kk) {
            const int kb = kk << 4;
            uint32_t bh[NF][2], bl[NF][2];
#pragma unroll
            for (int nf = 0; nf < NF; ++nf) {
                const int o = (wn * WTN + (nf << 3) + grp) * SB + kb + (tg << 1);
                bh[nf][0] = ld32h(sbh + o); bh[nf][1] = ld32h(sbh + o + 8);
                if (SPLIT) { bl[nf][0] = ld32h(sbl + o); bl[nf][1] = ld32h(sbl + o + 8); }
            }
#pragma unroll
            for (int mf = 0; mf < MF; ++mf) {
                const int o = (wm * WTM + (mf << 4) + grp) * SB + kb + (tg << 1);
                uint32_t ah[4] = { ld32h(sa + o), ld32h(sa + o + 8 * SB),
                                   ld32h(sa + o + 8), ld32h(sa + o + 8 * SB + 8) };
#pragma unroll
                for (int nf = 0; nf < NF; ++nf) MMAH(acc[mf][nf], ah, bh[nf]);
                if (SPLIT) {
                    uint32_t al[4] = { ld32h(sal + o), ld32h(sal + o + 8 * SB),
                                       ld32h(sal + o + 8), ld32h(sal + o + 8 * SB + 8) };
#pragma unroll
                    for (int nf = 0; nf < NF; ++nf) {
                        MMAH(acc[mf][nf], ah, bl[nf]);
                        MMAH(acc[mf][nf], al, bh[nf]);
                    }
                }
            }
        }
    };

    issue(0, 0);
    asm volatile("cp.async.commit_group;");
    for (int ch = 0; ch < nch; ++ch) {
        if (ch + 1 < nch) issue(ch + 1, (ch + 1) & 1);
        asm volatile("cp.async.commit_group;");
        asm volatile("cp.async.wait_group 1;");
        __syncthreads();
        compute(ch & 1);
        __syncthreads();
    }

    if (GEGLU) {
        // pairs: frag 2p = a-cols, frag 2p+1 = g-cols (same output cols, same lanes)
#pragma unroll
        for (int mf = 0; mf < MF; ++mf) {
            const int r0 = bm + wm * WTM + (mf << 4) + grp;
#pragma unroll
            for (int p = 0; p < NF / 2; ++p) {
                const int va = bn + wn * WTN + (p << 4) + (tg << 1);   // virtual a-col (e&1==0)
                const int oc = ((va >> 4) << 3) + (va & 7);            // output col
                const float ba0 = __ldg(g.bias + oc),        ba1 = __ldg(g.bias + oc + 1);
                const float bg0 = __ldg(g.bias + 4096 + oc), bg1 = __ldg(g.bias + 4096 + oc + 1);
                float* A2 = acc[mf][2 * p];
                float* G2 = acc[mf][2 * p + 1];
#pragma unroll
                for (int hrow = 0; hrow < 2; ++hrow) {
                    const int r = r0 + hrow * 8;
                    const float a0 = A2[hrow * 2 + 0] + ba0, a1 = A2[hrow * 2 + 1] + ba1;
                    const float g0 = G2[hrow * 2 + 0] + bg0, g1 = G2[hrow * 2 + 1] + bg1;
                    *reinterpret_cast<__half2*>((__half*)g.C + (long long)r * g.ldc + oc) =
                        __floats2half2_rn(a0 * gelu(g0), a1 * gelu(g1));
                }
            }
        }
        return;
    }

    float alpha = g.s0;
    if (g.s1) alpha *= __ldg(g.s1);
    if (g.s2) alpha *= __ldg(g.s2);
    const float qd = g.qd ? __ldg(g.qd) : 1.f;
#pragma unroll
    for (int mf = 0; mf < MF; ++mf) {
        const int r0 = bm + wm * WTM + (mf << 4) + grp;
#pragma unroll
        for (int nf = 0; nf < NF; ++nf) {
            const int c0 = bn + wn * WTN + (nf << 3) + (tg << 1);
#pragma unroll
            for (int e = 0; e < 4; ++e) {
                const int r = r0 + ((e >> 1) << 3);
                const int c = c0 + (e & 1);
                if (r < g.M && c < g.Nstore) {
                    float v = acc[mf][nf][e] * alpha;
                    if (g.bias) v += __ldg(g.bias + c);
                    if (g.res)  v += g.res[(long long)r * g.ldr + c];
                    if (g.qd) {
                        float xi = rintf(v / qd) + 128.f;
                        v = fminf(fmaxf(xi, 0.f), 255.f) - 128.f;
                    }
                    const long long o = (long long)(bb * g.sCb + hb * g.sCh) + (long long)r * g.ldc + c;
                    if (CHALF) ((__half*)g.C)[o] = __float2half_rn(v);
                    else       ((float*)g.C)[o] = v;
                }
            }
        }
    }
}

template<int BN, int WM, int BK, bool SPLIT, bool CHALF, bool GEGLU>
static void run_h(HArgs a, int nb)
{
    constexpr int STG = (SPLIT ? 2 : 1) * ((128 + BN) * (BK + 8));
    const int smem = 2 * STG * 2;
    cudaFuncSetAttribute(hgemm<BN, WM, BK, SPLIT, CHALF, GEGLU>,
                         cudaFuncAttributeMaxDynamicSharedMemorySize, smem);
    dim3 grid((a.N + BN - 1) / BN, (a.M + 127) / 128, nb);
    hgemm<BN, WM, BK, SPLIT, CHALF, GEGLU><<<grid, 256, smem>>>(a);
}
static HArgs ha(const __half* A, const __half* Al, const __half* B, const __half* Bl,
                void* C, int M, int N, int Nstore, int K, int lda, int ldb, int ldc)
{
    HArgs g;
    g.A = A; g.Al = Al; g.B = B; g.Bl = Bl; g.C = C;
    g.M = M; g.N = N; g.Nstore = Nstore; g.K = K;
    g.lda = lda; g.ldb = ldb; g.ldc = ldc; g.ldr = 0;
    g.sAb = g.sAh = g.sBb = g.sBh = g.sCb = g.sCh = 0;
    g.bias = 0; g.res = 0; g.s1 = 0; g.s2 = 0; g.qd = 0; g.s0 = 1.f;
    return g;
}

// ---------------- transposes / splits ----------------
__global__ void wtrans(const float* __restrict__ in, __half* __restrict__ out, int K, int N)
{
    __shared__ float t[32][33];
    const int n0 = blockIdx.x * 32, k0 = blockIdx.y * 32;
    const int tx = threadIdx.x, ty = threadIdx.y;
#pragma unroll
    for (int i = 0; i < 32; i += 8)
        t[ty + i][tx] = in[(long long)(k0 + ty + i) * N + n0 + tx];
    __syncthreads();
#pragma unroll
    for (int i = 0; i < 32; i += 8)
        out[(long long)(n0 + ty + i) * K + k0 + tx] = __float2half_rn(t[tx][ty + i]);
}
__global__ void wtrans_split(const float* __restrict__ in, __half* __restrict__ oH,
                             __half* __restrict__ oL, int K, int N)
{
    __shared__ float t[32][33];
    const int n0 = blockIdx.x * 32, k0 = blockIdx.y * 32;
    const int tx = threadIdx.x, ty = threadIdx.y;
#pragma unroll
    for (int i = 0; i < 32; i += 8)
        t[ty + i][tx] = in[(long long)(k0 + ty + i) * N + n0 + tx];
    __syncthreads();
#pragma unroll
    for (int i = 0; i < 32; i += 8) {
        const float v = t[tx][ty + i];
        const __half h = __float2half_rn(v);
        const long long o = (long long)(n0 + ty + i) * K + k0 + tx;
        oH[o] = h; oL[o] = __float2half_rn(v - __half2float(h));
    }
}
__global__ void vtrans(const __half* __restrict__ v, __half* __restrict__ vt, int T, int Tpad)
{
    __shared__ float t[32][33];
    const int bz = blockIdx.z, b = bz >> 4, h = bz & 15;
    const int t0 = blockIdx.x * 32, d0 = blockIdx.y * 32;
    const int tx = threadIdx.x, ty = threadIdx.y;
#pragma unroll
    for (int i = 0; i < 32; i += 8) {
        const int tt = t0 + ty + i;
        t[ty + i][tx] = (tt < T) ? __half2float(v[((long long)b * T + tt) * 1024 + h * 64 + d0 + tx]) : 0.f;
    }
    __syncthreads();
#pragma unroll
    for (int i = 0; i < 32; i += 8) {
        const int tt = t0 + tx;
        if (tt < Tpad)
            vt[(((long long)b * 16 + h) * 64 + d0 + ty + i) * Tpad + tt] = __float2half_rn(t[tx][ty + i]);
    }
}
__global__ void esplit(const float* __restrict__ in, __half* __restrict__ oH,
                       __half* __restrict__ oL, int n)
{
    const int i = blockIdx.x * 256 + threadIdx.x;
    if (i < n) {
        const float v = in[i];
        const __half h = __float2half_rn(v);
        oH[i] = h; oL[i] = __float2half_rn(v - __half2float(h));
    }
}

// ---------------- layernorm ----------------
__global__ void ln_kernel(const float* __restrict__ x, const float* __restrict__ gm,
                          const float* __restrict__ bt,
                          __half* __restrict__ outH, __half* __restrict__ outL)
{
    __shared__ float red[4];
    const long long row = blockIdx.x;
    const float* xr = x + row * 1024;
    const int t = threadIdx.x;
    float v[8];
    *reinterpret_cast<float4*>(&v[0]) = *reinterpret_cast<const float4*>(xr + t * 8);
    *reinterpret_cast<float4*>(&v[4]) = *reinterpret_cast<const float4*>(xr + t * 8 + 4);
    float s = 0.f;
#pragma unroll
    for (int i = 0; i < 8; ++i) s += v[i];
#pragma unroll
    for (int o = 16; o; o >>= 1) s += __shfl_xor_sync(0xffffffffu, s, o);
    if ((t & 31) == 0) red[t >> 5] = s;
    __syncthreads();
    const float mu = (red[0] + red[1] + red[2] + red[3]) * (1.f / 1024.f);
    __syncthreads();
    float ss = 0.f;
#pragma unroll
    for (int i = 0; i < 8; ++i) { float d = v[i] - mu; ss += d * d; }
#pragma unroll
    for (int o = 16; o; o >>= 1) ss += __shfl_xor_sync(0xffffffffu, ss, o);
    if ((t & 31) == 0) red[t >> 5] = ss;
    __syncthreads();
    const float rs = rsqrtf((red[0] + red[1] + red[2] + red[3]) * (1.f / 1024.f) + 1e-5f);
#pragma unroll
    for (int i = 0; i < 8; ++i) {
        const int c = t * 8 + i;
        const float y = (v[i] - mu) * rs * gm[c] + bt[c];
        const __half h = __float2half_rn(y);
        outH[row * 1024 + c] = h;
        if (outL) outL[row * 1024 + c] = __float2half_rn(y - __half2float(h));
    }
}

// ---------------- launcher ----------------
extern "C" void kernel_launch(void* const* d_in, const int* in_sizes, int n_in,
                              void* d_out, int out_size)
{
    (void)in_sizes; (void)n_in; (void)out_size;
    const float* x   = (const float*)d_in[0];
    const float* ctx = (const float*)d_in[1];
    const float *ln1g = (const float*)d_in[2], *ln1b = (const float*)d_in[3];
    const float *ln2g = (const float*)d_in[4], *ln2b = (const float*)d_in[5];
    const float *ln3g = (const float*)d_in[6], *ln3b = (const float*)d_in[7];
    const float *wq1 = (const float*)d_in[8],  *wk1 = (const float*)d_in[9];
    const float *wv1 = (const float*)d_in[10], *wo1 = (const float*)d_in[11];
    const float *bo1 = (const float*)d_in[12];
    const float *wq2 = (const float*)d_in[13], *wk2 = (const float*)d_in[14];
    const float *wv2 = (const float*)d_in[15], *wo2 = (const float*)d_in[16];
    const float *bo2 = (const float*)d_in[17];
    const float *w1 = (const float*)d_in[18], *b1 = (const float*)d_in[19];
    const float *w2 = (const float*)d_in[20], *b2 = (const float*)d_in[21];
    const float *dq1 = (const float*)d_in[22], *dk1 = (const float*)d_in[23];
    const float *dv1 = (const float*)d_in[24], *dw1 = (const float*)d_in[25];
    const float *dq2 = (const float*)d_in[26], *dk2 = (const float*)d_in[27];
    const float *dv2 = (const float*)d_in[28], *dw2 = (const float*)d_in[29];
    float* out = (float*)d_out;

    float *px, *ph, *phl, *pq, *pk, *pv, *po, *pvt, *pgg, *pw, *pcs;
    cudaGetSymbolAddress((void**)&px,  g_x);
    cudaGetSymbolAddress((void**)&ph,  g_h);
    cudaGetSymbolAddress((void**)&phl, g_hl);
    cudaGetSymbolAddress((void**)&pq,  g_q);
    cudaGetSymbolAddress((void**)&pk,  g_k);
    cudaGetSymbolAddress((void**)&pv,  g_v);
    cudaGetSymbolAddress((void**)&po,  g_o);
    cudaGetSymbolAddress((void**)&pvt, g_vt);
    cudaGetSymbolAddress((void**)&pgg, g_gg);
    cudaGetSymbolAddress((void**)&pw,  g_w);
    cudaGetSymbolAddress((void**)&pcs, g_cs);

    __half *hh = (__half*)ph, *hhl = (__half*)phl;
    __half *hq = (__half*)pq, *hk = (__half*)pk, *hv = (__half*)pv, *hvt = (__half*)pvt;
    __half *hpo = (__half*)po, *hgg = (__half*)pgg;

    const long long M1 = 1048576;
    __half *q1h = (__half*)pw,          *q1l = (__half*)(pw + M1);
    __half *k1h = (__half*)(pw + 2*M1), *k1l = (__half*)(pw + 3*M1);
    __half *v1h = (__half*)(pw + 4*M1), *v1l = (__half*)(pw + 5*M1);
    __half *q2h = (__half*)(pw + 6*M1), *q2l = (__half*)(pw + 7*M1);
    __half *k2h = (__half*)(pw + 8*M1), *k2l = (__half*)(pw + 9*M1);
    __half *v2h = (__half*)(pw + 10*M1),*v2l = (__half*)(pw + 11*M1);
    __half *o1t = (__half*)(pw + 12*M1), *o2t = (__half*)(pw + 13*M1);
    __half *w1t = (__half*)(pw + 14*M1), *w2t = (__half*)(pw + 18*M1);
    __half *chi = (__half*)pcs, *clo = (__half*)(pcs + 80000);

    dim3 tb(32, 8);
    wtrans_split<<<dim3(32,32), tb>>>(wq1, q1h, q1l, 1024, 1024);
    wtrans_split<<<dim3(32,32), tb>>>(wk1, k1h, k1l, 1024, 1024);
    wtrans_split<<<dim3(32,32), tb>>>(wv1, v1h, v1l, 1024, 1024);
    wtrans_split<<<dim3(32,32), tb>>>(wq2, q2h, q2l, 1024, 1024);
    wtrans_split<<<dim3(32,32), tb>>>(wk2, k2h, k2l, 1024, 1024);
    wtrans_split<<<dim3(32,32), tb>>>(wv2, v2h, v2l, 1024, 1024);
    wtrans<<<dim3(32,32),  tb>>>(wo1, o1t, 1024, 1024);
    wtrans<<<dim3(32,32),  tb>>>(wo2, o2t, 1024, 1024);
    wtrans<<<dim3(256,32), tb>>>(w1,  w1t, 1024, 8192);
    wtrans<<<dim3(32,128), tb>>>(w2,  w2t, 4096, 1024);
    esplit<<<616, 256>>>(ctx, chi, clo, 157696);

    const int FSM = 90112;
    cudaFuncSetAttribute(fattn, cudaFuncAttributeMaxDynamicSharedMemorySize, FSM);

    const long long ND = 2048LL * 1024;

    // ===== self attention =====
    ln_kernel<<<4096, 128>>>(x, ln1g, ln1b, hh, hhl);
    { HArgs g = ha(hh, hhl, q1h, q1l, hq, 4096,1024,1024,1024, 1024,1024,1024); g.qd = dq1; run_h<128,2,32,true,true,false>(g, 1); }
    { HArgs g = ha(hh, hhl, k1h, k1l, hk, 4096,1024,1024,1024, 1024,1024,1024); g.qd = dk1; run_h<128,2,32,true,true,false>(g, 1); }
    { HArgs g = ha(hh, hhl, v1h, v1l, hv, 4096,1024,1024,1024, 1024,1024,1024); g.qd = dv1; run_h<128,2,32,true,true,false>(g, 1); }
    vtrans<<<dim3(64,2,32), tb>>>(hv, hvt, 2048, 2048);
    fattn<<<dim3(16,1,32), 256, FSM>>>(hq, hk, hvt, hpo, 2048, 2048, 2048, dq1, dk1, dw1, dv1);
    { HArgs g = ha(hpo, 0, o1t, 0, px, 4096,1024,1024,1024, 1024,1024,1024);
      g.bias = bo1; g.res = x; g.ldr = 1024; run_h<128,2,64,false,false,false>(g, 1); }

    // ===== cross attention =====
    ln_kernel<<<4096, 128>>>(px, ln2g, ln2b, hh, hhl);
    { HArgs g = ha(hh, hhl, q2h, q2l, hq, 4096,1024,1024,1024, 1024,1024,1024); g.qd = dq2; run_h<128,2,32,true,true,false>(g, 1); }
    { HArgs g = ha(chi, clo, k2h, k2l, hk, 154,1024,1024,1024, 1024,1024,1024); g.qd = dk2; run_h<128,2,32,true,true,false>(g, 1); }
    { HArgs g = ha(chi, clo, v2h, v2l, hv, 154,1024,1024,1024, 1024,1024,1024); g.qd = dv2; run_h<128,2,32,true,true,false>(g, 1); }
    vtrans<<<dim3(3,2,32), tb>>>(hv, hvt, 77, 96);
    fattn<<<dim3(16,1,32), 256, FSM>>>(hq, hk, hvt, hpo, 2048, 77, 96, dq2, dk2, dw2, dv2);
    { HArgs g = ha(hpo, 0, o2t, 0, px, 4096,1024,1024,1024, 1024,1024,1024);
      g.bias = bo2; g.res = px; g.ldr = 1024; run_h<128,2,64,false,false,false>(g, 1); }

    // ===== GEGLU feed-forward (fused FFN1+GEGLU) =====
    ln_kernel<<<4096, 128>>>(px, ln3g, ln3b, hh, 0);
    { HArgs g = ha(hh, 0, w1t, 0, hgg, 4096,8192,8192,1024, 1024,1024,4096);
      g.bias = b1; run_h<128,2,64,false,true,true>(g, 1); }
    { HArgs g = ha(hgg, 0, w2t, 0, out, 4096,1024,1024,4096, 4096,4096,1024);
      g.bias = b2; g.res = px; g.ldr = 1024; run_h<128,2,64,false,false,false>(g, 1); }
}

// round 11
// speedup vs baseline: 3.7398x; 1.0313x over previous
#include <cuda_runtime.h>
#include <cuda_fp16.h>
#include <cstdint>
#include <math.h>

// ---------------- scratch ----------------
__device__ float g_x [4194304];
__device__ float g_h [4194304];   // ln out: half hi
__device__ float g_hl[4194304];   // ln out: half lo
__device__ float g_q [4194304];   // half codes
__device__ float g_k [4194304];
__device__ float g_v [4194304];
__device__ float g_o [4194304];   // half attn out
__device__ float g_vt[4194304];   // half v^T codes
__device__ float g_gg[16777216];  // half GEGLU out (reinterpret)
__device__ float g_w [27262976];
__device__ float g_cs[327680];

// ---------------- helpers ----------------
static __device__ __forceinline__ uint32_t smem_u32(const void* p) {
    uint32_t a;
    asm("{ .reg .u64 t; cvta.to.shared.u64 t, %1; cvt.u32.u64 %0, t; }" : "=r"(a) : "l"(p));
    return a;
}
#define MMAH(d, a, b) \
    asm volatile("mma.sync.aligned.m16n8k16.row.col.f32.f16.f16.f32 " \
        "{%0,%1,%2,%3},{%4,%5,%6,%7},{%8,%9},{%0,%1,%2,%3};" \
        : "+f"((d)[0]), "+f"((d)[1]), "+f"((d)[2]), "+f"((d)[3]) \
        : "r"((a)[0]), "r"((a)[1]), "r"((a)[2]), "r"((a)[3]), "r"((b)[0]), "r"((b)[1]))
#define LDSM4(r0, r1, r2, r3, addr) \
    asm volatile("ldmatrix.sync.aligned.m8n8.x4.shared.b16 {%0,%1,%2,%3}, [%4];" \
        : "=r"(r0), "=r"(r1), "=r"(r2), "=r"(r3) : "r"(addr))
#define CPA(dst, src, sz) \
    asm volatile("cp.async.cg.shared.global [%0], [%1], 16, %2;" :: "r"(dst), "l"(src), "r"(sz))
static __device__ __forceinline__ uint32_t packh2(float a, float b) {
    __half2 h = __floats2half2_rn(a, b);
    return *reinterpret_cast<uint32_t*>(&h);
}
static __device__ __forceinline__ float gelu(float g) {
    return 0.5f * g * (1.f + erff(g * 0.70710678118654752440f));
}

// ================= fused attention (two-pass, max-free softmax) =================
__global__ void __launch_bounds__(256)
fattn(const __half* __restrict__ q, const __half* __restrict__ k,
      const __half* __restrict__ vt, __half* __restrict__ o,
      int Tq, int Tk, int Tkpad,
      const float* __restrict__ dqp, const float* __restrict__ dkp,
      const float* __restrict__ dwp, const float* __restrict__ dvp)
{
    constexpr int QS = 128 * 72, KS = 128 * 72, VS = 64 * 136;
    extern __shared__ __half sh[];
    const uint32_t smb = smem_u32(sh);
    const uint32_t kb_ = smb + QS * 2, vb_ = smb + (QS + 2 * KS) * 2;

    const int tid = threadIdx.x, wid = tid >> 5, lane = tid & 31;
    const int grp = lane >> 2, tg = lane & 3;
    const int lm = lane & 7, lmat = lane >> 3;
    const int bh = blockIdx.z, b = bh >> 4, h = bh & 15;
    const int m0 = blockIdx.x * 128;
    const int nkt = (Tk + 127) >> 7;

    const float alpha = 0.125f * __ldg(dqp) * __ldg(dkp);
    const float dw = __ldg(dwp);
    const float beta = dw * __ldg(dvp);

    // ldmatrix per-lane offsets (bytes)
    const uint32_t qOff = ((uint32_t)((wid * 16 + (lmat & 1) * 8 + lm) * 72 + ((lmat >> 1) << 3))) * 2;
    uint32_t kOff[8], vOff[4];
#pragma unroll
    for (int p = 0; p < 8; ++p)
        kOff[p] = ((uint32_t)((p * 16 + (lmat >> 1) * 8 + lm) * 72 + ((lmat & 1) << 3))) * 2;
#pragma unroll
    for (int p = 0; p < 4; ++p)
        vOff[p] = ((uint32_t)((p * 16 + (lmat >> 1) * 8 + lm) * 136 + ((lmat & 1) << 3))) * 2;

    {
        const __half* qb = q + ((long long)b * Tq + m0) * 1024 + h * 64;
#pragma unroll
        for (int i = 0; i < 4; ++i) {
            const int idx = tid + (i << 8);
            const int r = idx >> 3, c = idx & 7;
            CPA(smb + (uint32_t)(r * 72 + (c << 3)) * 2, qb + (long long)r * 1024 + (c << 3), 16);
        }
    }

    auto loadK = [&](int t, int st) {
        const __half* kbase = k + ((long long)b * Tk) * 1024 + h * 64;
#pragma unroll
        for (int i = 0; i < 4; ++i) {
            const int idx = tid + (i << 8);
            const int r = idx >> 3, c = idx & 7;
            const int key = t * 128 + r;
            const int ok = key < Tk;
            const __half* s = ok ? (kbase + (long long)key * 1024 + (c << 3)) : kbase;
            CPA(kb_ + (uint32_t)(st * KS + r * 72 + (c << 3)) * 2, s, ok ? 16 : 0);
        }
    };
    auto loadV = [&](int t, int st) {
        const __half* vbase = vt + ((long long)bh * 64) * Tkpad;
#pragma unroll
        for (int i = 0; i < 4; ++i) {
            const int idx = tid + (i << 8);
            const int r = idx >> 4, c = idx & 15;
            const int key = t * 128 + (c << 3);
            const int ok = (key + 8) <= Tkpad;
            const __half* s = ok ? (vbase + (long long)r * Tkpad + key) : vbase;
            CPA(vb_ + (uint32_t)(st * VS + r * 136 + (c << 3)) * 2, s, ok ? 16 : 0);
        }
    };

    float sacc[16][4];
    auto computeS = [&](int st) {
#pragma unroll
        for (int nf = 0; nf < 16; ++nf)
#pragma unroll
            for (int e = 0; e < 4; ++e) sacc[nf][e] = 0.f;
        const uint32_t kB = kb_ + (uint32_t)st * KS * 2;
#pragma unroll
        for (int kc = 0; kc < 4; ++kc) {
            const uint32_t kb2 = (uint32_t)(kc << 5);   // 16 halfs = 32 bytes
            uint32_t ah[4];
            LDSM4(ah[0], ah[1], ah[2], ah[3], smb + qOff + kb2);
            uint32_t bf[16][2];
#pragma unroll
            for (int p = 0; p < 8; ++p)
                LDSM4(bf[2*p][0], bf[2*p][1], bf[2*p+1][0], bf[2*p+1][1], kB + kOff[p] + kb2);
#pragma unroll
            for (int nf = 0; nf < 16; ++nf) MMAH(sacc[nf], ah, bf[nf]);
        }
    };

    // ---- pass 1 ----
    float psum0 = 0.f, psum1 = 0.f;
    loadK(0, 0);
    asm volatile("cp.async.commit_group;");
    for (int t = 0; t < nkt; ++t) {
        if (t + 1 < nkt) loadK(t + 1, (t + 1) & 1);
        asm volatile("cp.async.commit_group;");
        if (t + 1 < nkt) asm volatile("cp.async.wait_group 1;");
        else             asm volatile("cp.async.wait_group 0;");
        __syncthreads();
        computeS(t & 1);
        __syncthreads();
        const int cb = t * 128;
#pragma unroll
        for (int nf = 0; nf < 16; ++nf) {
            const int c0 = cb + nf * 8 + (tg << 1);
            if (c0 < Tk)     { psum0 += expf(sacc[nf][0] * alpha); psum1 += expf(sacc[nf][2] * alpha); }
            if (c0 + 1 < Tk) { psum0 += expf(sacc[nf][1] * alpha); psum1 += expf(sacc[nf][3] * alpha); }
        }
    }
    psum0 += __shfl_xor_sync(0xffffffffu, psum0, 1);
    psum0 += __shfl_xor_sync(0xffffffffu, psum0, 2);
    psum1 += __shfl_xor_sync(0xffffffffu, psum1, 1);
    psum1 += __shfl_xor_sync(0xffffffffu, psum1, 2);

    // ---- pass 2 ----
    float oacc[8][4];
#pragma unroll
    for (int i = 0; i < 8; ++i)
#pragma unroll
        for (int e = 0; e < 4; ++e) oacc[i][e] = 0.f;

    loadK(0, 0); loadV(0, 0);
    asm volatile("cp.async.commit_group;");
    for (int t = 0; t < nkt; ++t) {
        if (t + 1 < nkt) { loadK(t + 1, (t + 1) & 1); loadV(t + 1, (t + 1) & 1); }
        asm volatile("cp.async.commit_group;");
        if (t + 1 < nkt) asm volatile("cp.async.wait_group 1;");
        else             asm volatile("cp.async.wait_group 0;");
        __syncthreads();
        computeS(t & 1);
        const uint32_t vB = vb_ + (uint32_t)(t & 1) * VS * 2;
        const int cb = t * 128;
#pragma unroll
        for (int kb = 0; kb < 8; ++kb) {
            uint32_t ah[4];
#pragma unroll
            for (int hf = 0; hf < 2; ++hf) {
                const int nf = 2 * kb + hf;
                const int c0 = cb + nf * 8 + (tg << 1);
                const int ok0 = c0 < Tk, ok1 = (c0 + 1) < Tk;
                float p0 = ok0 ? expf(sacc[nf][0] * alpha) / psum0 : 0.f;
                float p1 = ok1 ? expf(sacc[nf][1] * alpha) / psum0 : 0.f;
                float p2 = ok0 ? expf(sacc[nf][2] * alpha) / psum1 : 0.f;
                float p3 = ok1 ? expf(sacc[nf][3] * alpha) / psum1 : 0.f;
                const float q0 = fminf(fmaxf(rintf(p0 / dw), 0.f), 255.f);
                const float q1 = fminf(fmaxf(rintf(p1 / dw), 0.f), 255.f);
                const float q2 = fminf(fmaxf(rintf(p2 / dw), 0.f), 255.f);
                const float q3 = fminf(fmaxf(rintf(p3 / dw), 0.f), 255.f);
                ah[hf * 2]     = packh2(q0, q1);
                ah[hf * 2 + 1] = packh2(q2, q3);
            }
            const uint32_t kb2 = (uint32_t)(kb << 5);
            uint32_t bf[8][2];
#pragma unroll
            for (int p = 0; p < 4; ++p)
                LDSM4(bf[2*p][0], bf[2*p][1], bf[2*p+1][0], bf[2*p+1][1], vB + vOff[p] + kb2);
#pragma unroll
            for (int nfo = 0; nfo < 8; ++nfo) MMAH(oacc[nfo], ah, bf[nfo]);
        }
        __syncthreads();
    }

    const int row0 = m0 + wid * 16 + grp;
    __half* ob = o + ((long long)b * Tq) * 1024 + h * 64;
#pragma unroll
    for (int nfo = 0; nfo < 8; ++nfo) {
        const int c = nfo * 8 + (tg << 1);
        *reinterpret_cast<__half2*>(ob + (long long)row0 * 1024 + c) =
            __floats2half2_rn(oacc[nfo][0] * beta, oacc[nfo][1] * beta);
        *reinterpret_cast<__half2*>(ob + (long long)(row0 + 8) * 1024 + c) =
            __floats2half2_rn(oacc[nfo][2] * beta, oacc[nfo][3] * beta);
    }
}

// ================= fp16 mma GEMM =================
struct HArgs {
    const __half *A, *Al, *B, *Bl; void* C;
    int M, N, Nstore, K, lda, ldb, ldc, ldr;
    long long sAb, sAh, sBb, sBh, sCb, sCh;
    const float *bias, *res, *s1, *s2, *qd;
    float s0;
};

static __device__ __forceinline__ int geglu_src(int n) {
    const int gp = n >> 4, r = n & 15;
    return (r < 8) ? (gp * 8 + r) : (4096 + gp * 8 + (r - 8));
}

template<int BN, int WM, int BK, bool SPLIT, bool CHALF, bool GEGLU>
__global__ void __launch_bounds__(256)
hgemm(const __grid_constant__ HArgs g)
{
    constexpr int WN = 8 / WM, WTM = 128 / WM, WTN = BN / WN;
    constexpr int MF = WTM / 16, NF = WTN / 8;
    constexpr int SB = BK + 8;
    constexpr int AS = 128 * SB, BS = BN * SB;
    constexpr int NT = SPLIT ? 2 : 1, STG = NT * (AS + BS);
    constexpr int KPC = BK / 8;
    constexpr int KK  = BK / 16;

    extern __shared__ __half smh[];
    const uint32_t smb = smem_u32(smh);
    const int tid = threadIdx.x, wid = tid >> 5, lane = tid & 31;
    const int grp = lane >> 2, tg = lane & 3;
    const int lm = lane & 7, lmat = lane >> 3;
    const int wm = wid / WN, wn = wid % WN;

    const int z = blockIdx.z, bb = z >> 4, hb = z & 15;
    const __half* Ab = g.A + bb * g.sAb + hb * g.sAh;
    const __half* Al = SPLIT ? (g.Al + bb * g.sAb + hb * g.sAh) : (const __half*)0;
    const __half* Bb = g.B + bb * g.sBb + hb * g.sBh;
    const __half* Bl = SPLIT ? (g.Bl + bb * g.sBb + hb * g.sBh) : (const __half*)0;

    const int bm = blockIdx.y * 128, bn = blockIdx.x * BN;
    const int nch = g.K / BK;

    // ldmatrix per-lane offsets (bytes)
    uint32_t aOff[MF], bOff[NF / 2];
#pragma unroll
    for (int mf = 0; mf < MF; ++mf)
        aOff[mf] = ((uint32_t)((wm * WTM + mf * 16 + (lmat & 1) * 8 + lm) * SB + ((lmat >> 1) << 3))) * 2;
#pragma unroll
    for (int p = 0; p < NF / 2; ++p)
        bOff[p] = ((uint32_t)((wn * WTN + p * 16 + (lmat >> 1) * 8 + lm) * SB + ((lmat & 1) << 3))) * 2;

    float acc[MF][NF][4];
#pragma unroll
    for (int i = 0; i < MF; ++i)
#pragma unroll
        for (int j = 0; j < NF; ++j)
#pragma unroll
            for (int c = 0; c < 4; ++c) acc[i][j][c] = 0.f;

    auto issue = [&](int ch, int st) {
        const int k0 = ch * BK;
        const uint32_t sa = smb + (uint32_t)st * STG * 2;
#pragma unroll
        for (int i = 0; i < 128 * KPC / 256; ++i) {
            const int idx = tid + (i << 8);
            const int r = idx / KPC, c = idx % KPC;
            const int gr = bm + r, ok = (gr < g.M);
            const __half* s = ok ? (Ab + (long long)gr * g.lda + k0 + (c << 3)) : Ab;
            const uint32_t d = sa + (uint32_t)(r * SB + (c << 3)) * 2;
            CPA(d, s, ok ? 16 : 0);
            if (SPLIT) {
                const __half* s2 = ok ? (Al + (long long)gr * g.lda + k0 + (c << 3)) : Al;
                CPA(d + AS * 2, s2, ok ? 16 : 0);
            }
        }
#pragma unroll
        for (int i = 0; i < BN * KPC / 256; ++i) {
            const int idx = tid + (i << 8);
            const int r = idx / KPC, c = idx % KPC;
            const int gn = bn + r, ok = (gn < g.N);
            const int srow = GEGLU ? geglu_src(gn) : gn;
            const __half* s = ok ? (Bb + (long long)srow * g.ldb + k0 + (c << 3)) : Bb;
            const uint32_t d = sa + (uint32_t)(NT * AS + r * SB + (c << 3)) * 2;
            CPA(d, s, ok ? 16 : 0);
            if (SPLIT) {
                const __half* s2 = ok ? (Bl + (long long)srow * g.ldb + k0 + (c << 3)) : Bl;
                CPA(d + BS * 2, s2, ok ? 16 : 0);
            }
        }
    };

    auto compute = [&](int st) {
        const uint32_t aB = smb + (uint32_t)st * STG * 2;
        const uint32_t bB = aB + (uint32_t)NT * AS * 2;
#pragma unroll
        for (int kk = 0; kk < KK; ++kk) {
            const uint32_t kb2 = (uint32_t)(kk << 5);
            uint32_t bh[NF][2], bl[NF][2];
#pragma unroll
            for (int p = 0; p < NF / 2; ++p) {
                LDSM4(bh[2*p][0], bh[2*p][1], bh[2*p+1][0], bh[2*p+1][1], bB + bOff[p] + kb2);
                if (SPLIT)
                    LDSM4(bl[2*p][0], bl[2*p][1], bl[2*p+1][0], bl[2*p+1][1],
                          bB + (uint32_t)BS * 2 + bOff[p] + kb2);
            }
#pragma unroll
            for (int mf = 0; mf < MF; ++mf) {
                uint32_t ah[4];
                LDSM4(ah[0], ah[1], ah[2], ah[3], aB + aOff[mf] + kb2);
#pragma unroll
                for (int nf = 0; nf < NF; ++nf) MMAH(acc[mf][nf], ah, bh[nf]);
                if (SPLIT) {
                    uint32_t al[4];
                    LDSM4(al[0], al[1], al[2], al[3], aB + (uint32_t)AS * 2 + aOff[mf] + kb2);
#pragma unroll
                    for (int nf = 0; nf < NF; ++nf) {
                        MMAH(acc[mf][nf], ah, bl[nf]);
                        MMAH(acc[mf][nf], al, bh[nf]);
                    }
                }
            }
        }
    };

    issue(0, 0);
    asm volatile("cp.async.commit_group;");
    for (int ch = 0; ch < nch; ++ch) {
        if (ch + 1 < nch) issue(ch + 1, (ch + 1) & 1);
        asm volatile("cp.async.commit_group;");
        asm volatile("cp.async.wait_group 1;");
        __syncthreads();
        compute(ch & 1);
        __syncthreads();
    }

    if (GEGLU) {
#pragma unroll
        for (int mf = 0; mf < MF; ++mf) {
            const int r0 = bm + wm * WTM + (mf << 4) + grp;
#pragma unroll
            for (int p = 0; p < NF / 2; ++p) {
                const int va = bn + wn * WTN + (p << 4) + (tg << 1);
                const int oc = ((va >> 4) << 3) + (va & 7);
                const float ba0 = __ldg(g.bias + oc),        ba1 = __ldg(g.bias + oc + 1);
                const float bg0 = __ldg(g.bias + 4096 + oc), bg1 = __ldg(g.bias + 4096 + oc + 1);
                float* A2 = acc[mf][2 * p];
                float* G2 = acc[mf][2 * p + 1];
#pragma unroll
                for (int hrow = 0; hrow < 2; ++hrow) {
                    const int r = r0 + hrow * 8;
                    const float a0 = A2[hrow * 2 + 0] + ba0, a1 = A2[hrow * 2 + 1] + ba1;
                    const float g0 = G2[hrow * 2 + 0] + bg0, g1 = G2[hrow * 2 + 1] + bg1;
                    *reinterpret_cast<__half2*>((__half*)g.C + (long long)r * g.ldc + oc) =
                        __floats2half2_rn(a0 * gelu(g0), a1 * gelu(g1));
                }
            }
        }
        return;
    }

    float alpha = g.s0;
    if (g.s1) alpha *= __ldg(g.s1);
    if (g.s2) alpha *= __ldg(g.s2);
    const float qd = g.qd ? __ldg(g.qd) : 1.f;
#pragma unroll
    for (int mf = 0; mf < MF; ++mf) {
        const int r0 = bm + wm * WTM + (mf << 4) + grp;
#pragma unroll
        for (int nf = 0; nf < NF; ++nf) {
            const int c0 = bn + wn * WTN + (nf << 3) + (tg << 1);
#pragma unroll
            for (int e = 0; e < 4; ++e) {
                const int r = r0 + ((e >> 1) << 3);
                const int c = c0 + (e & 1);
                if (r < g.M && c < g.Nstore) {
                    float v = acc[mf][nf][e] * alpha;
                    if (g.bias) v += __ldg(g.bias + c);
                    if (g.res)  v += g.res[(long long)r * g.ldr + c];
                    if (g.qd) {
                        float xi = rintf(v / qd) + 128.f;
                        v = fminf(fmaxf(xi, 0.f), 255.f) - 128.f;
                    }
                    const long long o = (long long)(bb * g.sCb + hb * g.sCh) + (long long)r * g.ldc + c;
                    if (CHALF) ((__half*)g.C)[o] = __float2half_rn(v);
                    else       ((float*)g.C)[o] = v;
                }
            }
        }
    }
}

template<int BN, int WM, int BK, bool SPLIT, bool CHALF, bool GEGLU>
static void run_h(HArgs a, int nb)
{
    constexpr int STG = (SPLIT ? 2 : 1) * ((128 + BN) * (BK + 8));
    const int smem = 2 * STG * 2;
    cudaFuncSetAttribute(hgemm<BN, WM, BK, SPLIT, CHALF, GEGLU>,
                         cudaFuncAttributeMaxDynamicSharedMemorySize, smem);
    dim3 grid((a.N + BN - 1) / BN, (a.M + 127) / 128, nb);
    hgemm<BN, WM, BK, SPLIT, CHALF, GEGLU><<<grid, 256, smem>>>(a);
}
static HArgs ha(const __half* A, const __half* Al, const __half* B, const __half* Bl,
                void* C, int M, int N, int Nstore, int K, int lda, int ldb, int ldc)
{
    HArgs g;
    g.A = A; g.Al = Al; g.B = B; g.Bl = Bl; g.C = C;
    g.M = M; g.N = N; g.Nstore = Nstore; g.K = K;
    g.lda = lda; g.ldb = ldb; g.ldc = ldc; g.ldr = 0;
    g.sAb = g.sAh = g.sBb = g.sBh = g.sCb = g.sCh = 0;
    g.bias = 0; g.res = 0; g.s1 = 0; g.s2 = 0; g.qd = 0; g.s0 = 1.f;
    return g;
}

// ---------------- transposes / splits ----------------
__global__ void wtrans(const float* __restrict__ in, __half* __restrict__ out, int K, int N)
{
    __shared__ float t[32][33];
    const int n0 = blockIdx.x * 32, k0 = blockIdx.y * 32;
    const int tx = threadIdx.x, ty = threadIdx.y;
#pragma unroll
    for (int i = 0; i < 32; i += 8)
        t[ty + i][tx] = in[(long long)(k0 + ty + i) * N + n0 + tx];
    __syncthreads();
#pragma unroll
    for (int i = 0; i < 32; i += 8)
        out[(long long)(n0 + ty + i) * K + k0 + tx] = __float2half_rn(t[tx][ty + i]);
}
__global__ void wtrans_split(const float* __restrict__ in, __half* __restrict__ oH,
                             __half* __restrict__ oL, int K, int N)
{
    __shared__ float t[32][33];
    const int n0 = blockIdx.x * 32, k0 = blockIdx.y * 32;
    const int tx = threadIdx.x, ty = threadIdx.y;
#pragma unroll
    for (int i = 0; i < 32; i += 8)
        t[ty + i][tx] = in[(long long)(k0 + ty + i) * N + n0 + tx];
    __syncthreads();
#pragma unroll
    for (int i = 0; i < 32; i += 8) {
        const float v = t[tx][ty + i];
        const __half h = __float2half_rn(v);
        const long long o = (long long)(n0 + ty + i) * K + k0 + tx;
        oH[o] = h; oL[o] = __float2half_rn(v - __half2float(h));
    }
}
__global__ void vtrans(const __half* __restrict__ v, __half* __restrict__ vt, int T, int Tpad)
{
    __shared__ float t[32][33];
    const int bz = blockIdx.z, b = bz >> 4, h = bz & 15;
    const int t0 = blockIdx.x * 32, d0 = blockIdx.y * 32;
    const int tx = threadIdx.x, ty = threadIdx.y;
#pragma unroll
    for (int i = 0; i < 32; i += 8) {
        const int tt = t0 + ty + i;
        t[ty + i][tx] = (tt < T) ? __half2float(v[((long long)b * T + tt) * 1024 + h * 64 + d0 + tx]) : 0.f;
    }
    __syncthreads();
#pragma unroll
    for (int i = 0; i < 32; i += 8) {
        const int tt = t0 + tx;
        if (tt < Tpad)
            vt[(((long long)b * 16 + h) * 64 + d0 + ty + i) * Tpad + tt] = __float2half_rn(t[tx][ty + i]);
    }
}
__global__ void esplit(const float* __restrict__ in, __half* __restrict__ oH,
                       __half* __restrict__ oL, int n)
{
    const int i = blockIdx.x * 256 + threadIdx.x;
    if (i < n) {
        const float v = in[i];
        const __half h = __float2half_rn(v);
        oH[i] = h; oL[i] = __float2half_rn(v - __half2float(h));
    }
}

// ---------------- layernorm ----------------
__global__ void ln_kernel(const float* __restrict__ x, const float* __restrict__ gm,
                          const float* __restrict__ bt,
                          __half* __restrict__ outH, __half* __restrict__ outL)
{
    __shared__ float red[4];
    const long long row = blockIdx.x;
    const float* xr = x + row * 1024;
    const int t = threadIdx.x;
    float v[8];
    *reinterpret_cast<float4*>(&v[0]) = *reinterpret_cast<const float4*>(xr + t * 8);
    *reinterpret_cast<float4*>(&v[4]) = *reinterpret_cast<const float4*>(xr + t * 8 + 4);
    float s = 0.f;
#pragma unroll
    for (int i = 0; i < 8; ++i) s += v[i];
#pragma unroll
    for (int o = 16; o; o >>= 1) s += __shfl_xor_sync(0xffffffffu, s, o);
    if ((t & 31) == 0) red[t >> 5] = s;
    __syncthreads();
    const float mu = (red[0] + red[1] + red[2] + red[3]) * (1.f / 1024.f);
    __syncthreads();
    float ss = 0.f;
#pragma unroll
    for (int i = 0; i < 8; ++i) { float d = v[i] - mu; ss += d * d; }
#pragma unroll
    for (int o = 16; o; o >>= 1) ss += __shfl_xor_sync(0xffffffffu, ss, o);
    if ((t & 31) == 0) red[t >> 5] = ss;
    __syncthreads();
    const float rs = rsqrtf((red[0] + red[1] + red[2] + red[3]) * (1.f / 1024.f) + 1e-5f);
#pragma unroll
    for (int i = 0; i < 8; ++i) {
        const int c = t * 8 + i;
        const float y = (v[i] - mu) * rs * gm[c] + bt[c];
        const __half h = __float2half_rn(y);
        outH[row * 1024 + c] = h;
        if (outL) outL[row * 1024 + c] = __float2half_rn(y - __half2float(h));
    }
}

// ---------------- launcher ----------------
extern "C" void kernel_launch(void* const* d_in, const int* in_sizes, int n_in,
                              void* d_out, int out_size)
{
    (void)in_sizes; (void)n_in; (void)out_size;
    const float* x   = (const float*)d_in[0];
    const float* ctx = (const float*)d_in[1];
    const float *ln1g = (const float*)d_in[2], *ln1b = (const float*)d_in[3];
    const float *ln2g = (const float*)d_in[4], *ln2b = (const float*)d_in[5];
    const float *ln3g = (const float*)d_in[6], *ln3b = (const float*)d_in[7];
    const float *wq1 = (const float*)d_in[8],  *wk1 = (const float*)d_in[9];
    const float *wv1 = (const float*)d_in[10], *wo1 = (const float*)d_in[11];
    const float *bo1 = (const float*)d_in[12];
    const float *wq2 = (const float*)d_in[13], *wk2 = (const float*)d_in[14];
    const float *wv2 = (const float*)d_in[15], *wo2 = (const float*)d_in[16];
    const float *bo2 = (const float*)d_in[17];
    const float *w1 = (const float*)d_in[18], *b1 = (const float*)d_in[19];
    const float *w2 = (const float*)d_in[20], *b2 = (const float*)d_in[21];
    const float *dq1 = (const float*)d_in[22], *dk1 = (const float*)d_in[23];
    const float *dv1 = (const float*)d_in[24], *dw1 = (const float*)d_in[25];
    const float *dq2 = (const float*)d_in[26], *dk2 = (const float*)d_in[27];
    const float *dv2 = (const float*)d_in[28], *dw2 = (const float*)d_in[29];
    float* out = (float*)d_out;

    float *px, *ph, *phl, *pq, *pk, *pv, *po, *pvt, *pgg, *pw, *pcs;
    cudaGetSymbolAddress((void**)&px,  g_x);
    cudaGetSymbolAddress((void**)&ph,  g_h);
    cudaGetSymbolAddress((void**)&phl, g_hl);
    cudaGetSymbolAddress((void**)&pq,  g_q);
    cudaGetSymbolAddress((void**)&pk,  g_k);
    cudaGetSymbolAddress((void**)&pv,  g_v);
    cudaGetSymbolAddress((void**)&po,  g_o);
    cudaGetSymbolAddress((void**)&pvt, g_vt);
    cudaGetSymbolAddress((void**)&pgg, g_gg);
    cudaGetSymbolAddress((void**)&pw,  g_w);
    cudaGetSymbolAddress((void**)&pcs, g_cs);

    __half *hh = (__half*)ph, *hhl = (__half*)phl;
    __half *hq = (__half*)pq, *hk = (__half*)pk, *hv = (__half*)pv, *hvt = (__half*)pvt;
    __half *hpo = (__half*)po, *hgg = (__half*)pgg;

    const long long M1 = 1048576;
    __half *q1h = (__half*)pw,          *q1l = (__half*)(pw + M1);
    __half *k1h = (__half*)(pw + 2*M1), *k1l = (__half*)(pw + 3*M1);
    __half *v1h = (__half*)(pw + 4*M1), *v1l = (__half*)(pw + 5*M1);
    __half *q2h = (__half*)(pw + 6*M1), *q2l = (__half*)(pw + 7*M1);
    __half *k2h = (__half*)(pw + 8*M1), *k2l = (__half*)(pw + 9*M1);
    __half *v2h = (__half*)(pw + 10*M1),*v2l = (__half*)(pw + 11*M1);
    __half *o1t = (__half*)(pw + 12*M1), *o2t = (__half*)(pw + 13*M1);
    __half *w1t = (__half*)(pw + 14*M1), *w2t = (__half*)(pw + 18*M1);
    __half *chi = (__half*)pcs, *clo = (__half*)(pcs + 80000);

    dim3 tb(32, 8);
    wtrans_split<<<dim3(32,32), tb>>>(wq1, q1h, q1l, 1024, 1024);
    wtrans_split<<<dim3(32,32), tb>>>(wk1, k1h, k1l, 1024, 1024);
    wtrans_split<<<dim3(32,32), tb>>>(wv1, v1h, v1l, 1024, 1024);
    wtrans_split<<<dim3(32,32), tb>>>(wq2, q2h, q2l, 1024, 1024);
    wtrans_split<<<dim3(32,32), tb>>>(wk2, k2h, k2l, 1024, 1024);
    wtrans_split<<<dim3(32,32), tb>>>(wv2, v2h, v2l, 1024, 1024);
    wtrans<<<dim3(32,32),  tb>>>(wo1, o1t, 1024, 1024);
    wtrans<<<dim3(32,32),  tb>>>(wo2, o2t, 1024, 1024);
    wtrans<<<dim3(256,32), tb>>>(w1,  w1t, 1024, 8192);
    wtrans<<<dim3(32,128), tb>>>(w2,  w2t, 4096, 1024);
    esplit<<<616, 256>>>(ctx, chi, clo, 157696);

    const int FSM = 90112;
    cudaFuncSetAttribute(fattn, cudaFuncAttributeMaxDynamicSharedMemorySize, FSM);

    // ===== self attention =====
    ln_kernel<<<4096, 128>>>(x, ln1g, ln1b, hh, hhl);
    { HArgs g = ha(hh, hhl, q1h, q1l, hq, 4096,1024,1024,1024, 1024,1024,1024); g.qd = dq1; run_h<128,2,32,true,true,false>(g, 1); }
    { HArgs g = ha(hh, hhl, k1h, k1l, hk, 4096,1024,1024,1024, 1024,1024,1024); g.qd = dk1; run_h<128,2,32,true,true,false>(g, 1); }
    { HArgs g = ha(hh, hhl, v1h, v1l, hv, 4096,1024,1024,1024, 1024,1024,1024); g.qd = dv1; run_h<128,2,32,true,true,false>(g, 1); }
    vtrans<<<dim3(64,2,32), tb>>>(hv, hvt, 2048, 2048);
    fattn<<<dim3(16,1,32), 256, FSM>>>(hq, hk, hvt, hpo, 2048, 2048, 2048, dq1, dk1, dw1, dv1);
    { HArgs g = ha(hpo, 0, o1t, 0, px, 4096,1024,1024,1024, 1024,1024,1024);
      g.bias = bo1; g.res = x; g.ldr = 1024; run_h<128,2,64,false,false,false>(g, 1); }

    // ===== cross attention =====
    ln_kernel<<<4096, 128>>>(px, ln2g, ln2b, hh, hhl);
    { HArgs g = ha(hh, hhl, q2h, q2l, hq, 4096,1024,1024,1024, 1024,1024,1024); g.qd = dq2; run_h<128,2,32,true,true,false>(g, 1); }
    { HArgs g = ha(chi, clo, k2h, k2l, hk, 154,1024,1024,1024, 1024,1024,1024); g.qd = dk2; run_h<128,2,32,true,true,false>(g, 1); }
    { HArgs g = ha(chi, clo, v2h, v2l, hv, 154,1024,1024,1024, 1024,1024,1024); g.qd = dv2; run_h<128,2,32,true,true,false>(g, 1); }
    vtrans<<<dim3(3,2,32), tb>>>(hv, hvt, 77, 96);
    fattn<<<dim3(16,1,32), 256, FSM>>>(hq, hk, hvt, hpo, 2048, 77, 96, dq2, dk2, dw2, dv2);
    { HArgs g = ha(hpo, 0, o2t, 0, px, 4096,1024,1024,1024, 1024,1024,1024);
      g.bias = bo2; g.res = px; g.ldr = 1024; run_h<128,2,64,false,false,false>(g, 1); }

    // ===== GEGLU feed-forward (fused FFN1+GEGLU) =====
    ln_kernel<<<4096, 128>>>(px, ln3g, ln3b, hh, 0);
    { HArgs g = ha(hh, 0, w1t, 0, hgg, 4096,8192,8192,1024, 1024,1024,4096);
      g.bias = b1; run_h<128,2,64,false,true,true>(g, 1); }
    { HArgs g = ha(hgg, 0, w2t, 0, out, 4096,1024,1024,4096, 4096,4096,1024);
      g.bias = b2; g.res = px; g.ldr = 1024; run_h<128,2,64,false,false,false>(g, 1); }
}

// round 12
// speedup vs baseline: 5.0218x; 1.3428x over previous
#include <cuda_runtime.h>
#include <cuda_fp16.h>
#include <cstdint>
#include <math.h>

// ---------------- scratch ----------------
__device__ float g_x [4194304];
__device__ float g_h [4194304];   // ln out: half
__device__ float g_q [4194304];   // half codes
__device__ float g_k [4194304];
__device__ float g_v [4194304];
__device__ float g_o [4194304];   // half attn out
__device__ float g_vt[4194304];   // half v^T codes
__device__ float g_gg[16777216];  // half GEGLU out
__device__ float g_w [27262976];  // half weights (reinterpret)
__device__ float g_cs[163840];    // half ctx

// ---------------- helpers ----------------
static __device__ __forceinline__ uint32_t smem_u32(const void* p) {
    uint32_t a;
    asm("{ .reg .u64 t; cvta.to.shared.u64 t, %1; cvt.u32.u64 %0, t; }" : "=r"(a) : "l"(p));
    return a;
}
#define MMAH(d, a, b) \
    asm volatile("mma.sync.aligned.m16n8k16.row.col.f32.f16.f16.f32 " \
        "{%0,%1,%2,%3},{%4,%5,%6,%7},{%8,%9},{%0,%1,%2,%3};" \
        : "+f"((d)[0]), "+f"((d)[1]), "+f"((d)[2]), "+f"((d)[3]) \
        : "r"((a)[0]), "r"((a)[1]), "r"((a)[2]), "r"((a)[3]), "r"((b)[0]), "r"((b)[1]))
#define LDSM4(r0, r1, r2, r3, addr) \
    asm volatile("ldmatrix.sync.aligned.m8n8.x4.shared.b16 {%0,%1,%2,%3}, [%4];" \
        : "=r"(r0), "=r"(r1), "=r"(r2), "=r"(r3) : "r"(addr))
#define CPA(dst, src, sz) \
    asm volatile("cp.async.cg.shared.global [%0], [%1], 16, %2;" :: "r"(dst), "l"(src), "r"(sz))
static __device__ __forceinline__ uint32_t packh2(float a, float b) {
    __half2 h = __floats2half2_rn(a, b);
    return *reinterpret_cast<uint32_t*>(&h);
}
static __device__ __forceinline__ float gelu(float g) {
    return 0.5f * g * (1.f + erff(g * 0.70710678118654752440f));
}

// ================= fused attention (two-pass, max-free softmax) =================
__global__ void __launch_bounds__(256)
fattn(const __half* __restrict__ q, const __half* __restrict__ k,
      const __half* __restrict__ vt, __half* __restrict__ o,
      int Tq, int Tk, int Tkpad,
      const float* __restrict__ dqp, const float* __restrict__ dkp,
      const float* __restrict__ dwp, const float* __restrict__ dvp)
{
    constexpr int QS = 128 * 72, KS = 128 * 72, VS = 64 * 136;
    extern __shared__ __half sh[];
    const uint32_t smb = smem_u32(sh);
    const uint32_t kb_ = smb + QS * 2, vb_ = smb + (QS + 2 * KS) * 2;

    const int tid = threadIdx.x, wid = tid >> 5, lane = tid & 31;
    const int grp = lane >> 2, tg = lane & 3;
    const int lm = lane & 7, lmat = lane >> 3;
    const int bh = blockIdx.z, b = bh >> 4, h = bh & 15;
    const int m0 = blockIdx.x * 128;
    const int nkt = (Tk + 127) >> 7;

    const float alpha = 0.125f * __ldg(dqp) * __ldg(dkp);
    const float dw = __ldg(dwp);
    const float beta = dw * __ldg(dvp);

    const uint32_t qOff = ((uint32_t)((wid * 16 + (lmat & 1) * 8 + lm) * 72 + ((lmat >> 1) << 3))) * 2;
    uint32_t kOff[8], vOff[4];
#pragma unroll
    for (int p = 0; p < 8; ++p)
        kOff[p] = ((uint32_t)((p * 16 + (lmat >> 1) * 8 + lm) * 72 + ((lmat & 1) << 3))) * 2;
#pragma unroll
    for (int p = 0; p < 4; ++p)
        vOff[p] = ((uint32_t)((p * 16 + (lmat >> 1) * 8 + lm) * 136 + ((lmat & 1) << 3))) * 2;

    {
        const __half* qb = q + ((long long)b * Tq + m0) * 1024 + h * 64;
#pragma unroll
        for (int i = 0; i < 4; ++i) {
            const int idx = tid + (i << 8);
            const int r = idx >> 3, c = idx & 7;
            CPA(smb + (uint32_t)(r * 72 + (c << 3)) * 2, qb + (long long)r * 1024 + (c << 3), 16);
        }
    }

    auto loadK = [&](int t, int st) {
        const __half* kbase = k + ((long long)b * Tk) * 1024 + h * 64;
#pragma unroll
        for (int i = 0; i < 4; ++i) {
            const int idx = tid + (i << 8);
            const int r = idx >> 3, c = idx & 7;
            const int key = t * 128 + r;
            const int ok = key < Tk;
            const __half* s = ok ? (kbase + (long long)key * 1024 + (c << 3)) : kbase;
            CPA(kb_ + (uint32_t)(st * KS + r * 72 + (c << 3)) * 2, s, ok ? 16 : 0);
        }
    };
    auto loadV = [&](int t, int st) {
        const __half* vbase = vt + ((long long)bh * 64) * Tkpad;
#pragma unroll
        for (int i = 0; i < 4; ++i) {
            const int idx = tid + (i << 8);
            const int r = idx >> 4, c = idx & 15;
            const int key = t * 128 + (c << 3);
            const int ok = (key + 8) <= Tkpad;
            const __half* s = ok ? (vbase + (long long)r * Tkpad + key) : vbase;
            CPA(vb_ + (uint32_t)(st * VS + r * 136 + (c << 3)) * 2, s, ok ? 16 : 0);
        }
    };

    float sacc[16][4];
    auto computeS = [&](int st) {
#pragma unroll
        for (int nf = 0; nf < 16; ++nf)
#pragma unroll
            for (int e = 0; e < 4; ++e) sacc[nf][e] = 0.f;
        const uint32_t kB = kb_ + (uint32_t)st * KS * 2;
#pragma unroll
        for (int kc = 0; kc < 4; ++kc) {
            const uint32_t kb2 = (uint32_t)(kc << 5);
            uint32_t ah[4];
            LDSM4(ah[0], ah[1], ah[2], ah[3], smb + qOff + kb2);
            uint32_t bf[16][2];
#pragma unroll
            for (int p = 0; p < 8; ++p)
                LDSM4(bf[2*p][0], bf[2*p][1], bf[2*p+1][0], bf[2*p+1][1], kB + kOff[p] + kb2);
#pragma unroll
            for (int nf = 0; nf < 16; ++nf) MMAH(sacc[nf], ah, bf[nf]);
        }
    };

    // ---- pass 1 ----
    float psum0 = 0.f, psum1 = 0.f;
    loadK(0, 0);
    asm volatile("cp.async.commit_group;");
    for (int t = 0; t < nkt; ++t) {
        if (t + 1 < nkt) loadK(t + 1, (t + 1) & 1);
        asm volatile("cp.async.commit_group;");
        if (t + 1 < nkt) asm volatile("cp.async.wait_group 1;");
        else             asm volatile("cp.async.wait_group 0;");
        __syncthreads();
        computeS(t & 1);
        __syncthreads();
        const int cb = t * 128;
#pragma unroll
        for (int nf = 0; nf < 16; ++nf) {
            const int c0 = cb + nf * 8 + (tg << 1);
            if (c0 < Tk)     { psum0 += expf(sacc[nf][0] * alpha); psum1 += expf(sacc[nf][2] * alpha); }
            if (c0 + 1 < Tk) { psum0 += expf(sacc[nf][1] * alpha); psum1 += expf(sacc[nf][3] * alpha); }
        }
    }
    psum0 += __shfl_xor_sync(0xffffffffu, psum0, 1);
    psum0 += __shfl_xor_sync(0xffffffffu, psum0, 2);
    psum1 += __shfl_xor_sync(0xffffffffu, psum1, 1);
    psum1 += __shfl_xor_sync(0xffffffffu, psum1, 2);

    // ---- pass 2 ----
    float oacc[8][4];
#pragma unroll
    for (int i = 0; i < 8; ++i)
#pragma unroll
        for (int e = 0; e < 4; ++e) oacc[i][e] = 0.f;

    loadK(0, 0); loadV(0, 0);
    asm volatile("cp.async.commit_group;");
    for (int t = 0; t < nkt; ++t) {
        if (t + 1 < nkt) { loadK(t + 1, (t + 1) & 1); loadV(t + 1, (t + 1) & 1); }
        asm volatile("cp.async.commit_group;");
        if (t + 1 < nkt) asm volatile("cp.async.wait_group 1;");
        else             asm volatile("cp.async.wait_group 0;");
        __syncthreads();
        computeS(t & 1);
        const uint32_t vB = vb_ + (uint32_t)(t & 1) * VS * 2;
        const int cb = t * 128;
#pragma unroll
        for (int kb = 0; kb < 8; ++kb) {
            uint32_t ah[4];
#pragma unroll
            for (int hf = 0; hf < 2; ++hf) {
                const int nf = 2 * kb + hf;
                const int c0 = cb + nf * 8 + (tg << 1);
                const int ok0 = c0 < Tk, ok1 = (c0 + 1) < Tk;
                float p0 = ok0 ? expf(sacc[nf][0] * alpha) / psum0 : 0.f;
                float p1 = ok1 ? expf(sacc[nf][1] * alpha) / psum0 : 0.f;
                float p2 = ok0 ? expf(sacc[nf][2] * alpha) / psum1 : 0.f;
                float p3 = ok1 ? expf(sacc[nf][3] * alpha) / psum1 : 0.f;
                const float q0 = fminf(fmaxf(rintf(p0 / dw), 0.f), 255.f);
                const float q1 = fminf(fmaxf(rintf(p1 / dw), 0.f), 255.f);
                const float q2 = fminf(fmaxf(rintf(p2 / dw), 0.f), 255.f);
                const float q3 = fminf(fmaxf(rintf(p3 / dw), 0.f), 255.f);
                ah[hf * 2]     = packh2(q0, q1);
                ah[hf * 2 + 1] = packh2(q2, q3);
            }
            const uint32_t kb2 = (uint32_t)(kb << 5);
            uint32_t bf[8][2];
#pragma unroll
            for (int p = 0; p < 4; ++p)
                LDSM4(bf[2*p][0], bf[2*p][1], bf[2*p+1][0], bf[2*p+1][1], vB + vOff[p] + kb2);
#pragma unroll
            for (int nfo = 0; nfo < 8; ++nfo) MMAH(oacc[nfo], ah, bf[nfo]);
        }
        __syncthreads();
    }

    const int row0 = m0 + wid * 16 + grp;
    __half* ob = o + ((long long)b * Tq) * 1024 + h * 64;
#pragma unroll
    for (int nfo = 0; nfo < 8; ++nfo) {
        const int c = nfo * 8 + (tg << 1);
        *reinterpret_cast<__half2*>(ob + (long long)row0 * 1024 + c) =
            __floats2half2_rn(oacc[nfo][0] * beta, oacc[nfo][1] * beta);
        *reinterpret_cast<__half2*>(ob + (long long)(row0 + 8) * 1024 + c) =
            __floats2half2_rn(oacc[nfo][2] * beta, oacc[nfo][3] * beta);
    }
}

// ================= fp16 mma GEMM =================
struct HArgs {
    const __half *A, *B; void *C, *C2, *C3;
    int M, N, Nstore, K, lda, ldb, ldc, ldr;
    const float *bias, *res, *s1, *s2, *qd, *qd2, *qd3;
    float s0;
};

static __device__ __forceinline__ int geglu_src(int n) {
    const int gp = n >> 4, r = n & 15;
    return (r < 8) ? (gp * 8 + r) : (4096 + gp * 8 + (r - 8));
}

template<int BN, int WM, int BK, bool CHALF, bool GEGLU, bool QKV>
__global__ void __launch_bounds__(256)
hgemm(const __grid_constant__ HArgs g)
{
    constexpr int WN = 8 / WM, WTM = 128 / WM, WTN = BN / WN;
    constexpr int MF = WTM / 16, NF = WTN / 8;
    constexpr int SB = BK + 8;
    constexpr int AS = 128 * SB, BS = BN * SB;
    constexpr int STG = AS + BS;
    constexpr int KPC = BK / 8;
    constexpr int KK  = BK / 16;

    extern __shared__ __half smh[];
    const uint32_t smb = smem_u32(smh);
    const int tid = threadIdx.x, wid = tid >> 5, lane = tid & 31;
    const int grp = lane >> 2, tg = lane & 3;
    const int lm = lane & 7, lmat = lane >> 3;
    const int wm = wid / WN, wn = wid % WN;

    const int bm = blockIdx.y * 128, bn = blockIdx.x * BN;
    const int nch = g.K / BK;

    uint32_t aOff[MF], bOff[NF / 2];
#pragma unroll
    for (int mf = 0; mf < MF; ++mf)
        aOff[mf] = ((uint32_t)((wm * WTM + mf * 16 + (lmat & 1) * 8 + lm) * SB + ((lmat >> 1) << 3))) * 2;
#pragma unroll
    for (int p = 0; p < NF / 2; ++p)
        bOff[p] = ((uint32_t)((wn * WTN + p * 16 + (lmat >> 1) * 8 + lm) * SB + ((lmat & 1) << 3))) * 2;

    float acc[MF][NF][4];
#pragma unroll
    for (int i = 0; i < MF; ++i)
#pragma unroll
        for (int j = 0; j < NF; ++j)
#pragma unroll
            for (int c = 0; c < 4; ++c) acc[i][j][c] = 0.f;

    auto issue = [&](int ch, int st) {
        const int k0 = ch * BK;
        const uint32_t sa = smb + (uint32_t)st * STG * 2;
#pragma unroll
        for (int i = 0; i < 128 * KPC / 256; ++i) {
            const int idx = tid + (i << 8);
            const int r = idx / KPC, c = idx % KPC;
            const int gr = bm + r, ok = (gr < g.M);
            const __half* s = ok ? (g.A + (long long)gr * g.lda + k0 + (c << 3)) : g.A;
            CPA(sa + (uint32_t)(r * SB + (c << 3)) * 2, s, ok ? 16 : 0);
        }
#pragma unroll
        for (int i = 0; i < BN * KPC / 256; ++i) {
            const int idx = tid + (i << 8);
            const int r = idx / KPC, c = idx % KPC;
            const int gn = bn + r, ok = (gn < g.N);
            const int srow = GEGLU ? geglu_src(gn) : gn;
            const __half* s = ok ? (g.B + (long long)srow * g.ldb + k0 + (c << 3)) : g.B;
            CPA(sa + (uint32_t)(AS + r * SB + (c << 3)) * 2, s, ok ? 16 : 0);
        }
    };

    auto compute = [&](int st) {
        const uint32_t aB = smb + (uint32_t)st * STG * 2;
        const uint32_t bB = aB + (uint32_t)AS * 2;
#pragma unroll
        for (int kk = 0; kk < KK; ++kk) {
            const uint32_t kb2 = (uint32_t)(kk << 5);
            uint32_t bh[NF][2];
#pragma unroll
            for (int p = 0; p < NF / 2; ++p)
                LDSM4(bh[2*p][0], bh[2*p][1], bh[2*p+1][0], bh[2*p+1][1], bB + bOff[p] + kb2);
#pragma unroll
            for (int mf = 0; mf < MF; ++mf) {
                uint32_t ah[4];
                LDSM4(ah[0], ah[1], ah[2], ah[3], aB + aOff[mf] + kb2);
#pragma unroll
                for (int nf = 0; nf < NF; ++nf) MMAH(acc[mf][nf], ah, bh[nf]);
            }
        }
    };

    issue(0, 0);
    asm volatile("cp.async.commit_group;");
    for (int ch = 0; ch < nch; ++ch) {
        if (ch + 1 < nch) issue(ch + 1, (ch + 1) & 1);
        asm volatile("cp.async.commit_group;");
        asm volatile("cp.async.wait_group 1;");
        __syncthreads();
        compute(ch & 1);
        __syncthreads();
    }

    if (GEGLU) {
#pragma unroll
        for (int mf = 0; mf < MF; ++mf) {
            const int r0 = bm + wm * WTM + (mf << 4) + grp;
#pragma unroll
            for (int p = 0; p < NF / 2; ++p) {
                const int va = bn + wn * WTN + (p << 4) + (tg << 1);
                const int oc = ((va >> 4) << 3) + (va & 7);
                const float ba0 = __ldg(g.bias + oc),        ba1 = __ldg(g.bias + oc + 1);
                const float bg0 = __ldg(g.bias + 4096 + oc), bg1 = __ldg(g.bias + 4096 + oc + 1);
                float* A2 = acc[mf][2 * p];
                float* G2 = acc[mf][2 * p + 1];
#pragma unroll
                for (int hrow = 0; hrow < 2; ++hrow) {
                    const int r = r0 + hrow * 8;
                    const float a0 = A2[hrow * 2 + 0] + ba0, a1 = A2[hrow * 2 + 1] + ba1;
                    const float g0 = G2[hrow * 2 + 0] + bg0, g1 = G2[hrow * 2 + 1] + bg1;
                    *reinterpret_cast<__half2*>((__half*)g.C + (long long)r * g.ldc + oc) =
                        __floats2half2_rn(a0 * gelu(g0), a1 * gelu(g1));
                }
            }
        }
        return;
    }

    if (QKV) {
        // quantize-to-codes; output buffer + delta selected by 1024-column range
        const float d0 = g.qd  ? __ldg(g.qd)  : 1.f;
        const float d1 = g.qd2 ? __ldg(g.qd2) : 1.f;
        const float d2 = g.qd3 ? __ldg(g.qd3) : 1.f;
#pragma unroll
        for (int mf = 0; mf < MF; ++mf) {
            const int r0 = bm + wm * WTM + (mf << 4) + grp;
#pragma unroll
            for (int nf = 0; nf < NF; ++nf) {
                const int c0 = bn + wn * WTN + (nf << 3) + (tg << 1);
                if (c0 >= g.N) continue;
                const int sel = c0 >> 10, col = c0 & 1023;
                __half* Cp = (__half*)(sel == 0 ? g.C : sel == 1 ? g.C2 : g.C3);
                const float qd = sel == 0 ? d0 : sel == 1 ? d1 : d2;
#pragma unroll
                for (int e = 0; e < 4; ++e) {
                    const int r = r0 + ((e >> 1) << 3);
                    const int c = col + (e & 1);
                    if (r < g.M) {
                        float xi = rintf(acc[mf][nf][e] / qd) + 128.f;
                        Cp[(long long)r * 1024 + c] =
                            __float2half_rn(fminf(fmaxf(xi, 0.f), 255.f) - 128.f);
                    }
                }
            }
        }
        return;
    }

    float alpha = g.s0;
    if (g.s1) alpha *= __ldg(g.s1);
    if (g.s2) alpha *= __ldg(g.s2);
    const float qd = g.qd ? __ldg(g.qd) : 1.f;
#pragma unroll
    for (int mf = 0; mf < MF; ++mf) {
        const int r0 = bm + wm * WTM + (mf << 4) + grp;
#pragma unroll
        for (int nf = 0; nf < NF; ++nf) {
            const int c0 = bn + wn * WTN + (nf << 3) + (tg << 1);
#pragma unroll
            for (int e = 0; e < 4; ++e) {
                const int r = r0 + ((e >> 1) << 3);
                const int c = c0 + (e & 1);
                if (r < g.M && c < g.Nstore) {
                    float v = acc[mf][nf][e] * alpha;
                    if (g.bias) v += __ldg(g.bias + c);
                    if (g.res)  v += g.res[(long long)r * g.ldr + c];
                    if (g.qd) {
                        float xi = rintf(v / qd) + 128.f;
                        v = fminf(fmaxf(xi, 0.f), 255.f) - 128.f;
                    }
                    const long long o = (long long)r * g.ldc + c;
                    if (CHALF) ((__half*)g.C)[o] = __float2half_rn(v);
                    else       ((float*)g.C)[o] = v;
                }
            }
        }
    }
}

template<int BN, int WM, int BK, bool CHALF, bool GEGLU, bool QKV>
static void run_h(HArgs a)
{
    constexpr int STG = (128 + BN) * (BK + 8);
    const int smem = 2 * STG * 2;
    cudaFuncSetAttribute(hgemm<BN, WM, BK, CHALF, GEGLU, QKV>,
                         cudaFuncAttributeMaxDynamicSharedMemorySize, smem);
    dim3 grid((a.N + BN - 1) / BN, (a.M + 127) / 128, 1);
    hgemm<BN, WM, BK, CHALF, GEGLU, QKV><<<grid, 256, smem>>>(a);
}
static HArgs ha(const __half* A, const __half* B, void* C,
                int M, int N, int Nstore, int K, int lda, int ldb, int ldc)
{
    HArgs g;
    g.A = A; g.B = B; g.C = C; g.C2 = 0; g.C3 = 0;
    g.M = M; g.N = N; g.Nstore = Nstore; g.K = K;
    g.lda = lda; g.ldb = ldb; g.ldc = ldc; g.ldr = 0;
    g.bias = 0; g.res = 0; g.s1 = 0; g.s2 = 0; g.qd = 0; g.qd2 = 0; g.qd3 = 0;
    g.s0 = 1.f;
    return g;
}

// ---------------- transposes / casts ----------------
__global__ void wtrans(const float* __restrict__ in, __half* __restrict__ out, int K, int N)
{
    __shared__ float t[32][33];
    const int n0 = blockIdx.x * 32, k0 = blockIdx.y * 32;
    const int tx = threadIdx.x, ty = threadIdx.y;
#pragma unroll
    for (int i = 0; i < 32; i += 8)
        t[ty + i][tx] = in[(long long)(k0 + ty + i) * N + n0 + tx];
    __syncthreads();
#pragma unroll
    for (int i = 0; i < 32; i += 8)
        out[(long long)(n0 + ty + i) * K + k0 + tx] = __float2half_rn(t[tx][ty + i]);
}
__global__ void vtrans(const __half* __restrict__ v, __half* __restrict__ vt, int T, int Tpad)
{
    __shared__ float t[32][33];
    const int bz = blockIdx.z, b = bz >> 4, h = bz & 15;
    const int t0 = blockIdx.x * 32, d0 = blockIdx.y * 32;
    const int tx = threadIdx.x, ty = threadIdx.y;
#pragma unroll
    for (int i = 0; i < 32; i += 8) {
        const int tt = t0 + ty + i;
        t[ty + i][tx] = (tt < T) ? __half2float(v[((long long)b * T + tt) * 1024 + h * 64 + d0 + tx]) : 0.f;
    }
    __syncthreads();
#pragma unroll
    for (int i = 0; i < 32; i += 8) {
        const int tt = t0 + tx;
        if (tt < Tpad)
            vt[(((long long)b * 16 + h) * 64 + d0 + ty + i) * Tpad + tt] = __float2half_rn(t[tx][ty + i]);
    }
}
__global__ void f2h(const float* __restrict__ in, __half* __restrict__ out, int n)
{
    const int i = blockIdx.x * 256 + threadIdx.x;
    if (i < n) out[i] = __float2half_rn(in[i]);
}

// ---------------- layernorm -> half ----------------
__global__ void ln_kernel(const float* __restrict__ x, const float* __restrict__ gm,
                          const float* __restrict__ bt, __half* __restrict__ outH)
{
    __shared__ float red[4];
    const long long row = blockIdx.x;
    const float* xr = x + row * 1024;
    const int t = threadIdx.x;
    float v[8];
    *reinterpret_cast<float4*>(&v[0]) = *reinterpret_cast<const float4*>(xr + t * 8);
    *reinterpret_cast<float4*>(&v[4]) = *reinterpret_cast<const float4*>(xr + t * 8 + 4);
    float s = 0.f;
#pragma unroll
    for (int i = 0; i < 8; ++i) s += v[i];
#pragma unroll
    for (int o = 16; o; o >>= 1) s += __shfl_xor_sync(0xffffffffu, s, o);
    if ((t & 31) == 0) red[t >> 5] = s;
    __syncthreads();
    const float mu = (red[0] + red[1] + red[2] + red[3]) * (1.f / 1024.f);
    __syncthreads();
    float ss = 0.f;
#pragma unroll
    for (int i = 0; i < 8; ++i) { float d = v[i] - mu; ss += d * d; }
#pragma unroll
    for (int o = 16; o; o >>= 1) ss += __shfl_xor_sync(0xffffffffu, ss, o);
    if ((t & 31) == 0) red[t >> 5] = ss;
    __syncthreads();
    const float rs = rsqrtf((red[0] + red[1] + red[2] + red[3]) * (1.f / 1024.f) + 1e-5f);
#pragma unroll
    for (int i = 0; i < 4; ++i) {
        const int c = t * 8 + i * 2;
        *reinterpret_cast<__half2*>(outH + row * 1024 + c) =
            __floats2half2_rn((v[i*2]   - mu) * rs * gm[c]   + bt[c],
                              (v[i*2+1] - mu) * rs * gm[c+1] + bt[c+1]);
    }
}

// ---------------- launcher ----------------
extern "C" void kernel_launch(void* const* d_in, const int* in_sizes, int n_in,
                              void* d_out, int out_size)
{
    (void)in_sizes; (void)n_in; (void)out_size;
    const float* x   = (const float*)d_in[0];
    const float* ctx = (const float*)d_in[1];
    const float *ln1g = (const float*)d_in[2], *ln1b = (const float*)d_in[3];
    const float *ln2g = (const float*)d_in[4], *ln2b = (const float*)d_in[5];
    const float *ln3g = (const float*)d_in[6], *ln3b = (const float*)d_in[7];
    const float *wq1 = (const float*)d_in[8],  *wk1 = (const float*)d_in[9];
    const float *wv1 = (const float*)d_in[10], *wo1 = (const float*)d_in[11];
    const float *bo1 = (const float*)d_in[12];
    const float *wq2 = (const float*)d_in[13], *wk2 = (const float*)d_in[14];
    const float *wv2 = (const float*)d_in[15], *wo2 = (const float*)d_in[16];
    const float *bo2 = (const float*)d_in[17];
    const float *w1 = (const float*)d_in[18], *b1 = (const float*)d_in[19];
    const float *w2 = (const float*)d_in[20], *b2 = (const float*)d_in[21];
    const float *dq1 = (const float*)d_in[22], *dk1 = (const float*)d_in[23];
    const float *dv1 = (const float*)d_in[24], *dw1 = (const float*)d_in[25];
    const float *dq2 = (const float*)d_in[26], *dk2 = (const float*)d_in[27];
    const float *dv2 = (const float*)d_in[28], *dw2 = (const float*)d_in[29];
    float* out = (float*)d_out;

    float *px, *ph, *pq, *pk, *pv, *po, *pvt, *pgg, *pw, *pcs;
    cudaGetSymbolAddress((void**)&px,  g_x);
    cudaGetSymbolAddress((void**)&ph,  g_h);
    cudaGetSymbolAddress((void**)&pq,  g_q);
    cudaGetSymbolAddress((void**)&pk,  g_k);
    cudaGetSymbolAddress((void**)&pv,  g_v);
    cudaGetSymbolAddress((void**)&po,  g_o);
    cudaGetSymbolAddress((void**)&pvt, g_vt);
    cudaGetSymbolAddress((void**)&pgg, g_gg);
    cudaGetSymbolAddress((void**)&pw,  g_w);
    cudaGetSymbolAddress((void**)&pcs, g_cs);

    __half *hh = (__half*)ph;
    __half *hq = (__half*)pq, *hk = (__half*)pk, *hv = (__half*)pv, *hvt = (__half*)pvt;
    __half *hpo = (__half*)po, *hgg = (__half*)pgg;
    __half *hw = (__half*)pw, *chx = (__half*)pcs;

    const long long M1h = 1048576;                 // halfs
    __half *qkv1t = hw;                            // [3072,1024]
    __half *kv2t  = hw + 3*M1h;                    // [2048,1024]
    __half *q2t   = hw + 5*M1h;
    __half *o1t   = hw + 6*M1h, *o2t = hw + 7*M1h;
    __half *w1t   = hw + 8*M1h;                    // [8192,1024]
    __half *w2t   = hw + 16*M1h;                   // [1024,4096]

    dim3 tb(32, 8);
    wtrans<<<dim3(32,32),  tb>>>(wq1, qkv1t,           1024, 1024);
    wtrans<<<dim3(32,32),  tb>>>(wk1, qkv1t + M1h,     1024, 1024);
    wtrans<<<dim3(32,32),  tb>>>(wv1, qkv1t + 2*M1h,   1024, 1024);
    wtrans<<<dim3(32,32),  tb>>>(wk2, kv2t,            1024, 1024);
    wtrans<<<dim3(32,32),  tb>>>(wv2, kv2t + M1h,      1024, 1024);
    wtrans<<<dim3(32,32),  tb>>>(wq2, q2t,             1024, 1024);
    wtrans<<<dim3(32,32),  tb>>>(wo1, o1t,             1024, 1024);
    wtrans<<<dim3(32,32),  tb>>>(wo2, o2t,             1024, 1024);
    wtrans<<<dim3(256,32), tb>>>(w1,  w1t,             1024, 8192);
    wtrans<<<dim3(32,128), tb>>>(w2,  w2t,             4096, 1024);
    f2h<<<616, 256>>>(ctx, chx, 157696);

    const int FSM = 90112;
    cudaFuncSetAttribute(fattn, cudaFuncAttributeMaxDynamicSharedMemorySize, FSM);

    // ===== self attention =====
    ln_kernel<<<4096, 128>>>(x, ln1g, ln1b, hh);
    { HArgs g = ha(hh, qkv1t, hq, 4096,3072,3072,1024, 1024,1024,1024);
      g.C2 = hk; g.C3 = hv; g.qd = dq1; g.qd2 = dk1; g.qd3 = dv1;
      run_h<128,2,64,true,false,true>(g); }
    vtrans<<<dim3(64,2,32), tb>>>(hv, hvt, 2048, 2048);
    fattn<<<dim3(16,1,32), 256, FSM>>>(hq, hk, hvt, hpo, 2048, 2048, 2048, dq1, dk1, dw1, dv1);
    { HArgs g = ha(hpo, o1t, px, 4096,1024,1024,1024, 1024,1024,1024);
      g.bias = bo1; g.res = x; g.ldr = 1024; run_h<128,2,64,false,false,false>(g); }

    // ===== cross attention =====
    ln_kernel<<<4096, 128>>>(px, ln2g, ln2b, hh);
    { HArgs g = ha(hh, q2t, hq, 4096,1024,1024,1024, 1024,1024,1024);
      g.qd = dq2; run_h<128,2,64,true,false,false>(g); }
    { HArgs g = ha(chx, kv2t, hk, 154,2048,2048,1024, 1024,1024,1024);
      g.C2 = hv; g.qd = dk2; g.qd2 = dv2; run_h<128,2,64,true,false,true>(g); }
    vtrans<<<dim3(3,2,32), tb>>>(hv, hvt, 77, 96);
    fattn<<<dim3(16,1,32), 256, FSM>>>(hq, hk, hvt, hpo, 2048, 77, 96, dq2, dk2, dw2, dv2);
    { HArgs g = ha(hpo, o2t, px, 4096,1024,1024,1024, 1024,1024,1024);
      g.bias = bo2; g.res = px; g.ldr = 1024; run_h<128,2,64,false,false,false>(g); }

    // ===== GEGLU feed-forward (fused FFN1+GEGLU) =====
    ln_kernel<<<4096, 128>>>(px, ln3g, ln3b, hh);
    { HArgs g = ha(hh, w1t, hgg, 4096,8192,8192,1024, 1024,1024,4096);
      g.bias = b1; run_h<128,2,64,true,true,false>(g); }
    { HArgs g = ha(hgg, w2t, out, 4096,1024,1024,4096, 4096,4096,1024);
      g.bias = b2; g.res = px; g.ldr = 1024; run_h<128,2,64,false,false,false>(g); }
}